// round 2
// baseline (speedup 1.0000x reference)
#include <cuda_runtime.h>
#include <math.h>

// Problem dims (fixed by the reference)
#define SS    16
#define BB    128
#define FEATD 2048
#define HANDD 63
#define HH    1024
#define CC    1000

// ---------------------------------------------------------------------------
// Scratch: single __device__ global (no allocations anywhere).
// Layout (floats):
//   x        : SS*BB*2H          = 4,194,304
//   gates_x  : SS*BB*4H          = 8,388,608
//   gates_h  : BB*4H             =   524,288
//   gates_xu : BB*4H             =   524,288
//   h        : BB*H              =   131,072
//   c        : BB*H              =   131,072   (adjacent to h -> one zero pass)
//   hands    : SS*BB*2*HAND      =   258,048
//   lossrow  : BB                =       128
// total = 14,151,808
// ---------------------------------------------------------------------------
#define OFF_X        0
#define OFF_GATESX   (OFF_X      + SS*BB*2*HH)
#define OFF_GATESH   (OFF_GATESX + SS*BB*4*HH)
#define OFF_GATESXU  (OFF_GATESH + BB*4*HH)
#define OFF_H        (OFF_GATESXU+ BB*4*HH)
#define OFF_C        (OFF_H      + BB*HH)
#define OFF_HANDS    (OFF_C      + BB*HH)
#define OFF_LOSSROW  (OFF_HANDS  + SS*BB*2*HANDD)
#define SCRATCH_TOT  (OFF_LOSSROW + BB)

__device__ float g_scratch[SCRATCH_TOT];

// ---------------------------------------------------------------------------
// Generic fp32 GEMM:  C[m,n] = sum_k A[m,k] * W[n,k]  (+ b1[n]) (+ b2[n])
// A: (M,K) row-major lda; W: (N,K) row-major ldw; C row-major ldc.
// Tile 128x64, BK=16, 256 threads, 8x4 per-thread micro-tile.
// ---------------------------------------------------------------------------
#define BM 128
#define BN 64
#define BK 16
#define TM 8
#define TN 4

__global__ __launch_bounds__(256)
void gemm_nt(const float* __restrict__ A, int lda,
             const float* __restrict__ W, int ldw,
             float* __restrict__ Cmat, int ldc,
             const float* __restrict__ b1,
             const float* __restrict__ b2,
             int M, int N, int K)
{
    __shared__ float As[BK][BM + 4];
    __shared__ float Ws[BK][BN + 4];

    const int tid = threadIdx.x;
    const int tx  = tid & 15;        // 0..15 -> N direction
    const int ty  = tid >> 4;        // 0..15 -> M direction
    const int row0 = blockIdx.y * BM;
    const int col0 = blockIdx.x * BN;

    float acc[TM][TN];
#pragma unroll
    for (int i = 0; i < TM; i++)
#pragma unroll
        for (int j = 0; j < TN; j++) acc[i][j] = 0.f;

    for (int k0 = 0; k0 < K; k0 += BK) {
        // Load A tile (BM*BK = 2048 elems -> 8 per thread), K contiguous.
#pragma unroll
        for (int l = 0; l < (BM * BK) / 256; l++) {
            int i = tid + l * 256;
            int m = i >> 4;          // i / BK
            int k = i & 15;          // i % BK
            int gm = row0 + m, gk = k0 + k;
            float v = 0.f;
            if (gm < M && gk < K) v = A[(long)gm * lda + gk];
            As[k][m] = v;
        }
        // Load W tile (BN*BK = 1024 elems -> 4 per thread)
#pragma unroll
        for (int l = 0; l < (BN * BK) / 256; l++) {
            int i = tid + l * 256;
            int n = i >> 4;
            int k = i & 15;
            int gn = col0 + n, gk = k0 + k;
            float v = 0.f;
            if (gn < N && gk < K) v = W[(long)gn * ldw + gk];
            Ws[k][n] = v;
        }
        __syncthreads();

#pragma unroll
        for (int k = 0; k < BK; k++) {
            float ra[TM], rb[TN];
#pragma unroll
            for (int i = 0; i < TM; i++) ra[i] = As[k][ty * TM + i];
#pragma unroll
            for (int j = 0; j < TN; j++) rb[j] = Ws[k][tx * TN + j];
#pragma unroll
            for (int i = 0; i < TM; i++)
#pragma unroll
                for (int j = 0; j < TN; j++)
                    acc[i][j] += ra[i] * rb[j];
        }
        __syncthreads();
    }

#pragma unroll
    for (int i = 0; i < TM; i++) {
        int gm = row0 + ty * TM + i;
        if (gm >= M) continue;
#pragma unroll
        for (int j = 0; j < TN; j++) {
            int gn = col0 + tx * TN + j;
            if (gn >= N) continue;
            float v = acc[i][j];
            if (b1) v += b1[gn];
            if (b2) v += b2[gn];
            Cmat[(long)gm * ldc + gn] = v;
        }
    }
}

// ---------------------------------------------------------------------------
// Small helper kernels
// ---------------------------------------------------------------------------
__global__ void zero_kernel(float* p, int n)
{
    int i = blockIdx.x * blockDim.x + threadIdx.x;
    if (i < n) p[i] = 0.f;
}

__global__ void pack_hands(const float* __restrict__ lh,
                           const float* __restrict__ rh,
                           float* __restrict__ hands)
{
    int i = blockIdx.x * blockDim.x + threadIdx.x;
    const int total = SS * BB * 2 * HANDD;
    if (i >= total) return;
    int col = i % (2 * HANDD);
    int row = i / (2 * HANDD);
    hands[i] = (col < HANDD) ? lh[row * HANDD + col]
                             : rh[row * HANDD + (col - HANDD)];
}

// gates order (JAX split): [i | f | g | o], each H wide
__global__ void lstm_cell(const float* __restrict__ gx,
                          const float* __restrict__ gh,
                          float* __restrict__ h,
                          float* __restrict__ c)
{
    int i = blockIdx.x * blockDim.x + threadIdx.x;
    if (i >= BB * HH) return;
    int b = i / HH, j = i % HH;
    const float* gxr = gx + (long)b * 4 * HH;
    const float* ghr = gh + (long)b * 4 * HH;
    float gi = gxr[j]          + ghr[j];
    float gf = gxr[HH + j]     + ghr[HH + j];
    float gg = gxr[2 * HH + j] + ghr[2 * HH + j];
    float go = gxr[3 * HH + j] + ghr[3 * HH + j];
    float si = 1.f / (1.f + expf(-gi));
    float sf = 1.f / (1.f + expf(-gf));
    float so = 1.f / (1.f + expf(-go));
    float tg = tanhf(gg);
    float cn = sf * c[i] + si * tg;
    float hn = so * tanhf(cn);
    c[i] = cn;
    h[i] = hn;
}

// Per-row: argmax (first-max tie-break, matches jnp.argmax) + logsumexp loss term.
__global__ void row_stats(const float* __restrict__ out,
                          const int* __restrict__ act,
                          float* __restrict__ pred_f,   // may be null
                          float* __restrict__ lossrow)
{
    const int b = blockIdx.x;
    const float* row = out + (long)b * CC;
    __shared__ float smax[128];
    __shared__ int   sidx[128];
    __shared__ float ssum[128];
    const int t = threadIdx.x;

    float best = -INFINITY;
    int bidx = 0;
    for (int j = t; j < CC; j += 128) {
        float v = row[j];
        if (v > best) { best = v; bidx = j; }
    }
    smax[t] = best; sidx[t] = bidx;
    __syncthreads();
    for (int s = 64; s > 0; s >>= 1) {
        if (t < s) {
            float v2 = smax[t + s]; int i2 = sidx[t + s];
            if (v2 > smax[t] || (v2 == smax[t] && i2 < sidx[t])) {
                smax[t] = v2; sidx[t] = i2;
            }
        }
        __syncthreads();
    }
    const float rowmax = smax[0];
    const int   rowarg = sidx[0];

    float lsum = 0.f;
    for (int j = t; j < CC; j += 128) lsum += expf(row[j] - rowmax);
    ssum[t] = lsum;
    __syncthreads();
    for (int s = 64; s > 0; s >>= 1) {
        if (t < s) ssum[t] += ssum[t + s];
        __syncthreads();
    }
    if (t == 0) {
        float logz = rowmax + logf(ssum[0]);
        lossrow[b] = logz - row[act[b]];
        if (pred_f) pred_f[b] = (float)rowarg;
    }
}

__global__ void mean_loss(const float* __restrict__ lossrow, float* loss_out)
{
    __shared__ float s[128];
    int t = threadIdx.x;
    s[t] = lossrow[t];
    __syncthreads();
    for (int st = 64; st > 0; st >>= 1) {
        if (t < st) s[t] += s[t + st];
        __syncthreads();
    }
    if (t == 0) *loss_out = s[0] / (float)BB;
}

// ---------------------------------------------------------------------------
// Launch
// ---------------------------------------------------------------------------
static inline dim3 gemm_grid(int M, int N)
{
    return dim3((N + BN - 1) / BN, (M + BM - 1) / BM);
}

extern "C" void kernel_launch(void* const* d_in, const int* in_sizes, int n_in,
                              void* d_out, int out_size)
{
    const float* feats    = (const float*)d_in[0];
    const float* lh       = (const float*)d_in[1];
    const float* rh       = (const float*)d_in[2];
    const int*   act      = (const int*)  d_in[3];
    const float* fc1_w    = (const float*)d_in[4];
    const float* fc1_b    = (const float*)d_in[5];
    const float* fch_w    = (const float*)d_in[6];
    const float* fch_b    = (const float*)d_in[7];
    const float* roll_wih = (const float*)d_in[8];
    const float* roll_whh = (const float*)d_in[9];
    const float* roll_bih = (const float*)d_in[10];
    const float* roll_bhh = (const float*)d_in[11];
    const float* u_wih    = (const float*)d_in[12];
    const float* u_whh    = (const float*)d_in[13];
    const float* u_bih    = (const float*)d_in[14];
    const float* u_bhh    = (const float*)d_in[15];
    const float* cls_w    = (const float*)d_in[16];
    const float* cls_b    = (const float*)d_in[17];
    float* out = (float*)d_out;

    float* scratch = nullptr;
    cudaGetSymbolAddress((void**)&scratch, g_scratch);

    float* x        = scratch + OFF_X;
    float* gates_x  = scratch + OFF_GATESX;
    float* gates_h  = scratch + OFF_GATESH;
    float* gates_xu = scratch + OFF_GATESXU;
    float* h        = scratch + OFF_H;
    float* c        = scratch + OFF_C;
    float* hands    = scratch + OFF_HANDS;
    float* lossrow  = scratch + OFF_LOSSROW;

    const int M_seq = SS * BB;   // 2048

    // 1) pack hands = concat(lh, rh)
    {
        int total = SS * BB * 2 * HANDD;
        pack_hands<<<(total + 255) / 256, 256>>>(lh, rh, hands);
    }

    // 2) xproj -> x[:, 0:H]   (M=2048, N=1024, K=2048)
    gemm_nt<<<gemm_grid(M_seq, HH), 256>>>(feats, FEATD, fc1_w, FEATD,
                                           x, 2 * HH, fc1_b, nullptr,
                                           M_seq, HH, FEATD);
    // 3) hproj -> x[:, H:2H]  (M=2048, N=1024, K=126)
    gemm_nt<<<gemm_grid(M_seq, HH), 256>>>(hands, 2 * HANDD, fch_w, 2 * HANDD,
                                           x + HH, 2 * HH, fch_b, nullptr,
                                           M_seq, HH, 2 * HANDD);
    // 4) gates_x = x @ roll_wih.T + bih + bhh   (M=2048, N=4096, K=2048)
    gemm_nt<<<gemm_grid(M_seq, 4 * HH), 256>>>(x, 2 * HH, roll_wih, 2 * HH,
                                               gates_x, 4 * HH,
                                               roll_bih, roll_bhh,
                                               M_seq, 4 * HH, 2 * HH);
    // 5) h = c = 0
    zero_kernel<<<(2 * BB * HH + 255) / 256, 256>>>(h, 2 * BB * HH);

    // 6) roll LSTM, 16 sequential steps
    for (int t = 0; t < SS; t++) {
        gemm_nt<<<gemm_grid(BB, 4 * HH), 256>>>(h, HH, roll_whh, HH,
                                                gates_h, 4 * HH,
                                                nullptr, nullptr,
                                                BB, 4 * HH, HH);
        lstm_cell<<<(BB * HH + 255) / 256, 256>>>(
            gates_x + (long)t * BB * 4 * HH, gates_h, h, c);
    }

    // 7) unroll input gates (constant across the 2 steps), input = x[S-1]
    gemm_nt<<<gemm_grid(BB, 4 * HH), 256>>>(x + (long)(SS - 1) * BB * 2 * HH,
                                            2 * HH, u_wih, 2 * HH,
                                            gates_xu, 4 * HH,
                                            u_bih, u_bhh,
                                            BB, 4 * HH, 2 * HH);
    // 8) two unroll steps (output depends only on hs_all[S-1, 1])
    for (int t = 0; t < 2; t++) {
        gemm_nt<<<gemm_grid(BB, 4 * HH), 256>>>(h, HH, u_whh, HH,
                                                gates_h, 4 * HH,
                                                nullptr, nullptr,
                                                BB, 4 * HH, HH);
        lstm_cell<<<(BB * HH + 255) / 256, 256>>>(gates_xu, gates_h, h, c);
    }

    // 9) classifier: out = h @ cls_w.T + cls_b   (128 x 1000)
    gemm_nt<<<gemm_grid(BB, CC), 256>>>(h, HH, cls_w, HH,
                                        out, CC, cls_b, nullptr,
                                        BB, CC, HH);

    // 10) pred + loss (guarded by out_size so we never overrun d_out)
    float* pred_f  = (out_size >= BB * CC + BB)     ? out + BB * CC : nullptr;
    float* loss_p  = (out_size >= BB * CC + BB + 1) ? out + BB * CC + BB : nullptr;
    row_stats<<<BB, 128>>>(out, act, pred_f, lossrow);
    if (loss_p) mean_loss<<<1, 128>>>(lossrow, loss_p);
}

// round 3
// speedup vs baseline: 1.2967x; 1.2967x over previous
#include <cuda_runtime.h>
#include <math.h>

// Problem dims (fixed by the reference)
#define SS    16
#define BB    128
#define FEATD 2048
#define HANDD 63
#define HH    1024
#define CC    1000
#define HPAD  128          // padded 2*HANDD (126 -> 128) for vector loads

// ---------------------------------------------------------------------------
// Scratch (floats), all offsets multiples of 4 -> 16B aligned rows everywhere.
// ---------------------------------------------------------------------------
#define OFF_X        0                                   // SS*BB*2H
#define OFF_GATESX   (OFF_X       + SS*BB*2*HH)          // SS*BB*4H
#define OFF_GATESH   (OFF_GATESX  + SS*BB*4*HH)          // BB*4H
#define OFF_GATESXU  (OFF_GATESH  + BB*4*HH)             // BB*4H
#define OFF_H        (OFF_GATESXU + BB*4*HH)             // BB*H
#define OFF_C        (OFF_H       + BB*HH)               // BB*H
#define OFF_HANDS    (OFF_C       + BB*HH)               // SS*BB*HPAD
#define OFF_FCHW     (OFF_HANDS   + SS*BB*HPAD)          // HH*HPAD
#define OFF_LOSSROW  (OFF_FCHW    + HH*HPAD)             // BB
#define SCRATCH_TOT  (OFF_LOSSROW + BB)

__device__ __align__(16) float g_scratch[SCRATCH_TOT];

// ---------------------------------------------------------------------------
// Tiled fp32 GEMM:  C[m,n] = sum_k A[m,k] * W[n,k]  (+ b1[n]) (+ b2[n])
// A (M,K) row-major, W (N,K) row-major. Requirements:
//   K % BK == 0, K % 4 == 0, lda/ldw % 4 == 0, M % BM == 0. N may be ragged.
// Double-buffered smem, register staging, float4 global & shared loads.
// ---------------------------------------------------------------------------
template<int BM, int BN, int BK, int TM, int TN>
__global__ void __launch_bounds__((BM/TM)*(BN/TN))
gemm_nt_t(const float* __restrict__ A, int lda,
          const float* __restrict__ W, int ldw,
          float* __restrict__ Cmat, int ldc,
          const float* __restrict__ b1,
          const float* __restrict__ b2,
          int M, int N, int K)
{
    constexpr int NT  = (BM / TM) * (BN / TN);
    constexpr int BMP = BM + 4;
    constexpr int BNP = BN + 4;
    constexpr int KQ  = BK / 4;          // float4 per row of a K-tile
    constexpr int LA  = (BM * KQ) / NT;  // float4 loads of A per thread
    constexpr int LW  = (BN * KQ) / NT;  // float4 loads of W per thread

    __shared__ float As[2][BK][BMP];
    __shared__ float Ws[2][BK][BNP];

    const int tid  = threadIdx.x;
    const int tx   = tid % (BN / TN);
    const int ty   = tid / (BN / TN);
    const int row0 = blockIdx.y * BM;
    const int col0 = blockIdx.x * BN;

    float4 regA[LA];
    float4 regW[LW];
    float  acc[TM][TN];
#pragma unroll
    for (int i = 0; i < TM; i++)
#pragma unroll
        for (int j = 0; j < TN; j++) acc[i][j] = 0.f;

    const int nk = K / BK;

    // ---- loaders (gmem -> regs) ----
    auto loadA = [&](int k0) {
#pragma unroll
        for (int l = 0; l < LA; l++) {
            int idx = tid + l * NT;
            int r   = idx / KQ;
            int kq  = idx % KQ;
            regA[l] = *reinterpret_cast<const float4*>(
                &A[(size_t)(row0 + r) * lda + k0 + kq * 4]);
        }
    };
    auto loadW = [&](int k0) {
#pragma unroll
        for (int l = 0; l < LW; l++) {
            int idx = tid + l * NT;
            int r   = idx / KQ;
            int kq  = idx % KQ;
            int gn  = col0 + r;
            if (gn < N)
                regW[l] = *reinterpret_cast<const float4*>(
                    &W[(size_t)gn * ldw + k0 + kq * 4]);
            else
                regW[l] = make_float4(0.f, 0.f, 0.f, 0.f);
        }
    };
    // ---- stores (regs -> smem, transposed) ----
    auto storeA = [&](int buf) {
#pragma unroll
        for (int l = 0; l < LA; l++) {
            int idx = tid + l * NT;
            int r   = idx / KQ;
            int kq  = idx % KQ;
            As[buf][kq * 4 + 0][r] = regA[l].x;
            As[buf][kq * 4 + 1][r] = regA[l].y;
            As[buf][kq * 4 + 2][r] = regA[l].z;
            As[buf][kq * 4 + 3][r] = regA[l].w;
        }
    };
    auto storeW = [&](int buf) {
#pragma unroll
        for (int l = 0; l < LW; l++) {
            int idx = tid + l * NT;
            int r   = idx / KQ;
            int kq  = idx % KQ;
            Ws[buf][kq * 4 + 0][r] = regW[l].x;
            Ws[buf][kq * 4 + 1][r] = regW[l].y;
            Ws[buf][kq * 4 + 2][r] = regW[l].z;
            Ws[buf][kq * 4 + 3][r] = regW[l].w;
        }
    };

    loadA(0); loadW(0);
    storeA(0); storeW(0);
    __syncthreads();

    for (int kt = 0; kt < nk; kt++) {
        const int cur = kt & 1;
        if (kt + 1 < nk) { loadA((kt + 1) * BK); loadW((kt + 1) * BK); }

#pragma unroll
        for (int k = 0; k < BK; k++) {
            float ra[TM], rb[TN];
            const float4* ap = reinterpret_cast<const float4*>(&As[cur][k][ty * TM]);
            const float4* wp = reinterpret_cast<const float4*>(&Ws[cur][k][tx * TN]);
#pragma unroll
            for (int q = 0; q < TM / 4; q++) {
                float4 v = ap[q];
                ra[q * 4 + 0] = v.x; ra[q * 4 + 1] = v.y;
                ra[q * 4 + 2] = v.z; ra[q * 4 + 3] = v.w;
            }
#pragma unroll
            for (int q = 0; q < TN / 4; q++) {
                float4 v = wp[q];
                rb[q * 4 + 0] = v.x; rb[q * 4 + 1] = v.y;
                rb[q * 4 + 2] = v.z; rb[q * 4 + 3] = v.w;
            }
#pragma unroll
            for (int i = 0; i < TM; i++)
#pragma unroll
                for (int j = 0; j < TN; j++)
                    acc[i][j] += ra[i] * rb[j];
        }

        if (kt + 1 < nk) {
            storeA(cur ^ 1); storeW(cur ^ 1);
            __syncthreads();
        }
    }

    // epilogue
#pragma unroll
    for (int i = 0; i < TM; i++) {
        int gm = row0 + ty * TM + i;
#pragma unroll
        for (int j = 0; j < TN; j++) {
            int gn = col0 + tx * TN + j;
            if (gn >= N) continue;
            float v = acc[i][j];
            if (b1) v += b1[gn];
            if (b2) v += b2[gn];
            Cmat[(size_t)gm * ldc + gn] = v;
        }
    }
}

// ---------------------------------------------------------------------------
// Small helper kernels
// ---------------------------------------------------------------------------
__global__ void zero_kernel(float* p, int n)
{
    int i = blockIdx.x * blockDim.x + threadIdx.x;
    if (i < n) p[i] = 0.f;
}

// hands padded to HPAD columns (cols 126..127 = 0)
__global__ void pack_hands(const float* __restrict__ lh,
                           const float* __restrict__ rh,
                           float* __restrict__ hands)
{
    int i = blockIdx.x * blockDim.x + threadIdx.x;
    const int total = SS * BB * HPAD;
    if (i >= total) return;
    int col = i % HPAD;
    int row = i / HPAD;
    float v = 0.f;
    if (col < HANDD)          v = lh[row * HANDD + col];
    else if (col < 2 * HANDD) v = rh[row * HANDD + (col - HANDD)];
    hands[i] = v;
}

// fch_w (H x 126) -> padded (H x 128)
__global__ void pad_fchw(const float* __restrict__ w, float* __restrict__ wp)
{
    int i = blockIdx.x * blockDim.x + threadIdx.x;
    const int total = HH * HPAD;
    if (i >= total) return;
    int col = i % HPAD;
    int row = i / HPAD;
    wp[i] = (col < 2 * HANDD) ? w[row * 2 * HANDD + col] : 0.f;
}

// gates order (JAX split): [i | f | g | o], each H wide
__global__ void lstm_cell(const float* __restrict__ gx,
                          const float* __restrict__ gh,
                          float* __restrict__ h,
                          float* __restrict__ c)
{
    int i = blockIdx.x * blockDim.x + threadIdx.x;
    if (i >= BB * HH) return;
    int b = i / HH, j = i % HH;
    const float* gxr = gx + (size_t)b * 4 * HH;
    const float* ghr = gh + (size_t)b * 4 * HH;
    float gi = gxr[j]          + ghr[j];
    float gf = gxr[HH + j]     + ghr[HH + j];
    float gg = gxr[2 * HH + j] + ghr[2 * HH + j];
    float go = gxr[3 * HH + j] + ghr[3 * HH + j];
    float si = 1.f / (1.f + expf(-gi));
    float sf = 1.f / (1.f + expf(-gf));
    float so = 1.f / (1.f + expf(-go));
    float tg = tanhf(gg);
    float cn = sf * c[i] + si * tg;
    float hn = so * tanhf(cn);
    c[i] = cn;
    h[i] = hn;
}

// Per-row: argmax (first-max tie-break) + logsumexp loss term.
__global__ void row_stats(const float* __restrict__ out,
                          const int* __restrict__ act,
                          float* __restrict__ pred_f,   // may be null
                          float* __restrict__ lossrow)
{
    const int b = blockIdx.x;
    const float* row = out + (size_t)b * CC;
    __shared__ float smax[128];
    __shared__ int   sidx[128];
    __shared__ float ssum[128];
    const int t = threadIdx.x;

    float best = -INFINITY;
    int bidx = 0;
    for (int j = t; j < CC; j += 128) {
        float v = row[j];
        if (v > best) { best = v; bidx = j; }
    }
    smax[t] = best; sidx[t] = bidx;
    __syncthreads();
    for (int s = 64; s > 0; s >>= 1) {
        if (t < s) {
            float v2 = smax[t + s]; int i2 = sidx[t + s];
            if (v2 > smax[t] || (v2 == smax[t] && i2 < sidx[t])) {
                smax[t] = v2; sidx[t] = i2;
            }
        }
        __syncthreads();
    }
    const float rowmax = smax[0];
    const int   rowarg = sidx[0];

    float lsum = 0.f;
    for (int j = t; j < CC; j += 128) lsum += expf(row[j] - rowmax);
    ssum[t] = lsum;
    __syncthreads();
    for (int s = 64; s > 0; s >>= 1) {
        if (t < s) ssum[t] += ssum[t + s];
        __syncthreads();
    }
    if (t == 0) {
        float logz = rowmax + logf(ssum[0]);
        lossrow[b] = logz - row[act[b]];
        if (pred_f) pred_f[b] = (float)rowarg;
    }
}

__global__ void mean_loss(const float* __restrict__ lossrow, float* loss_out)
{
    __shared__ float s[128];
    int t = threadIdx.x;
    s[t] = lossrow[t];
    __syncthreads();
    for (int st = 64; st > 0; st >>= 1) {
        if (t < st) s[t] += s[t + st];
        __syncthreads();
    }
    if (t == 0) *loss_out = s[0] / (float)BB;
}

// ---------------------------------------------------------------------------
// Launch
// ---------------------------------------------------------------------------
// big: 128x128 tile, 256 threads, 8x8 micro  — for M=2048 matrices
// sml: 64x64 tile,   64 threads, 8x8 micro   — for M=128 matrices (+hproj)
static inline dim3 grid_big(int M, int N) { return dim3((N + 127) / 128, M / 128); }
static inline dim3 grid_sml(int M, int N) { return dim3((N + 63) / 64,  M / 64); }

#define GEMM_BIG gemm_nt_t<128,128,16,8,8>
#define GEMM_SML gemm_nt_t<64, 64, 16,8,8>

extern "C" void kernel_launch(void* const* d_in, const int* in_sizes, int n_in,
                              void* d_out, int out_size)
{
    const float* feats    = (const float*)d_in[0];
    const float* lh       = (const float*)d_in[1];
    const float* rh       = (const float*)d_in[2];
    const int*   act      = (const int*)  d_in[3];
    const float* fc1_w    = (const float*)d_in[4];
    const float* fc1_b    = (const float*)d_in[5];
    const float* fch_w    = (const float*)d_in[6];
    const float* fch_b    = (const float*)d_in[7];
    const float* roll_wih = (const float*)d_in[8];
    const float* roll_whh = (const float*)d_in[9];
    const float* roll_bih = (const float*)d_in[10];
    const float* roll_bhh = (const float*)d_in[11];
    const float* u_wih    = (const float*)d_in[12];
    const float* u_whh    = (const float*)d_in[13];
    const float* u_bih    = (const float*)d_in[14];
    const float* u_bhh    = (const float*)d_in[15];
    const float* cls_w    = (const float*)d_in[16];
    const float* cls_b    = (const float*)d_in[17];
    float* out = (float*)d_out;

    float* scratch = nullptr;
    cudaGetSymbolAddress((void**)&scratch, g_scratch);

    float* x        = scratch + OFF_X;
    float* gates_x  = scratch + OFF_GATESX;
    float* gates_h  = scratch + OFF_GATESH;
    float* gates_xu = scratch + OFF_GATESXU;
    float* h        = scratch + OFF_H;
    float* c        = scratch + OFF_C;
    float* hands    = scratch + OFF_HANDS;
    float* fchw_p   = scratch + OFF_FCHW;
    float* lossrow  = scratch + OFF_LOSSROW;

    const int M_seq = SS * BB;   // 2048

    // 0) pack padded hands + padded fch weight
    pack_hands<<<(SS * BB * HPAD + 255) / 256, 256>>>(lh, rh, hands);
    pad_fchw<<<(HH * HPAD + 255) / 256, 256>>>(fch_w, fchw_p);
    // 0b) h = c = 0
    zero_kernel<<<(2 * BB * HH + 255) / 256, 256>>>(h, 2 * BB * HH);

    // 1) xproj -> x[:, 0:H]   (M=2048, N=1024, K=2048)
    GEMM_BIG<<<grid_big(M_seq, HH), 256>>>(feats, FEATD, fc1_w, FEATD,
                                           x, 2 * HH, fc1_b, nullptr,
                                           M_seq, HH, FEATD);
    // 2) hproj -> x[:, H:2H]  (M=2048, N=1024, K=128 padded)
    GEMM_SML<<<grid_sml(M_seq, HH), 64>>>(hands, HPAD, fchw_p, HPAD,
                                          x + HH, 2 * HH, fch_b, nullptr,
                                          M_seq, HH, HPAD);
    // 3) gates_x = x @ roll_wih.T + bih + bhh   (M=2048, N=4096, K=2048)
    GEMM_BIG<<<grid_big(M_seq, 4 * HH), 256>>>(x, 2 * HH, roll_wih, 2 * HH,
                                               gates_x, 4 * HH,
                                               roll_bih, roll_bhh,
                                               M_seq, 4 * HH, 2 * HH);

    // 4) roll LSTM, 16 sequential steps (M=128 -> 64x64 tiles, 128 CTAs)
    for (int t = 0; t < SS; t++) {
        GEMM_SML<<<grid_sml(BB, 4 * HH), 64>>>(h, HH, roll_whh, HH,
                                               gates_h, 4 * HH,
                                               nullptr, nullptr,
                                               BB, 4 * HH, HH);
        lstm_cell<<<(BB * HH + 255) / 256, 256>>>(
            gates_x + (size_t)t * BB * 4 * HH, gates_h, h, c);
    }

    // 5) unroll input gates (constant across the 2 steps), input = x[S-1]
    GEMM_SML<<<grid_sml(BB, 4 * HH), 64>>>(x + (size_t)(SS - 1) * BB * 2 * HH,
                                           2 * HH, u_wih, 2 * HH,
                                           gates_xu, 4 * HH,
                                           u_bih, u_bhh,
                                           BB, 4 * HH, 2 * HH);
    // 6) two unroll steps (output depends only on hs_all[S-1, 1])
    for (int t = 0; t < 2; t++) {
        GEMM_SML<<<grid_sml(BB, 4 * HH), 64>>>(h, HH, u_whh, HH,
                                               gates_h, 4 * HH,
                                               nullptr, nullptr,
                                               BB, 4 * HH, HH);
        lstm_cell<<<(BB * HH + 255) / 256, 256>>>(gates_xu, gates_h, h, c);
    }

    // 7) classifier: out = h @ cls_w.T + cls_b   (128 x 1000, K=1024)
    GEMM_SML<<<grid_sml(BB, CC), 64>>>(h, HH, cls_w, HH,
                                       out, CC, cls_b, nullptr,
                                       BB, CC, HH);

    // 8) pred + loss (guarded by out_size so we never overrun d_out)
    float* pred_f = (out_size >= BB * CC + BB)     ? out + BB * CC : nullptr;
    float* loss_p = (out_size >= BB * CC + BB + 1) ? out + BB * CC + BB : nullptr;
    row_stats<<<BB, 128>>>(out, act, pred_f, lossrow);
    if (loss_p) mean_loss<<<1, 128>>>(lossrow, loss_p);
}

// round 5
// speedup vs baseline: 1.7846x; 1.3762x over previous
#include <cuda_runtime.h>
#include <math.h>
#include <stdint.h>

// Problem dims (fixed by the reference)
#define SS    16
#define BB    128
#define FEATD 2048
#define HANDD 63
#define HH    1024
#define CC    1000
#define HPAD  128          // padded 2*HANDD (126 -> 128)

// ---------------------------------------------------------------------------
// Scratch (floats)
// ---------------------------------------------------------------------------
#define OFF_X        0                                   // SS*BB*2H
#define OFF_GATESX   (OFF_X       + SS*BB*2*HH)          // SS*BB*4H (permuted cols)
#define OFF_GATESXU  (OFF_GATESX  + SS*BB*4*HH)          // BB*4H    (permuted cols)
#define OFF_H0       (OFF_GATESXU + BB*4*HH)             // BB*H
#define OFF_C        (OFF_H0      + BB*HH)               // BB*H   (adjacent to H0 -> one zero pass)
#define OFF_H1       (OFF_C       + BB*HH)               // BB*H
#define OFF_HANDS    (OFF_H1      + BB*HH)               // SS*BB*HPAD
#define OFF_FCHW     (OFF_HANDS   + SS*BB*HPAD)          // HH*HPAD
#define OFF_LOSSROW  (OFF_FCHW    + HH*HPAD)             // BB
#define SCRATCH_TOT  (OFF_LOSSROW + BB)

__device__ __align__(16) float g_scratch[SCRATCH_TOT];

// ---------------------------------------------------------------------------
// 3xTF32 helpers
// ---------------------------------------------------------------------------
__device__ __forceinline__ void split_tf32(float v, float& hi, float& lo)
{
    uint32_t u;
    asm("cvt.rna.tf32.f32 %0, %1;" : "=r"(u) : "f"(v));
    hi = __uint_as_float(u);
    float r = v - hi;
    uint32_t u2;
    asm("cvt.rna.tf32.f32 %0, %1;" : "=r"(u2) : "f"(r));
    lo = __uint_as_float(u2);
}

#define MMA_TF32(d, a, b)                                                     \
    asm volatile(                                                             \
        "mma.sync.aligned.m16n8k8.row.col.f32.tf32.tf32.f32 "                 \
        "{%0,%1,%2,%3},{%4,%5,%6,%7},{%8,%9},{%0,%1,%2,%3};"                  \
        : "+f"(d[0]), "+f"(d[1]), "+f"(d[2]), "+f"(d[3])                      \
        : "r"(a[0]), "r"(a[1]), "r"(a[2]), "r"(a[3]), "r"(b[0]), "r"(b[1]))

__device__ __forceinline__ uint32_t fbits(float f) { return __float_as_uint(f); }

// ---------------------------------------------------------------------------
// Big GEMM (3xTF32):  C[m,n] = sum_k A[m,k]*W[wrow(n),k]  (+b1[wrow(n)])(+b2)
// BM=128, BN=128, BK=16, 256 threads (8 warps: 2(M) x 4(N), warp tile 64x32)
// Requirements: M%128==0, K%16==0, lda/ldw%4==0. N may be ragged.
// PERM: W row / bias index mapping n -> (n&3)*HH + (n>>2)  (gate interleave)
// ---------------------------------------------------------------------------
template<int PERM>
__global__ void __launch_bounds__(256)
gemm3(const float* __restrict__ A, int lda,
      const float* __restrict__ W, int ldw,
      float* __restrict__ C, int ldc,
      const float* __restrict__ b1,
      const float* __restrict__ b2,
      int M, int N, int K)
{
    __shared__ float AsH[128][20], AsL[128][20];
    __shared__ float BsH[128][20], BsL[128][20];

    const int tid  = threadIdx.x;
    const int lane = tid & 31;
    const int warp = tid >> 5;
    const int wm   = warp >> 2;          // 0..1
    const int wn   = warp & 3;           // 0..3
    const int row0 = blockIdx.y * 128;
    const int col0 = blockIdx.x * 128;

    float acc[4][4][4];
#pragma unroll
    for (int i = 0; i < 4; i++)
#pragma unroll
        for (int j = 0; j < 4; j++)
#pragma unroll
            for (int q = 0; q < 4; q++) acc[i][j][q] = 0.f;

    const int kq_ld = tid & 3;
    float4 stA[2], stB[2];

    auto gload = [&](int k0) {
#pragma unroll
        for (int l = 0; l < 2; l++) {
            int r = (tid >> 2) + l * 64;
            stA[l] = *reinterpret_cast<const float4*>(
                &A[(size_t)(row0 + r) * lda + k0 + kq_ld * 4]);
            int gn = col0 + r;
            int gr = PERM ? ((gn & 3) * HH + (gn >> 2)) : gn;
            if (gn < N)
                stB[l] = *reinterpret_cast<const float4*>(
                    &W[(size_t)gr * ldw + k0 + kq_ld * 4]);
            else
                stB[l] = make_float4(0.f, 0.f, 0.f, 0.f);
        }
    };
    auto sstore = [&]() {
#pragma unroll
        for (int l = 0; l < 2; l++) {
            int r = (tid >> 2) + l * 64;
            int c = kq_ld * 4;
            float4 h4, l4;
            split_tf32(stA[l].x, h4.x, l4.x);
            split_tf32(stA[l].y, h4.y, l4.y);
            split_tf32(stA[l].z, h4.z, l4.z);
            split_tf32(stA[l].w, h4.w, l4.w);
            *reinterpret_cast<float4*>(&AsH[r][c]) = h4;
            *reinterpret_cast<float4*>(&AsL[r][c]) = l4;
            split_tf32(stB[l].x, h4.x, l4.x);
            split_tf32(stB[l].y, h4.y, l4.y);
            split_tf32(stB[l].z, h4.z, l4.z);
            split_tf32(stB[l].w, h4.w, l4.w);
            *reinterpret_cast<float4*>(&BsH[r][c]) = h4;
            *reinterpret_cast<float4*>(&BsL[r][c]) = l4;
        }
    };

    const int nk = K / 16;
    gload(0);
    sstore();
    __syncthreads();

    for (int kt = 0; kt < nk; kt++) {
        if (kt + 1 < nk) gload((kt + 1) * 16);

#pragma unroll
        for (int k8 = 0; k8 < 2; k8++) {
            const int kb = k8 * 8;
            uint32_t aH[4][4], aL[4][4];
#pragma unroll
            for (int mt = 0; mt < 4; mt++) {
                int r = wm * 64 + mt * 16 + (lane >> 2);
                int c = kb + (lane & 3);
                aH[mt][0] = fbits(AsH[r][c]);
                aH[mt][1] = fbits(AsH[r + 8][c]);
                aH[mt][2] = fbits(AsH[r][c + 4]);
                aH[mt][3] = fbits(AsH[r + 8][c + 4]);
                aL[mt][0] = fbits(AsL[r][c]);
                aL[mt][1] = fbits(AsL[r + 8][c]);
                aL[mt][2] = fbits(AsL[r][c + 4]);
                aL[mt][3] = fbits(AsL[r + 8][c + 4]);
            }
            uint32_t bH[4][2], bL[4][2];
#pragma unroll
            for (int nt = 0; nt < 4; nt++) {
                int n = wn * 32 + nt * 8 + (lane >> 2);
                int c = kb + (lane & 3);
                bH[nt][0] = fbits(BsH[n][c]);
                bH[nt][1] = fbits(BsH[n][c + 4]);
                bL[nt][0] = fbits(BsL[n][c]);
                bL[nt][1] = fbits(BsL[n][c + 4]);
            }
#pragma unroll
            for (int mt = 0; mt < 4; mt++)
#pragma unroll
                for (int nt = 0; nt < 4; nt++) {
                    MMA_TF32(acc[mt][nt], aH[mt], bH[nt]);
                    MMA_TF32(acc[mt][nt], aH[mt], bL[nt]);
                    MMA_TF32(acc[mt][nt], aL[mt], bH[nt]);
                }
        }

        if (kt + 1 < nk) {
            __syncthreads();
            sstore();
            __syncthreads();
        }
    }

    // epilogue
    auto biasAt = [&](int n) -> float {
        float v = 0.f;
        int bi = PERM ? ((n & 3) * HH + (n >> 2)) : n;
        if (b1) v += b1[bi];
        if (b2) v += b2[bi];
        return v;
    };
#pragma unroll
    for (int mt = 0; mt < 4; mt++)
#pragma unroll
        for (int nt = 0; nt < 4; nt++) {
            int m = row0 + wm * 64 + mt * 16 + (lane >> 2);
            int n = col0 + wn * 32 + nt * 8 + 2 * (lane & 3);
            if (n + 1 < N) {
                float bv0 = biasAt(n), bv1 = biasAt(n + 1);
                float2 v0 = make_float2(acc[mt][nt][0] + bv0, acc[mt][nt][1] + bv1);
                float2 v1 = make_float2(acc[mt][nt][2] + bv0, acc[mt][nt][3] + bv1);
                *reinterpret_cast<float2*>(&C[(size_t)m * ldc + n]) = v0;
                *reinterpret_cast<float2*>(&C[(size_t)(m + 8) * ldc + n]) = v1;
            } else if (n < N) {
                float bv0 = biasAt(n);
                C[(size_t)m * ldc + n] = acc[mt][nt][0] + bv0;
                C[(size_t)(m + 8) * ldc + n] = acc[mt][nt][2] + bv0;
            }
        }
}

// ---------------------------------------------------------------------------
// Fused LSTM step (3xTF32 GEMM + cell epilogue), gate-interleaved layout.
// gates_h[b, p] = sum_k h[b,k] * whh[(p&3)*HH + (p>>2), k]
// grid.x = 4096/32 = 128 CTAs, 128 threads (4 warps over M, warp tile 32x32).
// Epilogue: g = gates_h + gx (gx includes both biases); LSTM cell; writes
// hout and c (in place) for this CTA's 8 hidden units x 128 batches.
// ---------------------------------------------------------------------------
__global__ void __launch_bounds__(128)
lstm_step_fused(const float* __restrict__ hin,
                const float* __restrict__ whh,
                const float* __restrict__ gx,     // [BB][4H] permuted
                float* __restrict__ c,            // [BB][H] in/out
                float* __restrict__ hout)         // [BB][H]
{
    __shared__ float AsH[128][20], AsL[128][20];
    __shared__ float BsH[32][20],  BsL[32][20];
    __shared__ float gsum[128][36];

    const int tid  = threadIdx.x;
    const int lane = tid & 31;
    const int warp = tid >> 5;           // 0..3 -> M
    const int col0 = blockIdx.x * 32;

    float acc[2][4][4];
#pragma unroll
    for (int i = 0; i < 2; i++)
#pragma unroll
        for (int j = 0; j < 4; j++)
#pragma unroll
            for (int q = 0; q < 4; q++) acc[i][j][q] = 0.f;

    const int kq_ld = tid & 3;
    float4 stA[4], stB;

    auto gload = [&](int k0) {
#pragma unroll
        for (int l = 0; l < 4; l++) {
            int r = (tid >> 2) + l * 32;
            stA[l] = *reinterpret_cast<const float4*>(
                &hin[(size_t)r * HH + k0 + kq_ld * 4]);
        }
        int gn = col0 + (tid >> 2);
        int gr = (gn & 3) * HH + (gn >> 2);
        stB = *reinterpret_cast<const float4*>(
            &whh[(size_t)gr * HH + k0 + kq_ld * 4]);
    };
    auto sstore = [&]() {
#pragma unroll
        for (int l = 0; l < 4; l++) {
            int r = (tid >> 2) + l * 32;
            int cc = kq_ld * 4;
            float4 h4, l4;
            split_tf32(stA[l].x, h4.x, l4.x);
            split_tf32(stA[l].y, h4.y, l4.y);
            split_tf32(stA[l].z, h4.z, l4.z);
            split_tf32(stA[l].w, h4.w, l4.w);
            *reinterpret_cast<float4*>(&AsH[r][cc]) = h4;
            *reinterpret_cast<float4*>(&AsL[r][cc]) = l4;
        }
        {
            int r = tid >> 2;
            int cc = kq_ld * 4;
            float4 h4, l4;
            split_tf32(stB.x, h4.x, l4.x);
            split_tf32(stB.y, h4.y, l4.y);
            split_tf32(stB.z, h4.z, l4.z);
            split_tf32(stB.w, h4.w, l4.w);
            *reinterpret_cast<float4*>(&BsH[r][cc]) = h4;
            *reinterpret_cast<float4*>(&BsL[r][cc]) = l4;
        }
    };

    const int nk = HH / 16;      // 64
    gload(0);
    sstore();
    __syncthreads();

    for (int kt = 0; kt < nk; kt++) {
        if (kt + 1 < nk) gload((kt + 1) * 16);

#pragma unroll
        for (int k8 = 0; k8 < 2; k8++) {
            const int kb = k8 * 8;
            uint32_t aH[2][4], aL[2][4];
#pragma unroll
            for (int mt = 0; mt < 2; mt++) {
                int r = warp * 32 + mt * 16 + (lane >> 2);
                int cc = kb + (lane & 3);
                aH[mt][0] = fbits(AsH[r][cc]);
                aH[mt][1] = fbits(AsH[r + 8][cc]);
                aH[mt][2] = fbits(AsH[r][cc + 4]);
                aH[mt][3] = fbits(AsH[r + 8][cc + 4]);
                aL[mt][0] = fbits(AsL[r][cc]);
                aL[mt][1] = fbits(AsL[r + 8][cc]);
                aL[mt][2] = fbits(AsL[r][cc + 4]);
                aL[mt][3] = fbits(AsL[r + 8][cc + 4]);
            }
            uint32_t bH[4][2], bL[4][2];
#pragma unroll
            for (int nt = 0; nt < 4; nt++) {
                int n = nt * 8 + (lane >> 2);
                int cc = kb + (lane & 3);
                bH[nt][0] = fbits(BsH[n][cc]);
                bH[nt][1] = fbits(BsH[n][cc + 4]);
                bL[nt][0] = fbits(BsL[n][cc]);
                bL[nt][1] = fbits(BsL[n][cc + 4]);
            }
#pragma unroll
            for (int mt = 0; mt < 2; mt++)
#pragma unroll
                for (int nt = 0; nt < 4; nt++) {
                    MMA_TF32(acc[mt][nt], aH[mt], bH[nt]);
                    MMA_TF32(acc[mt][nt], aH[mt], bL[nt]);
                    MMA_TF32(acc[mt][nt], aL[mt], bH[nt]);
                }
        }

        if (kt + 1 < nk) {
            __syncthreads();
            sstore();
            __syncthreads();
        }
    }

    // dump accumulators to smem tile
#pragma unroll
    for (int mt = 0; mt < 2; mt++)
#pragma unroll
        for (int nt = 0; nt < 4; nt++) {
            int m = warp * 32 + mt * 16 + (lane >> 2);
            int n = nt * 8 + 2 * (lane & 3);
            gsum[m][n]     = acc[mt][nt][0];
            gsum[m][n + 1] = acc[mt][nt][1];
            gsum[m + 8][n]     = acc[mt][nt][2];
            gsum[m + 8][n + 1] = acc[mt][nt][3];
        }
    __syncthreads();

    // cell: 128 batches x 8 hidden units
#pragma unroll
    for (int q = 0; q < 8; q++) {
        int idx = tid + q * 128;
        int b = idx >> 3;
        int jj = idx & 7;
        float4 g  = *reinterpret_cast<float4*>(&gsum[b][jj * 4]);
        float4 gv = *reinterpret_cast<const float4*>(
            &gx[(size_t)b * (4 * HH) + col0 + jj * 4]);
        float gi = g.x + gv.x;
        float gf = g.y + gv.y;
        float gg = g.z + gv.z;
        float go = g.w + gv.w;
        float si = 1.f / (1.f + expf(-gi));
        float sf = 1.f / (1.f + expf(-gf));
        float so = 1.f / (1.f + expf(-go));
        float tg = tanhf(gg);
        int j = (col0 >> 2) + jj;
        float cn = sf * c[(size_t)b * HH + j] + si * tg;
        float hn = so * tanhf(cn);
        c[(size_t)b * HH + j] = cn;
        hout[(size_t)b * HH + j] = hn;
    }
}

// ---------------------------------------------------------------------------
// Small helper kernels
// ---------------------------------------------------------------------------
__global__ void zero_kernel(float* p, int n)
{
    int i = blockIdx.x * blockDim.x + threadIdx.x;
    if (i < n) p[i] = 0.f;
}

__global__ void pack_hands(const float* __restrict__ lh,
                           const float* __restrict__ rh,
                           float* __restrict__ hands)
{
    int i = blockIdx.x * blockDim.x + threadIdx.x;
    const int total = SS * BB * HPAD;
    if (i >= total) return;
    int col = i % HPAD;
    int row = i / HPAD;
    float v = 0.f;
    if (col < HANDD)          v = lh[row * HANDD + col];
    else if (col < 2 * HANDD) v = rh[row * HANDD + (col - HANDD)];
    hands[i] = v;
}

__global__ void pad_fchw(const float* __restrict__ w, float* __restrict__ wp)
{
    int i = blockIdx.x * blockDim.x + threadIdx.x;
    const int total = HH * HPAD;
    if (i >= total) return;
    int col = i % HPAD;
    int row = i / HPAD;
    wp[i] = (col < 2 * HANDD) ? w[row * 2 * HANDD + col] : 0.f;
}

__global__ void row_stats(const float* __restrict__ out,
                          const int* __restrict__ act,
                          float* __restrict__ pred_f,
                          float* __restrict__ lossrow)
{
    const int b = blockIdx.x;
    const float* row = out + (size_t)b * CC;
    __shared__ float smax[128];
    __shared__ int   sidx[128];
    __shared__ float ssum[128];
    const int t = threadIdx.x;

    float best = -INFINITY;
    int bidx = 0;
    for (int j = t; j < CC; j += 128) {
        float v = row[j];
        if (v > best) { best = v; bidx = j; }
    }
    smax[t] = best; sidx[t] = bidx;
    __syncthreads();
    for (int s = 64; s > 0; s >>= 1) {
        if (t < s) {
            float v2 = smax[t + s]; int i2 = sidx[t + s];
            if (v2 > smax[t] || (v2 == smax[t] && i2 < sidx[t])) {
                smax[t] = v2; sidx[t] = i2;
            }
        }
        __syncthreads();
    }
    const float rowmax = smax[0];
    const int   rowarg = sidx[0];

    float lsum = 0.f;
    for (int j = t; j < CC; j += 128) lsum += expf(row[j] - rowmax);
    ssum[t] = lsum;
    __syncthreads();
    for (int s = 64; s > 0; s >>= 1) {
        if (t < s) ssum[t] += ssum[t + s];
        __syncthreads();
    }
    if (t == 0) {
        float logz = rowmax + logf(ssum[0]);
        lossrow[b] = logz - row[act[b]];
        if (pred_f) pred_f[b] = (float)rowarg;
    }
}

__global__ void mean_loss(const float* __restrict__ lossrow, float* loss_out)
{
    __shared__ float s[128];
    int t = threadIdx.x;
    s[t] = lossrow[t];
    __syncthreads();
    for (int st = 64; st > 0; st >>= 1) {
        if (t < st) s[t] += s[t + st];
        __syncthreads();
    }
    if (t == 0) *loss_out = s[0] / (float)BB;
}

// ---------------------------------------------------------------------------
// Launch
// ---------------------------------------------------------------------------
static inline dim3 grid128(int M, int N) { return dim3((N + 127) / 128, M / 128); }

extern "C" void kernel_launch(void* const* d_in, const int* in_sizes, int n_in,
                              void* d_out, int out_size)
{
    const float* feats    = (const float*)d_in[0];
    const float* lh       = (const float*)d_in[1];
    const float* rh       = (const float*)d_in[2];
    const int*   act      = (const int*)  d_in[3];
    const float* fc1_w    = (const float*)d_in[4];
    const float* fc1_b    = (const float*)d_in[5];
    const float* fch_w    = (const float*)d_in[6];
    const float* fch_b    = (const float*)d_in[7];
    const float* roll_wih = (const float*)d_in[8];
    const float* roll_whh = (const float*)d_in[9];
    const float* roll_bih = (const float*)d_in[10];
    const float* roll_bhh = (const float*)d_in[11];
    const float* u_wih    = (const float*)d_in[12];
    const float* u_whh    = (const float*)d_in[13];
    const float* u_bih    = (const float*)d_in[14];
    const float* u_bhh    = (const float*)d_in[15];
    const float* cls_w    = (const float*)d_in[16];
    const float* cls_b    = (const float*)d_in[17];
    float* out = (float*)d_out;

    float* scratch = nullptr;
    cudaGetSymbolAddress((void**)&scratch, g_scratch);

    float* x        = scratch + OFF_X;
    float* gates_x  = scratch + OFF_GATESX;
    float* gates_xu = scratch + OFF_GATESXU;
    float* h0       = scratch + OFF_H0;
    float* c        = scratch + OFF_C;
    float* h1       = scratch + OFF_H1;
    float* hands    = scratch + OFF_HANDS;
    float* fchw_p   = scratch + OFF_FCHW;
    float* lossrow  = scratch + OFF_LOSSROW;
    float* hbuf[2]  = { h0, h1 };

    const int M_seq = SS * BB;   // 2048

    // 0) packing + zero init (h0 and c are adjacent)
    pack_hands<<<(SS * BB * HPAD + 255) / 256, 256>>>(lh, rh, hands);
    pad_fchw<<<(HH * HPAD + 255) / 256, 256>>>(fch_w, fchw_p);
    zero_kernel<<<(2 * BB * HH + 255) / 256, 256>>>(h0, 2 * BB * HH);

    // 1) xproj -> x[:, 0:H]
    gemm3<0><<<grid128(M_seq, HH), 256>>>(feats, FEATD, fc1_w, FEATD,
                                          x, 2 * HH, fc1_b, nullptr,
                                          M_seq, HH, FEATD);
    // 2) hproj -> x[:, H:2H]
    gemm3<0><<<grid128(M_seq, HH), 256>>>(hands, HPAD, fchw_p, HPAD,
                                          x + HH, 2 * HH, fch_b, nullptr,
                                          M_seq, HH, HPAD);
    // 3) gates_x = x @ P(roll_wih).T + P(bih + bhh)  (permuted gate columns)
    gemm3<1><<<grid128(M_seq, 4 * HH), 256>>>(x, 2 * HH, roll_wih, 2 * HH,
                                              gates_x, 4 * HH,
                                              roll_bih, roll_bhh,
                                              M_seq, 4 * HH, 2 * HH);
    // 4) gates_xu = x[S-1] @ P(u_wih).T + P(u biases)
    gemm3<1><<<grid128(BB, 4 * HH), 256>>>(x + (size_t)(SS - 1) * BB * 2 * HH,
                                           2 * HH, u_wih, 2 * HH,
                                           gates_xu, 4 * HH,
                                           u_bih, u_bhh,
                                           BB, 4 * HH, 2 * HH);

    // 5) roll LSTM: 16 fused steps (h ping-pong, c in place)
    int cur = 0;
    for (int t = 0; t < SS; t++) {
        lstm_step_fused<<<4 * HH / 32, 128>>>(hbuf[cur], roll_whh,
                                              gates_x + (size_t)t * BB * 4 * HH,
                                              c, hbuf[cur ^ 1]);
        cur ^= 1;
    }
    // 6) two unroll steps
    for (int t = 0; t < 2; t++) {
        lstm_step_fused<<<4 * HH / 32, 128>>>(hbuf[cur], u_whh,
                                              gates_xu, c, hbuf[cur ^ 1]);
        cur ^= 1;
    }

    // 7) classifier: out = h @ cls_w.T + cls_b   (128 x 1000, K=1024)
    gemm3<0><<<grid128(BB, CC), 256>>>(hbuf[cur], HH, cls_w, HH,
                                       out, CC, cls_b, nullptr,
                                       BB, CC, HH);

    // 8) pred + loss (guarded by out_size so we never overrun d_out)
    float* pred_f = (out_size >= BB * CC + BB)     ? out + BB * CC : nullptr;
    float* loss_p = (out_size >= BB * CC + BB + 1) ? out + BB * CC + BB : nullptr;
    row_stats<<<BB, 128>>>(out, act, pred_f, lossrow);
    if (loss_p) mean_loss<<<1, 128>>>(lossrow, loss_p);
}

// round 6
// speedup vs baseline: 1.8587x; 1.0415x over previous
#include <cuda_runtime.h>
#include <math.h>
#include <stdint.h>

#define SS    16
#define BB    128
#define FEATD 2048
#define HANDD 63
#define HH    1024
#define CC    1000
#define HPAD  128

// ---------------------------------------------------------------------------
// Scratch layout (floats)
// ---------------------------------------------------------------------------
#define OFF_FEATSH  0
#define OFF_FEATSL  (OFF_FEATSH + SS*BB*FEATD)
#define OFF_XH      (OFF_FEATSL + SS*BB*FEATD)
#define OFF_XL      (OFF_XH     + SS*BB*2*HH)
#define OFF_GATESX  (OFF_XL     + SS*BB*2*HH)
#define OFF_GATESXU (OFF_GATESX + SS*BB*4*HH)
#define OFF_C       (OFF_GATESXU+ BB*4*HH)
#define OFF_H0H     (OFF_C      + BB*HH)
#define OFF_H0L     (OFF_H0H    + BB*HH)
#define OFF_H1H     (OFF_H0L    + BB*HH)
#define OFF_H1L     (OFF_H1H    + BB*HH)
#define OFF_HANDSH  (OFF_H1L    + BB*HH)
#define OFF_HANDSL  (OFF_HANDSH + SS*BB*HPAD)
#define OFF_FC1H    (OFF_HANDSL + SS*BB*HPAD)
#define OFF_FC1L    (OFF_FC1H   + HH*FEATD)
#define OFF_FCHWH   (OFF_FC1L   + HH*FEATD)
#define OFF_FCHWL   (OFF_FCHWH  + HH*HPAD)
#define OFF_RWIHH   (OFF_FCHWL  + HH*HPAD)
#define OFF_RWIHL   (OFF_RWIHH  + 4*HH*2*HH)
#define OFF_RWHHH   (OFF_RWIHL  + 4*HH*2*HH)
#define OFF_RWHHL   (OFF_RWHHH  + 4*HH*HH)
#define OFF_UWIHH   (OFF_RWHHL  + 4*HH*HH)
#define OFF_UWIHL   (OFF_UWIHH  + 4*HH*2*HH)
#define OFF_UWHHH   (OFF_UWIHL  + 4*HH*2*HH)
#define OFF_UWHHL   (OFF_UWHHH  + 4*HH*HH)
#define OFF_CLSH    (OFF_UWHHL  + 4*HH*HH)
#define OFF_CLSL    (OFF_CLSH   + 1024*HH)
#define OFF_LOSSROW (OFF_CLSL   + 1024*HH)
#define SCRATCH_TOT (OFF_LOSSROW + BB)

__device__ __align__(16) float g_scratch[SCRATCH_TOT];

// ---------------------------------------------------------------------------
// helpers
// ---------------------------------------------------------------------------
__device__ __forceinline__ void split_tf32(float v, float& hi, float& lo)
{
    uint32_t u;
    asm("cvt.rna.tf32.f32 %0, %1;" : "=r"(u) : "f"(v));
    hi = __uint_as_float(u);
    float r = v - hi;
    uint32_t u2;
    asm("cvt.rna.tf32.f32 %0, %1;" : "=r"(u2) : "f"(r));
    lo = __uint_as_float(u2);
}

#define MMA_TF32(d, a, b)                                                     \
    asm volatile(                                                             \
        "mma.sync.aligned.m16n8k8.row.col.f32.tf32.tf32.f32 "                 \
        "{%0,%1,%2,%3},{%4,%5,%6,%7},{%8,%9},{%0,%1,%2,%3};"                  \
        : "+f"(d[0]), "+f"(d[1]), "+f"(d[2]), "+f"(d[3])                      \
        : "r"(a[0]), "r"(a[1]), "r"(a[2]), "r"(a[3]), "r"(b[0]), "r"(b[1]))

__device__ __forceinline__ uint32_t fbits(float f) { return __float_as_uint(f); }

__device__ __forceinline__ void cp16(uint32_t dst, const void* src)
{
    asm volatile("cp.async.cg.shared.global [%0], [%1], 16;" :: "r"(dst), "l"(src));
}
__device__ __forceinline__ void cp_commit() { asm volatile("cp.async.commit_group;"); }
__device__ __forceinline__ void cp_wait()   { asm volatile("cp.async.wait_group 0;"); }

// ---------------------------------------------------------------------------
// Pre-split GEMM (3xTF32): C[m,n] = sum_k A[m,k]*W[n,k] (+bias)
// All operands pre-split (hi/lo). Dense tiles: M%128==0, N%128==0 (grid), K%16==0.
// BM=128,BN=128,BK=16, 256 threads, cp.async double-buffered.
// PERMBIAS: bias index n -> (n&3)*HH + (n>>2).  SPLITOUT: write hi/lo C.
// dyn smem = 8*2560*4 = 81920 B
// ---------------------------------------------------------------------------
template<int PERMBIAS, int SPLITOUT>
__global__ void __launch_bounds__(256, 2)
gemm_ts(const float* __restrict__ AH, const float* __restrict__ AL, int lda,
        const float* __restrict__ WH, const float* __restrict__ WL, int ldw,
        float* __restrict__ C0, float* __restrict__ C1, int ldc,
        const float* __restrict__ b1, const float* __restrict__ b2,
        int Nstore, int K)
{
    extern __shared__ __align__(16) float sm[];
    float* sAH = sm;
    float* sAL = sm + 2 * 2560;
    float* sBH = sm + 4 * 2560;
    float* sBL = sm + 6 * 2560;

    const int tid  = threadIdx.x;
    const int lane = tid & 31;
    const int warp = tid >> 5;
    const int wm   = warp >> 2;
    const int wn   = warp & 3;
    const int row0 = blockIdx.y * 128;
    const int col0 = blockIdx.x * 128;

    float acc[4][4][4];
#pragma unroll
    for (int i = 0; i < 4; i++)
#pragma unroll
        for (int j = 0; j < 4; j++)
#pragma unroll
            for (int q = 0; q < 4; q++) acc[i][j][q] = 0.f;

    const uint32_t bAH = (uint32_t)__cvta_generic_to_shared(sAH);
    const uint32_t bAL = (uint32_t)__cvta_generic_to_shared(sAL);
    const uint32_t bBH = (uint32_t)__cvta_generic_to_shared(sBH);
    const uint32_t bBL = (uint32_t)__cvta_generic_to_shared(sBL);
    const int rld = tid >> 2;
    const int kq4 = (tid & 3) * 4;

    auto gload = [&](int buf, int k0) {
        const uint32_t bo = (uint32_t)(buf * 2560 * 4);
#pragma unroll
        for (int l = 0; l < 2; l++) {
            int r = rld + l * 64;
            uint32_t so = (uint32_t)((r * 20 + kq4) << 2);
            cp16(bAH + bo + so, &AH[(size_t)(row0 + r) * lda + k0 + kq4]);
            cp16(bAL + bo + so, &AL[(size_t)(row0 + r) * lda + k0 + kq4]);
            cp16(bBH + bo + so, &WH[(size_t)(col0 + r) * ldw + k0 + kq4]);
            cp16(bBL + bo + so, &WL[(size_t)(col0 + r) * ldw + k0 + kq4]);
        }
        cp_commit();
    };

    const int nk = K / 16;
    gload(0, 0);
    cp_wait();
    __syncthreads();

    for (int kt = 0; kt < nk; kt++) {
        const int cur = kt & 1;
        if (kt + 1 < nk) gload(cur ^ 1, (kt + 1) * 16);

        const float* AHc = sAH + cur * 2560;
        const float* ALc = sAL + cur * 2560;
        const float* BHc = sBH + cur * 2560;
        const float* BLc = sBL + cur * 2560;

#pragma unroll
        for (int k8 = 0; k8 < 2; k8++) {
            const int cc = k8 * 8 + (lane & 3);
            uint32_t aH[4][4], aL[4][4];
#pragma unroll
            for (int mt = 0; mt < 4; mt++) {
                int r = wm * 64 + mt * 16 + (lane >> 2);
                aH[mt][0] = fbits(AHc[r * 20 + cc]);
                aH[mt][1] = fbits(AHc[(r + 8) * 20 + cc]);
                aH[mt][2] = fbits(AHc[r * 20 + cc + 4]);
                aH[mt][3] = fbits(AHc[(r + 8) * 20 + cc + 4]);
                aL[mt][0] = fbits(ALc[r * 20 + cc]);
                aL[mt][1] = fbits(ALc[(r + 8) * 20 + cc]);
                aL[mt][2] = fbits(ALc[r * 20 + cc + 4]);
                aL[mt][3] = fbits(ALc[(r + 8) * 20 + cc + 4]);
            }
            uint32_t bH[4][2], bL[4][2];
#pragma unroll
            for (int nt = 0; nt < 4; nt++) {
                int n = wn * 32 + nt * 8 + (lane >> 2);
                bH[nt][0] = fbits(BHc[n * 20 + cc]);
                bH[nt][1] = fbits(BHc[n * 20 + cc + 4]);
                bL[nt][0] = fbits(BLc[n * 20 + cc]);
                bL[nt][1] = fbits(BLc[n * 20 + cc + 4]);
            }
#pragma unroll
            for (int mt = 0; mt < 4; mt++)
#pragma unroll
                for (int nt = 0; nt < 4; nt++) {
                    MMA_TF32(acc[mt][nt], aH[mt], bH[nt]);
                    MMA_TF32(acc[mt][nt], aH[mt], bL[nt]);
                    MMA_TF32(acc[mt][nt], aL[mt], bH[nt]);
                }
        }

        if (kt + 1 < nk) { cp_wait(); __syncthreads(); }
    }

    // epilogue (Nstore is even; n is always even -> pair-or-nothing)
#pragma unroll
    for (int mt = 0; mt < 4; mt++)
#pragma unroll
        for (int nt = 0; nt < 4; nt++) {
            int m = row0 + wm * 64 + mt * 16 + (lane >> 2);
            int n = col0 + wn * 32 + nt * 8 + 2 * (lane & 3);
            if (n + 1 >= Nstore) continue;
            float bv0 = 0.f, bv1 = 0.f;
            int bi0 = PERMBIAS ? ((n & 3) * HH + (n >> 2)) : n;
            int bi1 = PERMBIAS ? (((n + 1) & 3) * HH + ((n + 1) >> 2)) : (n + 1);
            if (b1) { bv0 += b1[bi0]; bv1 += b1[bi1]; }
            if (b2) { bv0 += b2[bi0]; bv1 += b2[bi1]; }
            float v00 = acc[mt][nt][0] + bv0, v01 = acc[mt][nt][1] + bv1;
            float v10 = acc[mt][nt][2] + bv0, v11 = acc[mt][nt][3] + bv1;
            if (SPLITOUT) {
                float h00, l00, h01, l01, h10, l10, h11, l11;
                split_tf32(v00, h00, l00); split_tf32(v01, h01, l01);
                split_tf32(v10, h10, l10); split_tf32(v11, h11, l11);
                *reinterpret_cast<float2*>(&C0[(size_t)m * ldc + n])       = make_float2(h00, h01);
                *reinterpret_cast<float2*>(&C0[(size_t)(m + 8) * ldc + n]) = make_float2(h10, h11);
                *reinterpret_cast<float2*>(&C1[(size_t)m * ldc + n])       = make_float2(l00, l01);
                *reinterpret_cast<float2*>(&C1[(size_t)(m + 8) * ldc + n]) = make_float2(l10, l11);
            } else {
                *reinterpret_cast<float2*>(&C0[(size_t)m * ldc + n])       = make_float2(v00, v01);
                *reinterpret_cast<float2*>(&C0[(size_t)(m + 8) * ldc + n]) = make_float2(v10, v11);
            }
        }
}

// ---------------------------------------------------------------------------
// Fused LSTM step, pre-split inputs, 256 threads (8 warps, warp tile 16x32).
// grid.x = 128 CTAs (32 permuted gate-cols each). dyn smem = 69632 B.
// ---------------------------------------------------------------------------
__global__ void __launch_bounds__(256)
lstm_step(const float* __restrict__ hH, const float* __restrict__ hL,
          const float* __restrict__ wH, const float* __restrict__ wL,  // pre-permuted [4096][1024]
          const float* __restrict__ gx,                                 // [128][4096] permuted
          float* __restrict__ c,
          float* __restrict__ houtH, float* __restrict__ houtL)
{
    extern __shared__ __align__(16) float sm[];
    float* sAH  = sm;                       // 2*2560
    float* sAL  = sm + 2 * 2560;
    float* sBH  = sm + 4 * 2560;            // 2*640
    float* sBL  = sm + 4 * 2560 + 2 * 640;
    float* gsum = sm + 4 * 2560 + 4 * 640;  // 128*36

    const int tid  = threadIdx.x;
    const int lane = tid & 31;
    const int warp = tid >> 5;              // 0..7 over M
    const int col0 = blockIdx.x * 32;

    float acc[4][4];
#pragma unroll
    for (int j = 0; j < 4; j++)
#pragma unroll
        for (int q = 0; q < 4; q++) acc[j][q] = 0.f;

    const uint32_t bAH = (uint32_t)__cvta_generic_to_shared(sAH);
    const uint32_t bAL = (uint32_t)__cvta_generic_to_shared(sAL);
    const uint32_t bBH = (uint32_t)__cvta_generic_to_shared(sBH);
    const uint32_t bBL = (uint32_t)__cvta_generic_to_shared(sBL);
    const int rld = tid >> 2;
    const int kq4 = (tid & 3) * 4;
    const int rB  = (tid & 127) >> 2;       // 0..31

    auto gload = [&](int buf, int k0) {
        const uint32_t boA = (uint32_t)(buf * 2560 * 4);
        const uint32_t boB = (uint32_t)(buf * 640 * 4);
#pragma unroll
        for (int l = 0; l < 2; l++) {
            int r = rld + l * 64;
            uint32_t so = (uint32_t)((r * 20 + kq4) << 2);
            cp16(bAH + boA + so, &hH[(size_t)r * HH + k0 + kq4]);
            cp16(bAL + boA + so, &hL[(size_t)r * HH + k0 + kq4]);
        }
        {
            uint32_t so = (uint32_t)((rB * 20 + kq4) << 2);
            const float* src = (tid < 128)
                ? &wH[(size_t)(col0 + rB) * HH + k0 + kq4]
                : &wL[(size_t)(col0 + rB) * HH + k0 + kq4];
            cp16(((tid < 128) ? bBH : bBL) + boB + so, src);
        }
        cp_commit();
    };

    const int nk = HH / 16;   // 64
    gload(0, 0);
    cp_wait();
    __syncthreads();

    for (int kt = 0; kt < nk; kt++) {
        const int cur = kt & 1;
        if (kt + 1 < nk) gload(cur ^ 1, (kt + 1) * 16);

        const float* AHc = sAH + cur * 2560;
        const float* ALc = sAL + cur * 2560;
        const float* BHc = sBH + cur * 640;
        const float* BLc = sBL + cur * 640;

#pragma unroll
        for (int k8 = 0; k8 < 2; k8++) {
            const int cc = k8 * 8 + (lane & 3);
            const int r  = warp * 16 + (lane >> 2);
            uint32_t aH[4], aL[4];
            aH[0] = fbits(AHc[r * 20 + cc]);
            aH[1] = fbits(AHc[(r + 8) * 20 + cc]);
            aH[2] = fbits(AHc[r * 20 + cc + 4]);
            aH[3] = fbits(AHc[(r + 8) * 20 + cc + 4]);
            aL[0] = fbits(ALc[r * 20 + cc]);
            aL[1] = fbits(ALc[(r + 8) * 20 + cc]);
            aL[2] = fbits(ALc[r * 20 + cc + 4]);
            aL[3] = fbits(ALc[(r + 8) * 20 + cc + 4]);
            uint32_t bH[4][2], bL[4][2];
#pragma unroll
            for (int nt = 0; nt < 4; nt++) {
                int n = nt * 8 + (lane >> 2);
                bH[nt][0] = fbits(BHc[n * 20 + cc]);
                bH[nt][1] = fbits(BHc[n * 20 + cc + 4]);
                bL[nt][0] = fbits(BLc[n * 20 + cc]);
                bL[nt][1] = fbits(BLc[n * 20 + cc + 4]);
            }
#pragma unroll
            for (int nt = 0; nt < 4; nt++) {
                MMA_TF32(acc[nt], aH, bH[nt]);
                MMA_TF32(acc[nt], aH, bL[nt]);
                MMA_TF32(acc[nt], aL, bH[nt]);
            }
        }

        if (kt + 1 < nk) { cp_wait(); __syncthreads(); }
    }

    // dump to smem
#pragma unroll
    for (int nt = 0; nt < 4; nt++) {
        int m = warp * 16 + (lane >> 2);
        int n = nt * 8 + 2 * (lane & 3);
        gsum[m * 36 + n]           = acc[nt][0];
        gsum[m * 36 + n + 1]       = acc[nt][1];
        gsum[(m + 8) * 36 + n]     = acc[nt][2];
        gsum[(m + 8) * 36 + n + 1] = acc[nt][3];
    }
    __syncthreads();

    // cell: 128 batches x 8 hidden units for this CTA
#pragma unroll
    for (int q = 0; q < 4; q++) {
        int idx = tid + q * 256;
        int b  = idx >> 3;
        int jj = idx & 7;
        float4 g  = *reinterpret_cast<float4*>(&gsum[b * 36 + jj * 4]);
        float4 gv = *reinterpret_cast<const float4*>(
            &gx[(size_t)b * (4 * HH) + col0 + jj * 4]);
        float gi = g.x + gv.x;
        float gf = g.y + gv.y;
        float gg = g.z + gv.z;
        float go = g.w + gv.w;
        float si = 1.f / (1.f + expf(-gi));
        float sf = 1.f / (1.f + expf(-gf));
        float so = 1.f / (1.f + expf(-go));
        float tg = tanhf(gg);
        int j = (col0 >> 2) + jj;
        float cn = sf * c[(size_t)b * HH + j] + si * tg;
        float hn = so * tanhf(cn);
        c[(size_t)b * HH + j] = cn;
        float hh, hl;
        split_tf32(hn, hh, hl);
        houtH[(size_t)b * HH + j] = hh;
        houtL[(size_t)b * HH + j] = hl;
    }
}

// ---------------------------------------------------------------------------
// Prep kernels
// ---------------------------------------------------------------------------
__global__ void split2_vec(const float* __restrict__ s,
                           float* __restrict__ H, float* __restrict__ L, int n4)
{
    int i = blockIdx.x * blockDim.x + threadIdx.x;
    if (i >= n4) return;
    float4 v = reinterpret_cast<const float4*>(s)[i];
    float4 h, l;
    split_tf32(v.x, h.x, l.x); split_tf32(v.y, h.y, l.y);
    split_tf32(v.z, h.z, l.z); split_tf32(v.w, h.w, l.w);
    reinterpret_cast<float4*>(H)[i] = h;
    reinterpret_cast<float4*>(L)[i] = l;
}

// dst row p <- src row (p&3)*HH + (p>>2);  rows = 4*HH
__global__ void split_perm_vec(const float* __restrict__ s,
                               float* __restrict__ H, float* __restrict__ L, int cols)
{
    int i = blockIdx.x * blockDim.x + threadIdx.x;
    int cols4 = cols >> 2;
    int tot = 4 * HH * cols4;
    if (i >= tot) return;
    int p  = i / cols4;
    int cq = i % cols4;
    int sr = (p & 3) * HH + (p >> 2);
    float4 v = *reinterpret_cast<const float4*>(&s[(size_t)sr * cols + cq * 4]);
    float4 h, l;
    split_tf32(v.x, h.x, l.x); split_tf32(v.y, h.y, l.y);
    split_tf32(v.z, h.z, l.z); split_tf32(v.w, h.w, l.w);
    *reinterpret_cast<float4*>(&H[(size_t)p * cols + cq * 4]) = h;
    *reinterpret_cast<float4*>(&L[(size_t)p * cols + cq * 4]) = l;
}

__global__ void hands_split(const float* __restrict__ lh, const float* __restrict__ rh,
                            float* __restrict__ H, float* __restrict__ L)
{
    int i = blockIdx.x * blockDim.x + threadIdx.x;
    if (i >= SS * BB * HPAD) return;
    int col = i % HPAD, row = i / HPAD;
    float v = 0.f;
    if (col < HANDD)          v = lh[row * HANDD + col];
    else if (col < 2 * HANDD) v = rh[row * HANDD + (col - HANDD)];
    float h, l; split_tf32(v, h, l);
    H[i] = h; L[i] = l;
}

__global__ void fchw_split(const float* __restrict__ w,
                           float* __restrict__ H, float* __restrict__ L)
{
    int i = blockIdx.x * blockDim.x + threadIdx.x;
    if (i >= HH * HPAD) return;
    int col = i % HPAD, row = i / HPAD;
    float v = (col < 2 * HANDD) ? w[row * 2 * HANDD + col] : 0.f;
    float h, l; split_tf32(v, h, l);
    H[i] = h; L[i] = l;
}

// cls_w (1000x1024) -> padded (1024x1024) split
__global__ void cls_split(const float* __restrict__ w,
                          float* __restrict__ H, float* __restrict__ L)
{
    int i = blockIdx.x * blockDim.x + threadIdx.x;
    if (i >= 1024 * (HH / 4)) return;
    int r = i / (HH / 4), cq = i % (HH / 4);
    float4 v = (r < CC)
        ? *reinterpret_cast<const float4*>(&w[(size_t)r * HH + cq * 4])
        : make_float4(0.f, 0.f, 0.f, 0.f);
    float4 h, l;
    split_tf32(v.x, h.x, l.x); split_tf32(v.y, h.y, l.y);
    split_tf32(v.z, h.z, l.z); split_tf32(v.w, h.w, l.w);
    *reinterpret_cast<float4*>(&H[(size_t)r * HH + cq * 4]) = h;
    *reinterpret_cast<float4*>(&L[(size_t)r * HH + cq * 4]) = l;
}

__global__ void zero_kernel(float* p, int n)
{
    int i = blockIdx.x * blockDim.x + threadIdx.x;
    if (i < n) p[i] = 0.f;
}

__global__ void row_stats(const float* __restrict__ out,
                          const int* __restrict__ act,
                          float* __restrict__ pred_f,
                          float* __restrict__ lossrow)
{
    const int b = blockIdx.x;
    const float* row = out + (size_t)b * CC;
    __shared__ float smax[128];
    __shared__ int   sidx[128];
    __shared__ float ssum[128];
    const int t = threadIdx.x;

    float best = -INFINITY;
    int bidx = 0;
    for (int j = t; j < CC; j += 128) {
        float v = row[j];
        if (v > best) { best = v; bidx = j; }
    }
    smax[t] = best; sidx[t] = bidx;
    __syncthreads();
    for (int s = 64; s > 0; s >>= 1) {
        if (t < s) {
            float v2 = smax[t + s]; int i2 = sidx[t + s];
            if (v2 > smax[t] || (v2 == smax[t] && i2 < sidx[t])) {
                smax[t] = v2; sidx[t] = i2;
            }
        }
        __syncthreads();
    }
    const float rowmax = smax[0];
    const int   rowarg = sidx[0];

    float lsum = 0.f;
    for (int j = t; j < CC; j += 128) lsum += expf(row[j] - rowmax);
    ssum[t] = lsum;
    __syncthreads();
    for (int s = 64; s > 0; s >>= 1) {
        if (t < s) ssum[t] += ssum[t + s];
        __syncthreads();
    }
    if (t == 0) {
        float logz = rowmax + logf(ssum[0]);
        lossrow[b] = logz - row[act[b]];
        if (pred_f) pred_f[b] = (float)rowarg;
    }
}

__global__ void mean_loss(const float* __restrict__ lossrow, float* loss_out)
{
    __shared__ float s[128];
    int t = threadIdx.x;
    s[t] = lossrow[t];
    __syncthreads();
    for (int st = 64; st > 0; st >>= 1) {
        if (t < st) s[t] += s[t + st];
        __syncthreads();
    }
    if (t == 0) *loss_out = s[0] / (float)BB;
}

// ---------------------------------------------------------------------------
// Launch
// ---------------------------------------------------------------------------
#define GSM 81920
#define LSM 69632

extern "C" void kernel_launch(void* const* d_in, const int* in_sizes, int n_in,
                              void* d_out, int out_size)
{
    const float* feats    = (const float*)d_in[0];
    const float* lh       = (const float*)d_in[1];
    const float* rh       = (const float*)d_in[2];
    const int*   act      = (const int*)  d_in[3];
    const float* fc1_w    = (const float*)d_in[4];
    const float* fc1_b    = (const float*)d_in[5];
    const float* fch_w    = (const float*)d_in[6];
    const float* fch_b    = (const float*)d_in[7];
    const float* roll_wih = (const float*)d_in[8];
    const float* roll_whh = (const float*)d_in[9];
    const float* roll_bih = (const float*)d_in[10];
    const float* roll_bhh = (const float*)d_in[11];
    const float* u_wih    = (const float*)d_in[12];
    const float* u_whh    = (const float*)d_in[13];
    const float* u_bih    = (const float*)d_in[14];
    const float* u_bhh    = (const float*)d_in[15];
    const float* cls_w    = (const float*)d_in[16];
    const float* cls_b    = (const float*)d_in[17];
    float* out = (float*)d_out;

    static int attr_done = 0;
    cudaFuncSetAttribute(gemm_ts<0, 1>, cudaFuncAttributeMaxDynamicSharedMemorySize, GSM);
    cudaFuncSetAttribute(gemm_ts<1, 0>, cudaFuncAttributeMaxDynamicSharedMemorySize, GSM);
    cudaFuncSetAttribute(gemm_ts<0, 0>, cudaFuncAttributeMaxDynamicSharedMemorySize, GSM);
    cudaFuncSetAttribute(lstm_step,     cudaFuncAttributeMaxDynamicSharedMemorySize, LSM);
    (void)attr_done;

    float* sc = nullptr;
    cudaGetSymbolAddress((void**)&sc, g_scratch);

    float* featsH = sc + OFF_FEATSH; float* featsL = sc + OFF_FEATSL;
    float* xH     = sc + OFF_XH;     float* xL     = sc + OFF_XL;
    float* gatesx = sc + OFF_GATESX;
    float* gatesxu= sc + OFF_GATESXU;
    float* cbuf   = sc + OFF_C;
    float* hHb[2] = { sc + OFF_H0H, sc + OFF_H1H };
    float* hLb[2] = { sc + OFF_H0L, sc + OFF_H1L };
    float* handsH = sc + OFF_HANDSH; float* handsL = sc + OFF_HANDSL;
    float* fc1H   = sc + OFF_FC1H;   float* fc1L   = sc + OFF_FC1L;
    float* fchwH  = sc + OFF_FCHWH;  float* fchwL  = sc + OFF_FCHWL;
    float* rwihH  = sc + OFF_RWIHH;  float* rwihL  = sc + OFF_RWIHL;
    float* rwhhH  = sc + OFF_RWHHH;  float* rwhhL  = sc + OFF_RWHHL;
    float* uwihH  = sc + OFF_UWIHH;  float* uwihL  = sc + OFF_UWIHL;
    float* uwhhH  = sc + OFF_UWHHH;  float* uwhhL  = sc + OFF_UWHHL;
    float* clsH   = sc + OFF_CLSH;   float* clsL   = sc + OFF_CLSL;
    float* lossrow= sc + OFF_LOSSROW;

    const int M_seq = SS * BB;   // 2048

    // ---- prep: split all operands (one pass each) ----
    split2_vec<<<(SS*BB*FEATD/4 + 255)/256, 256>>>(feats, featsH, featsL, SS*BB*FEATD/4);
    split2_vec<<<(HH*FEATD/4 + 255)/256, 256>>>(fc1_w, fc1H, fc1L, HH*FEATD/4);
    split_perm_vec<<<(4*HH*(2*HH/4) + 255)/256, 256>>>(roll_wih, rwihH, rwihL, 2*HH);
    split_perm_vec<<<(4*HH*(HH/4)   + 255)/256, 256>>>(roll_whh, rwhhH, rwhhL, HH);
    split_perm_vec<<<(4*HH*(2*HH/4) + 255)/256, 256>>>(u_wih, uwihH, uwihL, 2*HH);
    split_perm_vec<<<(4*HH*(HH/4)   + 255)/256, 256>>>(u_whh, uwhhH, uwhhL, HH);
    hands_split<<<(SS*BB*HPAD + 255)/256, 256>>>(lh, rh, handsH, handsL);
    fchw_split<<<(HH*HPAD + 255)/256, 256>>>(fch_w, fchwH, fchwL);
    cls_split<<<(1024*(HH/4) + 255)/256, 256>>>(cls_w, clsH, clsL);
    // zero c, h0H, h0L (contiguous)
    zero_kernel<<<(3*BB*HH + 255)/256, 256>>>(cbuf, 3*BB*HH);

    // ---- GEMMs ----
    // xproj -> x[:, 0:H] (split output)
    gemm_ts<0,1><<<dim3(8,16), 256, GSM>>>(featsH, featsL, FEATD,
                                           fc1H, fc1L, FEATD,
                                           xH, xL, 2*HH, fc1_b, nullptr,
                                           HH, FEATD);
    // hproj -> x[:, H:2H] (split output)
    gemm_ts<0,1><<<dim3(8,16), 256, GSM>>>(handsH, handsL, HPAD,
                                           fchwH, fchwL, HPAD,
                                           xH + HH, xL + HH, 2*HH, fch_b, nullptr,
                                           HH, HPAD);
    // gates_x = x @ P(roll_wih).T + P(biases)
    gemm_ts<1,0><<<dim3(32,16), 256, GSM>>>(xH, xL, 2*HH,
                                            rwihH, rwihL, 2*HH,
                                            gatesx, nullptr, 4*HH,
                                            roll_bih, roll_bhh,
                                            4*HH, 2*HH);
    // gates_xu = x[S-1] @ P(u_wih).T + P(u biases)
    gemm_ts<1,0><<<dim3(32,1), 256, GSM>>>(xH + (size_t)(SS-1)*BB*2*HH,
                                           xL + (size_t)(SS-1)*BB*2*HH, 2*HH,
                                           uwihH, uwihL, 2*HH,
                                           gatesxu, nullptr, 4*HH,
                                           u_bih, u_bhh,
                                           4*HH, 2*HH);

    // ---- recurrence ----
    int cur = 0;
    for (int t = 0; t < SS; t++) {
        lstm_step<<<128, 256, LSM>>>(hHb[cur], hLb[cur], rwhhH, rwhhL,
                                     gatesx + (size_t)t * BB * 4 * HH,
                                     cbuf, hHb[cur ^ 1], hLb[cur ^ 1]);
        cur ^= 1;
    }
    for (int t = 0; t < 2; t++) {
        lstm_step<<<128, 256, LSM>>>(hHb[cur], hLb[cur], uwhhH, uwhhL,
                                     gatesxu, cbuf, hHb[cur ^ 1], hLb[cur ^ 1]);
        cur ^= 1;
    }

    // ---- classifier ----
    gemm_ts<0,0><<<dim3(8,1), 256, GSM>>>(hHb[cur], hLb[cur], HH,
                                          clsH, clsL, HH,
                                          out, nullptr, CC, cls_b, nullptr,
                                          CC, HH);

    // ---- stats ----
    float* pred_f = (out_size >= BB * CC + BB)     ? out + BB * CC : nullptr;
    float* loss_p = (out_size >= BB * CC + BB + 1) ? out + BB * CC + BB : nullptr;
    row_stats<<<BB, 128>>>(out, act, pred_f, lossrow);
    if (loss_p) mean_loss<<<1, 128>>>(lossrow, loss_p);
}

// round 7
// speedup vs baseline: 3.3889x; 1.8233x over previous
#include <cuda_runtime.h>
#include <cuda_bf16.h>
#include <math.h>
#include <stdint.h>

#define SS    16
#define BB    128
#define FEATD 2048
#define HANDD 63
#define HH    1024
#define CC    1000
#define HPAD  128

// ---------------------------------------------------------------------------
// Scratch layout. bf16 arrays are carved out of the float scratch (count/2).
// ---------------------------------------------------------------------------
#define NB_FEATS (SS*BB*FEATD)
#define NB_X     (SS*BB*2*HH)
#define NB_HANDS (SS*BB*HPAD)
#define NB_FC1   (HH*FEATD)
#define NB_FCHW  (HH*HPAD)
#define NB_RWIH  (4*HH*2*HH)
#define NB_RWHH  (4*HH*HH)
#define NB_CLS   (1024*HH)
#define NB_H     (BB*HH)

#define OFF_FEATSH  0
#define OFF_FEATSM  (OFF_FEATSH + NB_FEATS/2)
#define OFF_XH      (OFF_FEATSM + NB_FEATS/2)
#define OFF_XM      (OFF_XH     + NB_X/2)
#define OFF_GATESX  (OFF_XM     + NB_X/2)
#define OFF_GATESXU (OFF_GATESX + SS*BB*4*HH)
#define OFF_C       (OFF_GATESXU+ BB*4*HH)
#define OFF_H0H     (OFF_C      + BB*HH)
#define OFF_H0M     (OFF_H0H    + NB_H/2)
#define OFF_H1H     (OFF_H0M    + NB_H/2)
#define OFF_H1M     (OFF_H1H    + NB_H/2)
#define OFF_HANDSH  (OFF_H1M    + NB_H/2)
#define OFF_HANDSM  (OFF_HANDSH + NB_HANDS/2)
#define OFF_FC1H    (OFF_HANDSM + NB_HANDS/2)
#define OFF_FC1M    (OFF_FC1H   + NB_FC1/2)
#define OFF_FCHWH   (OFF_FC1M   + NB_FC1/2)
#define OFF_FCHWM   (OFF_FCHWH  + NB_FCHW/2)
#define OFF_RWIHH   (OFF_FCHWM  + NB_FCHW/2)
#define OFF_RWIHM   (OFF_RWIHH  + NB_RWIH/2)
#define OFF_RWHHH   (OFF_RWIHM  + NB_RWIH/2)
#define OFF_RWHHM   (OFF_RWHHH  + NB_RWHH/2)
#define OFF_UWIHH   (OFF_RWHHM  + NB_RWHH/2)
#define OFF_UWIHM   (OFF_UWIHH  + NB_RWIH/2)
#define OFF_UWHHH   (OFF_UWIHM  + NB_RWIH/2)
#define OFF_UWHHM   (OFF_UWHHH  + NB_RWHH/2)
#define OFF_CLSH    (OFF_UWHHM  + NB_RWHH/2)
#define OFF_CLSM    (OFF_CLSH   + NB_CLS/2)
#define OFF_LOSSROW (OFF_CLSM   + NB_CLS/2)
#define SCRATCH_TOT (OFF_LOSSROW + BB)

__device__ __align__(16) float g_scratch[SCRATCH_TOT];

typedef __nv_bfloat16 bf16;

// ---------------------------------------------------------------------------
// helpers
// ---------------------------------------------------------------------------
__device__ __forceinline__ void split_bf(float v, bf16& h, bf16& m)
{
    h = __float2bfloat16_rn(v);
    m = __float2bfloat16_rn(v - __bfloat162float(h));
}

#define MMA_BF16(d, a, b)                                                     \
    asm volatile(                                                             \
        "mma.sync.aligned.m16n8k16.row.col.f32.bf16.bf16.f32 "                \
        "{%0,%1,%2,%3},{%4,%5,%6,%7},{%8,%9},{%0,%1,%2,%3};"                  \
        : "+f"(d[0]), "+f"(d[1]), "+f"(d[2]), "+f"(d[3])                      \
        : "r"(a[0]), "r"(a[1]), "r"(a[2]), "r"(a[3]), "r"(b[0]), "r"(b[1]))

__device__ __forceinline__ void ldsm4(uint32_t& r0, uint32_t& r1,
                                      uint32_t& r2, uint32_t& r3, uint32_t addr)
{
    asm volatile("ldmatrix.sync.aligned.m8n8.x4.shared.b16 {%0,%1,%2,%3}, [%4];"
                 : "=r"(r0), "=r"(r1), "=r"(r2), "=r"(r3) : "r"(addr));
}
__device__ __forceinline__ void ldsm2(uint32_t& r0, uint32_t& r1, uint32_t addr)
{
    asm volatile("ldmatrix.sync.aligned.m8n8.x2.shared.b16 {%0,%1}, [%2];"
                 : "=r"(r0), "=r"(r1) : "r"(addr));
}

__device__ __forceinline__ void cp16(uint32_t dst, const void* src)
{
    asm volatile("cp.async.cg.shared.global [%0], [%1], 16;" :: "r"(dst), "l"(src));
}
__device__ __forceinline__ void cp_commit() { asm volatile("cp.async.commit_group;"); }
__device__ __forceinline__ void cp_wait()   { asm volatile("cp.async.wait_group 0;"); }

// ---------------------------------------------------------------------------
// bf16x2-split GEMM (3 products): C = A*W^T (+bias)
// BM=128,BN=128,BK=32, 256 threads (8 warps 2x4, warp tile 64x32).
// A,W pre-split into (hi,mid) bf16. Rows padded to 40 bf16 (80B) in smem
// -> conflict-free ldmatrix. Double buffered cp.async. dyn smem 81920 B.
// PERMBIAS: bias index n -> (n&3)*HH + (n>>2).
// SPLITOUT: write split bf16 (CbH,CbM); else fp32 Cf.
// ---------------------------------------------------------------------------
template<int PERMBIAS, int SPLITOUT>
__global__ void __launch_bounds__(256, 2)
gemm_bf(const bf16* __restrict__ AH, const bf16* __restrict__ AM, int lda,
        const bf16* __restrict__ WH, const bf16* __restrict__ WM, int ldw,
        float* __restrict__ Cf, bf16* __restrict__ CbH, bf16* __restrict__ CbM,
        int ldc, const float* __restrict__ b1, const float* __restrict__ b2,
        int Nstore, int K)
{
    extern __shared__ __align__(16) char smraw[];
    const uint32_t sbase = (uint32_t)__cvta_generic_to_shared(smraw);

    const int tid  = threadIdx.x;
    const int lane = tid & 31;
    const int warp = tid >> 5;
    const int wm   = warp >> 2;          // 0..1
    const int wn   = warp & 3;           // 0..3
    const int row0 = blockIdx.y * 128;
    const int col0 = blockIdx.x * 128;

    float acc[4][4][4];
#pragma unroll
    for (int i = 0; i < 4; i++)
#pragma unroll
        for (int j = 0; j < 4; j++)
#pragma unroll
            for (int q = 0; q < 4; q++) acc[i][j][q] = 0.f;

    const int r  = tid >> 2;             // 0..63
    const int ch = tid & 3;              // 16B chunk within 64B row-tile

    auto gload = [&](int buf, int k0) {
        const uint32_t bo = (uint32_t)(buf * 40960);
#pragma unroll
        for (int l = 0; l < 2; l++) {
            int rr = r + l * 64;
            uint32_t so = (uint32_t)(rr * 80 + ch * 16);
            cp16(sbase + bo +         so, &AH[(size_t)(row0 + rr) * lda + k0 + ch * 8]);
            cp16(sbase + bo + 10240 + so, &AM[(size_t)(row0 + rr) * lda + k0 + ch * 8]);
            cp16(sbase + bo + 20480 + so, &WH[(size_t)(col0 + rr) * ldw + k0 + ch * 8]);
            cp16(sbase + bo + 30720 + so, &WM[(size_t)(col0 + rr) * ldw + k0 + ch * 8]);
        }
        cp_commit();
    };

    const int nk = K / 32;
    gload(0, 0);
    cp_wait();
    __syncthreads();

    for (int kt = 0; kt < nk; kt++) {
        const int cur = kt & 1;
        if (kt + 1 < nk) gload(cur ^ 1, (kt + 1) * 32);

        const uint32_t bo  = (uint32_t)(cur * 40960);
        const uint32_t aA0 = sbase + bo;
        const uint32_t aA1 = sbase + bo + 10240;
        const uint32_t aB0 = sbase + bo + 20480;
        const uint32_t aB1 = sbase + bo + 30720;

#pragma unroll
        for (int s = 0; s < 2; s++) {
            uint32_t b0f[4][2], b1f[4][2];
            const uint32_t bOff = (uint32_t)((lane & 7) * 80 + s * 32 + ((lane >> 3) & 1) * 16);
#pragma unroll
            for (int nt = 0; nt < 4; nt++) {
                uint32_t na = (uint32_t)((wn * 32 + nt * 8) * 80);
                ldsm2(b0f[nt][0], b0f[nt][1], aB0 + na + bOff);
                ldsm2(b1f[nt][0], b1f[nt][1], aB1 + na + bOff);
            }
            const uint32_t aOff = (uint32_t)((lane & 15) * 80 + s * 32 + (lane >> 4) * 16);
#pragma unroll
            for (int mt = 0; mt < 4; mt++) {
                uint32_t ma = (uint32_t)((wm * 64 + mt * 16) * 80);
                uint32_t a0[4], a1[4];
                ldsm4(a0[0], a0[1], a0[2], a0[3], aA0 + ma + aOff);
                ldsm4(a1[0], a1[1], a1[2], a1[3], aA1 + ma + aOff);
#pragma unroll
                for (int nt = 0; nt < 4; nt++) {
                    MMA_BF16(acc[mt][nt], a0, b0f[nt]);
                    MMA_BF16(acc[mt][nt], a0, b1f[nt]);
                    MMA_BF16(acc[mt][nt], a1, b0f[nt]);
                }
            }
        }

        if (kt + 1 < nk) { cp_wait(); __syncthreads(); }
    }

    // epilogue (n always even; Nstore even -> pair-or-nothing)
#pragma unroll
    for (int mt = 0; mt < 4; mt++)
#pragma unroll
        for (int nt = 0; nt < 4; nt++) {
            int m = row0 + wm * 64 + mt * 16 + (lane >> 2);
            int n = col0 + wn * 32 + nt * 8 + 2 * (lane & 3);
            if (n + 1 >= Nstore) continue;
            float bv0 = 0.f, bv1 = 0.f;
            int bi0 = PERMBIAS ? ((n & 3) * HH + (n >> 2)) : n;
            int bi1 = PERMBIAS ? (((n + 1) & 3) * HH + ((n + 1) >> 2)) : (n + 1);
            if (b1) { bv0 += b1[bi0]; bv1 += b1[bi1]; }
            if (b2) { bv0 += b2[bi0]; bv1 += b2[bi1]; }
            float v00 = acc[mt][nt][0] + bv0, v01 = acc[mt][nt][1] + bv1;
            float v10 = acc[mt][nt][2] + bv0, v11 = acc[mt][nt][3] + bv1;
            if (SPLITOUT) {
                __nv_bfloat162 h0, m0, h1, m1;
                split_bf(v00, h0.x, m0.x); split_bf(v01, h0.y, m0.y);
                split_bf(v10, h1.x, m1.x); split_bf(v11, h1.y, m1.y);
                *reinterpret_cast<__nv_bfloat162*>(&CbH[(size_t)m * ldc + n])       = h0;
                *reinterpret_cast<__nv_bfloat162*>(&CbM[(size_t)m * ldc + n])       = m0;
                *reinterpret_cast<__nv_bfloat162*>(&CbH[(size_t)(m + 8) * ldc + n]) = h1;
                *reinterpret_cast<__nv_bfloat162*>(&CbM[(size_t)(m + 8) * ldc + n]) = m1;
            } else {
                *reinterpret_cast<float2*>(&Cf[(size_t)m * ldc + n])       = make_float2(v00, v01);
                *reinterpret_cast<float2*>(&Cf[(size_t)(m + 8) * ldc + n]) = make_float2(v10, v11);
            }
        }
}

// ---------------------------------------------------------------------------
// Fused LSTM step (bf16x2-split GEMM + cell). grid 128 CTAs x 256 threads.
// Warp tile 16x32 (8 warps over 128 batches). BK=32. dyn smem 69632 B.
// ---------------------------------------------------------------------------
__global__ void __launch_bounds__(256)
lstm_step(const bf16* __restrict__ hH, const bf16* __restrict__ hM,
          const bf16* __restrict__ wH, const bf16* __restrict__ wM,  // pre-permuted [4096][1024]
          const float* __restrict__ gx,                               // [128][4096] permuted
          float* __restrict__ c,
          bf16* __restrict__ houtH, bf16* __restrict__ houtM)
{
    extern __shared__ __align__(16) char smraw[];
    const uint32_t sbase = (uint32_t)__cvta_generic_to_shared(smraw);
    float* gsum = reinterpret_cast<float*>(smraw + 51200);   // [128][36]

    const int tid  = threadIdx.x;
    const int lane = tid & 31;
    const int warp = tid >> 5;            // 0..7 over batches
    const int col0 = blockIdx.x * 32;

    float acc[4][4];
#pragma unroll
    for (int j = 0; j < 4; j++)
#pragma unroll
        for (int q = 0; q < 4; q++) acc[j][q] = 0.f;

    const int r   = tid >> 2;
    const int ch  = tid & 3;
    const int bm  = tid >> 7;             // 0/1 -> B0/B1
    const int rb  = (tid >> 2) & 31;

    auto gload = [&](int buf, int k0) {
        const uint32_t bo = (uint32_t)(buf * 25600);
#pragma unroll
        for (int l = 0; l < 2; l++) {
            int rr = r + l * 64;
            uint32_t so = (uint32_t)(rr * 80 + ch * 16);
            cp16(sbase + bo +         so, &hH[(size_t)rr * HH + k0 + ch * 8]);
            cp16(sbase + bo + 10240 + so, &hM[(size_t)rr * HH + k0 + ch * 8]);
        }
        {
            uint32_t so = (uint32_t)(rb * 80 + ch * 16);
            const bf16* src = bm ? &wM[(size_t)(col0 + rb) * HH + k0 + ch * 8]
                                 : &wH[(size_t)(col0 + rb) * HH + k0 + ch * 8];
            cp16(sbase + bo + (bm ? 23040u : 20480u) + so, src);
        }
        cp_commit();
    };

    const int nk = HH / 32;   // 32
    gload(0, 0);
    cp_wait();
    __syncthreads();

    for (int kt = 0; kt < nk; kt++) {
        const int cur = kt & 1;
        if (kt + 1 < nk) gload(cur ^ 1, (kt + 1) * 32);

        const uint32_t bo  = (uint32_t)(cur * 25600);
        const uint32_t aA0 = sbase + bo;
        const uint32_t aA1 = sbase + bo + 10240;
        const uint32_t aB0 = sbase + bo + 20480;
        const uint32_t aB1 = sbase + bo + 23040;

#pragma unroll
        for (int s = 0; s < 2; s++) {
            uint32_t b0f[4][2], b1f[4][2];
            const uint32_t bOff = (uint32_t)((lane & 7) * 80 + s * 32 + ((lane >> 3) & 1) * 16);
#pragma unroll
            for (int nt = 0; nt < 4; nt++) {
                uint32_t na = (uint32_t)((nt * 8) * 80);
                ldsm2(b0f[nt][0], b0f[nt][1], aB0 + na + bOff);
                ldsm2(b1f[nt][0], b1f[nt][1], aB1 + na + bOff);
            }
            const uint32_t aOff = (uint32_t)((warp * 16 + (lane & 15)) * 80
                                             + s * 32 + (lane >> 4) * 16);
            uint32_t a0[4], a1[4];
            ldsm4(a0[0], a0[1], a0[2], a0[3], aA0 + aOff);
            ldsm4(a1[0], a1[1], a1[2], a1[3], aA1 + aOff);
#pragma unroll
            for (int nt = 0; nt < 4; nt++) {
                MMA_BF16(acc[nt], a0, b0f[nt]);
                MMA_BF16(acc[nt], a0, b1f[nt]);
                MMA_BF16(acc[nt], a1, b0f[nt]);
            }
        }

        if (kt + 1 < nk) { cp_wait(); __syncthreads(); }
    }

    // dump accumulators to smem tile
#pragma unroll
    for (int nt = 0; nt < 4; nt++) {
        int m = warp * 16 + (lane >> 2);
        int n = nt * 8 + 2 * (lane & 3);
        gsum[m * 36 + n]           = acc[nt][0];
        gsum[m * 36 + n + 1]       = acc[nt][1];
        gsum[(m + 8) * 36 + n]     = acc[nt][2];
        gsum[(m + 8) * 36 + n + 1] = acc[nt][3];
    }
    __syncthreads();

    // cell: 128 batches x 8 hidden units for this CTA
#pragma unroll
    for (int q = 0; q < 4; q++) {
        int idx = tid + q * 256;
        int b  = idx >> 3;
        int jj = idx & 7;
        float4 g  = *reinterpret_cast<float4*>(&gsum[b * 36 + jj * 4]);
        float4 gv = *reinterpret_cast<const float4*>(
            &gx[(size_t)b * (4 * HH) + col0 + jj * 4]);
        float gi = g.x + gv.x;
        float gf = g.y + gv.y;
        float gg = g.z + gv.z;
        float go = g.w + gv.w;
        float si = 1.f / (1.f + expf(-gi));
        float sf = 1.f / (1.f + expf(-gf));
        float so = 1.f / (1.f + expf(-go));
        float tg = tanhf(gg);
        int j = (col0 >> 2) + jj;
        float cn = sf * c[(size_t)b * HH + j] + si * tg;
        float hn = so * tanhf(cn);
        c[(size_t)b * HH + j] = cn;
        bf16 hh, hm;
        split_bf(hn, hh, hm);
        houtH[(size_t)b * HH + j] = hh;
        houtM[(size_t)b * HH + j] = hm;
    }
}

// ---------------------------------------------------------------------------
// Prep kernels (fp32 -> split bf16)
// ---------------------------------------------------------------------------
__global__ void split2bf(const float* __restrict__ s,
                         bf16* __restrict__ H, bf16* __restrict__ M, int n4)
{
    int i = blockIdx.x * blockDim.x + threadIdx.x;
    if (i >= n4) return;
    float4 v = reinterpret_cast<const float4*>(s)[i];
    __nv_bfloat162 h0, h1, m0, m1;
    split_bf(v.x, h0.x, m0.x); split_bf(v.y, h0.y, m0.y);
    split_bf(v.z, h1.x, m1.x); split_bf(v.w, h1.y, m1.y);
    reinterpret_cast<__nv_bfloat162*>(H)[2 * i]     = h0;
    reinterpret_cast<__nv_bfloat162*>(H)[2 * i + 1] = h1;
    reinterpret_cast<__nv_bfloat162*>(M)[2 * i]     = m0;
    reinterpret_cast<__nv_bfloat162*>(M)[2 * i + 1] = m1;
}

// dst row p <- src row (p&3)*HH + (p>>2);  rows = 4*HH
__global__ void split_perm_bf(const float* __restrict__ s,
                              bf16* __restrict__ H, bf16* __restrict__ M, int cols)
{
    int i = blockIdx.x * blockDim.x + threadIdx.x;
    int cols4 = cols >> 2;
    int tot = 4 * HH * cols4;
    if (i >= tot) return;
    int p  = i / cols4;
    int cq = i % cols4;
    int sr = (p & 3) * HH + (p >> 2);
    float4 v = *reinterpret_cast<const float4*>(&s[(size_t)sr * cols + cq * 4]);
    __nv_bfloat162 h0, h1, m0, m1;
    split_bf(v.x, h0.x, m0.x); split_bf(v.y, h0.y, m0.y);
    split_bf(v.z, h1.x, m1.x); split_bf(v.w, h1.y, m1.y);
    size_t o = (size_t)p * cols + cq * 4;
    *reinterpret_cast<__nv_bfloat162*>(&H[o])     = h0;
    *reinterpret_cast<__nv_bfloat162*>(&H[o + 2]) = h1;
    *reinterpret_cast<__nv_bfloat162*>(&M[o])     = m0;
    *reinterpret_cast<__nv_bfloat162*>(&M[o + 2]) = m1;
}

__global__ void hands_split_bf(const float* __restrict__ lh, const float* __restrict__ rh,
                               bf16* __restrict__ H, bf16* __restrict__ M)
{
    int i = blockIdx.x * blockDim.x + threadIdx.x;
    if (i >= SS * BB * HPAD) return;
    int col = i % HPAD, row = i / HPAD;
    float v = 0.f;
    if (col < HANDD)          v = lh[row * HANDD + col];
    else if (col < 2 * HANDD) v = rh[row * HANDD + (col - HANDD)];
    bf16 h, m; split_bf(v, h, m);
    H[i] = h; M[i] = m;
}

__global__ void fchw_split_bf(const float* __restrict__ w,
                              bf16* __restrict__ H, bf16* __restrict__ M)
{
    int i = blockIdx.x * blockDim.x + threadIdx.x;
    if (i >= HH * HPAD) return;
    int col = i % HPAD, row = i / HPAD;
    float v = (col < 2 * HANDD) ? w[row * 2 * HANDD + col] : 0.f;
    bf16 h, m; split_bf(v, h, m);
    H[i] = h; M[i] = m;
}

// cls_w (1000x1024) -> padded (1024x1024) split
__global__ void cls_split_bf(const float* __restrict__ w,
                             bf16* __restrict__ H, bf16* __restrict__ M)
{
    int i = blockIdx.x * blockDim.x + threadIdx.x;
    if (i >= 1024 * (HH / 4)) return;
    int rr = i / (HH / 4), cq = i % (HH / 4);
    float4 v = (rr < CC)
        ? *reinterpret_cast<const float4*>(&w[(size_t)rr * HH + cq * 4])
        : make_float4(0.f, 0.f, 0.f, 0.f);
    __nv_bfloat162 h0, h1, m0, m1;
    split_bf(v.x, h0.x, m0.x); split_bf(v.y, h0.y, m0.y);
    split_bf(v.z, h1.x, m1.x); split_bf(v.w, h1.y, m1.y);
    size_t o = (size_t)rr * HH + cq * 4;
    *reinterpret_cast<__nv_bfloat162*>(&H[o])     = h0;
    *reinterpret_cast<__nv_bfloat162*>(&H[o + 2]) = h1;
    *reinterpret_cast<__nv_bfloat162*>(&M[o])     = m0;
    *reinterpret_cast<__nv_bfloat162*>(&M[o + 2]) = m1;
}

__global__ void zero_kernel(float* p, int n)
{
    int i = blockIdx.x * blockDim.x + threadIdx.x;
    if (i < n) p[i] = 0.f;
}

__global__ void row_stats(const float* __restrict__ out,
                          const int* __restrict__ act,
                          float* __restrict__ pred_f,
                          float* __restrict__ lossrow)
{
    const int b = blockIdx.x;
    const float* row = out + (size_t)b * CC;
    __shared__ float smax[128];
    __shared__ int   sidx[128];
    __shared__ float ssum[128];
    const int t = threadIdx.x;

    float best = -INFINITY;
    int bidx = 0;
    for (int j = t; j < CC; j += 128) {
        float v = row[j];
        if (v > best) { best = v; bidx = j; }
    }
    smax[t] = best; sidx[t] = bidx;
    __syncthreads();
    for (int s = 64; s > 0; s >>= 1) {
        if (t < s) {
            float v2 = smax[t + s]; int i2 = sidx[t + s];
            if (v2 > smax[t] || (v2 == smax[t] && i2 < sidx[t])) {
                smax[t] = v2; sidx[t] = i2;
            }
        }
        __syncthreads();
    }
    const float rowmax = smax[0];
    const int   rowarg = sidx[0];

    float lsum = 0.f;
    for (int j = t; j < CC; j += 128) lsum += expf(row[j] - rowmax);
    ssum[t] = lsum;
    __syncthreads();
    for (int s = 64; s > 0; s >>= 1) {
        if (t < s) ssum[t] += ssum[t + s];
        __syncthreads();
    }
    if (t == 0) {
        float logz = rowmax + logf(ssum[0]);
        lossrow[b] = logz - row[act[b]];
        if (pred_f) pred_f[b] = (float)rowarg;
    }
}

__global__ void mean_loss(const float* __restrict__ lossrow, float* loss_out)
{
    __shared__ float s[128];
    int t = threadIdx.x;
    s[t] = lossrow[t];
    __syncthreads();
    for (int st = 64; st > 0; st >>= 1) {
        if (t < st) s[t] += s[t + st];
        __syncthreads();
    }
    if (t == 0) *loss_out = s[0] / (float)BB;
}

// ---------------------------------------------------------------------------
// Launch
// ---------------------------------------------------------------------------
#define GSM 81920
#define LSM 69632

extern "C" void kernel_launch(void* const* d_in, const int* in_sizes, int n_in,
                              void* d_out, int out_size)
{
    const float* feats    = (const float*)d_in[0];
    const float* lh       = (const float*)d_in[1];
    const float* rh       = (const float*)d_in[2];
    const int*   act      = (const int*)  d_in[3];
    const float* fc1_w    = (const float*)d_in[4];
    const float* fc1_b    = (const float*)d_in[5];
    const float* fch_w    = (const float*)d_in[6];
    const float* fch_b    = (const float*)d_in[7];
    const float* roll_wih = (const float*)d_in[8];
    const float* roll_whh = (const float*)d_in[9];
    const float* roll_bih = (const float*)d_in[10];
    const float* roll_bhh = (const float*)d_in[11];
    const float* u_wih    = (const float*)d_in[12];
    const float* u_whh    = (const float*)d_in[13];
    const float* u_bih    = (const float*)d_in[14];
    const float* u_bhh    = (const float*)d_in[15];
    const float* cls_w    = (const float*)d_in[16];
    const float* cls_b    = (const float*)d_in[17];
    float* out = (float*)d_out;

    cudaFuncSetAttribute(gemm_bf<0, 1>, cudaFuncAttributeMaxDynamicSharedMemorySize, GSM);
    cudaFuncSetAttribute(gemm_bf<1, 0>, cudaFuncAttributeMaxDynamicSharedMemorySize, GSM);
    cudaFuncSetAttribute(gemm_bf<0, 0>, cudaFuncAttributeMaxDynamicSharedMemorySize, GSM);
    cudaFuncSetAttribute(lstm_step,     cudaFuncAttributeMaxDynamicSharedMemorySize, LSM);

    float* sc = nullptr;
    cudaGetSymbolAddress((void**)&sc, g_scratch);

    bf16* featsH = (bf16*)(sc + OFF_FEATSH); bf16* featsM = (bf16*)(sc + OFF_FEATSM);
    bf16* xH     = (bf16*)(sc + OFF_XH);     bf16* xM     = (bf16*)(sc + OFF_XM);
    float* gatesx  = sc + OFF_GATESX;
    float* gatesxu = sc + OFF_GATESXU;
    float* cbuf    = sc + OFF_C;
    bf16* hHb[2] = { (bf16*)(sc + OFF_H0H), (bf16*)(sc + OFF_H1H) };
    bf16* hMb[2] = { (bf16*)(sc + OFF_H0M), (bf16*)(sc + OFF_H1M) };
    bf16* handsH = (bf16*)(sc + OFF_HANDSH); bf16* handsM = (bf16*)(sc + OFF_HANDSM);
    bf16* fc1H   = (bf16*)(sc + OFF_FC1H);   bf16* fc1M   = (bf16*)(sc + OFF_FC1M);
    bf16* fchwH  = (bf16*)(sc + OFF_FCHWH);  bf16* fchwM  = (bf16*)(sc + OFF_FCHWM);
    bf16* rwihH  = (bf16*)(sc + OFF_RWIHH);  bf16* rwihM  = (bf16*)(sc + OFF_RWIHM);
    bf16* rwhhH  = (bf16*)(sc + OFF_RWHHH);  bf16* rwhhM  = (bf16*)(sc + OFF_RWHHM);
    bf16* uwihH  = (bf16*)(sc + OFF_UWIHH);  bf16* uwihM  = (bf16*)(sc + OFF_UWIHM);
    bf16* uwhhH  = (bf16*)(sc + OFF_UWHHH);  bf16* uwhhM  = (bf16*)(sc + OFF_UWHHM);
    bf16* clsH   = (bf16*)(sc + OFF_CLSH);   bf16* clsM   = (bf16*)(sc + OFF_CLSM);
    float* lossrow = sc + OFF_LOSSROW;

    // ---- prep: split all operands to (hi,mid) bf16 ----
    split2bf<<<(NB_FEATS/4 + 255)/256, 256>>>(feats, featsH, featsM, NB_FEATS/4);
    split2bf<<<(NB_FC1/4 + 255)/256, 256>>>(fc1_w, fc1H, fc1M, NB_FC1/4);
    split_perm_bf<<<(4*HH*(2*HH/4) + 255)/256, 256>>>(roll_wih, rwihH, rwihM, 2*HH);
    split_perm_bf<<<(4*HH*(HH/4)   + 255)/256, 256>>>(roll_whh, rwhhH, rwhhM, HH);
    split_perm_bf<<<(4*HH*(2*HH/4) + 255)/256, 256>>>(u_wih, uwihH, uwihM, 2*HH);
    split_perm_bf<<<(4*HH*(HH/4)   + 255)/256, 256>>>(u_whh, uwhhH, uwhhM, HH);
    hands_split_bf<<<(SS*BB*HPAD + 255)/256, 256>>>(lh, rh, handsH, handsM);
    fchw_split_bf<<<(HH*HPAD + 255)/256, 256>>>(fch_w, fchwH, fchwM);
    cls_split_bf<<<(1024*(HH/4) + 255)/256, 256>>>(cls_w, clsH, clsM);
    // zero c + h0 (hi,mid) — contiguous floats
    zero_kernel<<<(2*BB*HH + 255)/256, 256>>>(cbuf, 2*BB*HH);

    // ---- GEMMs ----
    // xproj -> x[:, 0:H] (split bf16 output)
    gemm_bf<0,1><<<dim3(8,16), 256, GSM>>>(featsH, featsM, FEATD,
                                           fc1H, fc1M, FEATD,
                                           nullptr, xH, xM, 2*HH,
                                           fc1_b, nullptr, HH, FEATD);
    // hproj -> x[:, H:2H]
    gemm_bf<0,1><<<dim3(8,16), 256, GSM>>>(handsH, handsM, HPAD,
                                           fchwH, fchwM, HPAD,
                                           nullptr, xH + HH, xM + HH, 2*HH,
                                           fch_b, nullptr, HH, HPAD);
    // gates_x = x @ P(roll_wih).T + P(biases)  (fp32 out)
    gemm_bf<1,0><<<dim3(32,16), 256, GSM>>>(xH, xM, 2*HH,
                                            rwihH, rwihM, 2*HH,
                                            gatesx, nullptr, nullptr, 4*HH,
                                            roll_bih, roll_bhh, 4*HH, 2*HH);
    // gates_xu = x[S-1] @ P(u_wih).T + P(u biases)
    gemm_bf<1,0><<<dim3(32,1), 256, GSM>>>(xH + (size_t)(SS-1)*BB*2*HH,
                                           xM + (size_t)(SS-1)*BB*2*HH, 2*HH,
                                           uwihH, uwihM, 2*HH,
                                           gatesxu, nullptr, nullptr, 4*HH,
                                           u_bih, u_bhh, 4*HH, 2*HH);

    // ---- recurrence ----
    int cur = 0;
    for (int t = 0; t < SS; t++) {
        lstm_step<<<128, 256, LSM>>>(hHb[cur], hMb[cur], rwhhH, rwhhM,
                                     gatesx + (size_t)t * BB * 4 * HH,
                                     cbuf, hHb[cur ^ 1], hMb[cur ^ 1]);
        cur ^= 1;
    }
    for (int t = 0; t < 2; t++) {
        lstm_step<<<128, 256, LSM>>>(hHb[cur], hMb[cur], uwhhH, uwhhM,
                                     gatesxu, cbuf, hHb[cur ^ 1], hMb[cur ^ 1]);
        cur ^= 1;
    }

    // ---- classifier ----
    gemm_bf<0,0><<<dim3(8,1), 256, GSM>>>(hHb[cur], hMb[cur], HH,
                                          clsH, clsM, HH,
                                          out, nullptr, nullptr, CC,
                                          cls_b, nullptr, CC, HH);

    // ---- stats ----
    float* pred_f = (out_size >= BB * CC + BB)     ? out + BB * CC : nullptr;
    float* loss_p = (out_size >= BB * CC + BB + 1) ? out + BB * CC + BB : nullptr;
    row_stats<<<BB, 128>>>(out, act, pred_f, lossrow);
    if (loss_p) mean_loss<<<1, 128>>>(lossrow, loss_p);
}

// round 9
// speedup vs baseline: 3.6495x; 1.0769x over previous
#include <cuda_runtime.h>
#include <cuda_bf16.h>
#include <math.h>
#include <stdint.h>

#define SS    16
#define BB    128
#define FEATD 2048
#define HANDD 63
#define HH    1024
#define CC    1000
#define HPAD  128

// ---------------------------------------------------------------------------
// Scratch layout. bf16 arrays are carved out of the float scratch (count/2).
// ---------------------------------------------------------------------------
#define NB_FEATS (SS*BB*FEATD)
#define NB_X     (SS*BB*2*HH)
#define NB_HANDS (SS*BB*HPAD)
#define NB_FC1   (HH*FEATD)
#define NB_FCHW  (HH*HPAD)
#define NB_RWIH  (4*HH*2*HH)
#define NB_RWHH  (4*HH*HH)
#define NB_CLS   (1024*HH)
#define NB_H     (BB*HH)

#define OFF_FEATSH  0
#define OFF_FEATSM  (OFF_FEATSH + NB_FEATS/2)
#define OFF_XH      (OFF_FEATSM + NB_FEATS/2)
#define OFF_XM      (OFF_XH     + NB_X/2)
#define OFF_GATESX  (OFF_XM     + NB_X/2)
#define OFF_GATESXU (OFF_GATESX + SS*BB*4*HH)
#define OFF_H0H     (OFF_GATESXU+ BB*4*HH)
#define OFF_H0M     (OFF_H0H    + NB_H/2)
#define OFF_H1H     (OFF_H0M    + NB_H/2)
#define OFF_H1M     (OFF_H1H    + NB_H/2)
#define OFF_HANDSH  (OFF_H1M    + NB_H/2)
#define OFF_HANDSM  (OFF_HANDSH + NB_HANDS/2)
#define OFF_FC1H    (OFF_HANDSM + NB_HANDS/2)
#define OFF_FC1M    (OFF_FC1H   + NB_FC1/2)
#define OFF_FCHWH   (OFF_FC1M   + NB_FC1/2)
#define OFF_FCHWM   (OFF_FCHWH  + NB_FCHW/2)
#define OFF_RWIHH   (OFF_FCHWM  + NB_FCHW/2)
#define OFF_RWIHM   (OFF_RWIHH  + NB_RWIH/2)
#define OFF_RWHHH   (OFF_RWIHM  + NB_RWIH/2)
#define OFF_RWHHM   (OFF_RWHHH  + NB_RWHH/2)
#define OFF_UWIHH   (OFF_RWHHM  + NB_RWHH/2)
#define OFF_UWIHM   (OFF_UWIHH  + NB_RWIH/2)
#define OFF_UWHHH   (OFF_UWIHM  + NB_RWIH/2)
#define OFF_UWHHM   (OFF_UWHHH  + NB_RWHH/2)
#define OFF_CLSH    (OFF_UWHHM  + NB_RWHH/2)
#define OFF_CLSM    (OFF_CLSH   + NB_CLS/2)
#define OFF_LOSSROW (OFF_CLSM   + NB_CLS/2)
#define SCRATCH_TOT (OFF_LOSSROW + BB)

__device__ __align__(16) float g_scratch[SCRATCH_TOT];

// grid-barrier state (phase-counting; snapshot at kernel entry -> replay-safe)
__device__ unsigned int g_bar_count = 0;
__device__ unsigned int g_bar_phase = 0;

typedef __nv_bfloat16 bf16;

// ---------------------------------------------------------------------------
// helpers
// ---------------------------------------------------------------------------
__device__ __forceinline__ void split_bf(float v, bf16& h, bf16& m)
{
    h = __float2bfloat16_rn(v);
    m = __float2bfloat16_rn(v - __bfloat162float(h));
}

#define MMA_BF16(d, a, b)                                                     \
    asm volatile(                                                             \
        "mma.sync.aligned.m16n8k16.row.col.f32.bf16.bf16.f32 "                \
        "{%0,%1,%2,%3},{%4,%5,%6,%7},{%8,%9},{%0,%1,%2,%3};"                  \
        : "+f"(d[0]), "+f"(d[1]), "+f"(d[2]), "+f"(d[3])                      \
        : "r"(a[0]), "r"(a[1]), "r"(a[2]), "r"(a[3]), "r"(b[0]), "r"(b[1]))

__device__ __forceinline__ void ldsm4(uint32_t& r0, uint32_t& r1,
                                      uint32_t& r2, uint32_t& r3, uint32_t addr)
{
    asm volatile("ldmatrix.sync.aligned.m8n8.x4.shared.b16 {%0,%1,%2,%3}, [%4];"
                 : "=r"(r0), "=r"(r1), "=r"(r2), "=r"(r3) : "r"(addr));
}
__device__ __forceinline__ void ldsm2(uint32_t& r0, uint32_t& r1, uint32_t addr)
{
    asm volatile("ldmatrix.sync.aligned.m8n8.x2.shared.b16 {%0,%1}, [%2];"
                 : "=r"(r0), "=r"(r1) : "r"(addr));
}

__device__ __forceinline__ void cp16(uint32_t dst, const void* src)
{
    asm volatile("cp.async.cg.shared.global [%0], [%1], 16;" :: "r"(dst), "l"(src));
}
__device__ __forceinline__ void cp_commit() { asm volatile("cp.async.commit_group;"); }
__device__ __forceinline__ void cp_wait()   { asm volatile("cp.async.wait_group 0;"); }

// ---------------------------------------------------------------------------
// bf16x2-split GEMM (3 products): C = A*W^T (+bias)  [proven in R7]
// ---------------------------------------------------------------------------
template<int PERMBIAS, int SPLITOUT>
__global__ void __launch_bounds__(256, 2)
gemm_bf(const bf16* __restrict__ AH, const bf16* __restrict__ AM, int lda,
        const bf16* __restrict__ WH, const bf16* __restrict__ WM, int ldw,
        float* __restrict__ Cf, bf16* __restrict__ CbH, bf16* __restrict__ CbM,
        int ldc, const float* __restrict__ b1, const float* __restrict__ b2,
        int Nstore, int K)
{
    extern __shared__ __align__(16) char smraw[];
    const uint32_t sbase = (uint32_t)__cvta_generic_to_shared(smraw);

    const int tid  = threadIdx.x;
    const int lane = tid & 31;
    const int warp = tid >> 5;
    const int wm   = warp >> 2;
    const int wn   = warp & 3;
    const int row0 = blockIdx.y * 128;
    const int col0 = blockIdx.x * 128;

    float acc[4][4][4];
#pragma unroll
    for (int i = 0; i < 4; i++)
#pragma unroll
        for (int j = 0; j < 4; j++)
#pragma unroll
            for (int q = 0; q < 4; q++) acc[i][j][q] = 0.f;

    const int r  = tid >> 2;
    const int ch = tid & 3;

    auto gload = [&](int buf, int k0) {
        const uint32_t bo = (uint32_t)(buf * 40960);
#pragma unroll
        for (int l = 0; l < 2; l++) {
            int rr = r + l * 64;
            uint32_t so = (uint32_t)(rr * 80 + ch * 16);
            cp16(sbase + bo +         so, &AH[(size_t)(row0 + rr) * lda + k0 + ch * 8]);
            cp16(sbase + bo + 10240 + so, &AM[(size_t)(row0 + rr) * lda + k0 + ch * 8]);
            cp16(sbase + bo + 20480 + so, &WH[(size_t)(col0 + rr) * ldw + k0 + ch * 8]);
            cp16(sbase + bo + 30720 + so, &WM[(size_t)(col0 + rr) * ldw + k0 + ch * 8]);
        }
        cp_commit();
    };

    const int nk = K / 32;
    gload(0, 0);
    cp_wait();
    __syncthreads();

    for (int kt = 0; kt < nk; kt++) {
        const int cur = kt & 1;
        if (kt + 1 < nk) gload(cur ^ 1, (kt + 1) * 32);

        const uint32_t bo  = (uint32_t)(cur * 40960);
        const uint32_t aA0 = sbase + bo;
        const uint32_t aA1 = sbase + bo + 10240;
        const uint32_t aB0 = sbase + bo + 20480;
        const uint32_t aB1 = sbase + bo + 30720;

#pragma unroll
        for (int s = 0; s < 2; s++) {
            uint32_t b0f[4][2], b1f[4][2];
            const uint32_t bOff = (uint32_t)((lane & 7) * 80 + s * 32 + ((lane >> 3) & 1) * 16);
#pragma unroll
            for (int nt = 0; nt < 4; nt++) {
                uint32_t na = (uint32_t)((wn * 32 + nt * 8) * 80);
                ldsm2(b0f[nt][0], b0f[nt][1], aB0 + na + bOff);
                ldsm2(b1f[nt][0], b1f[nt][1], aB1 + na + bOff);
            }
            const uint32_t aOff = (uint32_t)((lane & 15) * 80 + s * 32 + (lane >> 4) * 16);
#pragma unroll
            for (int mt = 0; mt < 4; mt++) {
                uint32_t ma = (uint32_t)((wm * 64 + mt * 16) * 80);
                uint32_t a0[4], a1[4];
                ldsm4(a0[0], a0[1], a0[2], a0[3], aA0 + ma + aOff);
                ldsm4(a1[0], a1[1], a1[2], a1[3], aA1 + ma + aOff);
#pragma unroll
                for (int nt = 0; nt < 4; nt++) {
                    MMA_BF16(acc[mt][nt], a0, b0f[nt]);
                    MMA_BF16(acc[mt][nt], a0, b1f[nt]);
                    MMA_BF16(acc[mt][nt], a1, b0f[nt]);
                }
            }
        }

        if (kt + 1 < nk) { cp_wait(); __syncthreads(); }
    }

#pragma unroll
    for (int mt = 0; mt < 4; mt++)
#pragma unroll
        for (int nt = 0; nt < 4; nt++) {
            int m = row0 + wm * 64 + mt * 16 + (lane >> 2);
            int n = col0 + wn * 32 + nt * 8 + 2 * (lane & 3);
            if (n + 1 >= Nstore) continue;
            float bv0 = 0.f, bv1 = 0.f;
            int bi0 = PERMBIAS ? ((n & 3) * HH + (n >> 2)) : n;
            int bi1 = PERMBIAS ? (((n + 1) & 3) * HH + ((n + 1) >> 2)) : (n + 1);
            if (b1) { bv0 += b1[bi0]; bv1 += b1[bi1]; }
            if (b2) { bv0 += b2[bi0]; bv1 += b2[bi1]; }
            float v00 = acc[mt][nt][0] + bv0, v01 = acc[mt][nt][1] + bv1;
            float v10 = acc[mt][nt][2] + bv0, v11 = acc[mt][nt][3] + bv1;
            if (SPLITOUT) {
                __nv_bfloat162 h0, m0, h1, m1;
                split_bf(v00, h0.x, m0.x); split_bf(v01, h0.y, m0.y);
                split_bf(v10, h1.x, m1.x); split_bf(v11, h1.y, m1.y);
                *reinterpret_cast<__nv_bfloat162*>(&CbH[(size_t)m * ldc + n])       = h0;
                *reinterpret_cast<__nv_bfloat162*>(&CbM[(size_t)m * ldc + n])       = m0;
                *reinterpret_cast<__nv_bfloat162*>(&CbH[(size_t)(m + 8) * ldc + n]) = h1;
                *reinterpret_cast<__nv_bfloat162*>(&CbM[(size_t)(m + 8) * ldc + n]) = m1;
            } else {
                *reinterpret_cast<float2*>(&Cf[(size_t)m * ldc + n])       = make_float2(v00, v01);
                *reinterpret_cast<float2*>(&Cf[(size_t)(m + 8) * ldc + n]) = make_float2(v10, v11);
            }
        }
}

// ---------------------------------------------------------------------------
// Persistent LSTM recurrence: all 18 steps in one kernel.
// 128 CTAs x 256 threads; each CTA owns 32 permuted gate-cols (8 hidden units).
// Resident weights: 32 rows x 1024 bf16 = 2048 B/row, padded stride 2064 B
// (129*16, odd multiple of 16 -> the 8 ldmatrix row addresses hit distinct
// 16-B bank groups). c resident in smem. h ping-pongs via global (bf16 split),
// grid barrier between steps. Step 0 skips the GEMM (h=0).
//
// smem layout (dyn, 195584 B):
//   0      : A tiles, 2 bufs x (H 10240 | M 10240)  = 40960
//   40960  : W_H  32 rows x 2064 B                  = 66048
//   107008 : W_M  32 rows x 2064 B                  = 66048
//   173056 : gsum 128 x 36 floats                   = 18432
//   191488 : c    128 x 8 floats                    = 4096
// ---------------------------------------------------------------------------
#define PSM  195584
#define SW_H 40960
#define SW_M 107008
#define SGS  173056
#define SCC  191488
#define WSTR 2064

__global__ void __launch_bounds__(256)
lstm_persistent(const bf16* __restrict__ rwhhH, const bf16* __restrict__ rwhhM,
                const bf16* __restrict__ uwhhH, const bf16* __restrict__ uwhhM,
                const float* __restrict__ gatesx,   // [16][128][4096] permuted
                const float* __restrict__ gatesxu,  // [128][4096] permuted
                bf16* __restrict__ h0H, bf16* __restrict__ h0M,
                bf16* __restrict__ h1H, bf16* __restrict__ h1M)
{
    extern __shared__ __align__(16) char smraw[];
    const uint32_t sbase = (uint32_t)__cvta_generic_to_shared(smraw);
    float* gsum = reinterpret_cast<float*>(smraw + SGS);
    float* c_sm = reinterpret_cast<float*>(smraw + SCC);

    const int tid  = threadIdx.x;
    const int lane = tid & 31;
    const int warp = tid >> 5;
    const int col0 = blockIdx.x * 32;

    // snapshot barrier phase BEFORE first arrival (replay-safe)
    __shared__ unsigned int s_phase;
    if (tid == 0) s_phase = g_bar_phase;

    // init resident c = 0
#pragma unroll
    for (int q = 0; q < 4; q++) c_sm[tid + q * 256] = 0.f;

    const int r  = tid >> 2;
    const int ch = tid & 3;

    // ---- load resident weights: 32 rows x 2048 B (hi & mid), stride 2064 ----
    auto load_weights = [&](const bf16* wH, const bf16* wM) {
        for (int i = tid; i < 4096; i += 256) {
            int row = i >> 7;          // 0..31
            int chk = i & 127;         // 16-B chunk, 0..127 -> 2048 B/row
            uint32_t so = (uint32_t)(row * WSTR + chk * 16);
            cp16(sbase + SW_H + so, &wH[(size_t)(col0 + row) * HH + chk * 8]);
            cp16(sbase + SW_M + so, &wM[(size_t)(col0 + row) * HH + chk * 8]);
        }
        cp_commit();
        cp_wait();
        __syncthreads();
    };
    load_weights(rwhhH, rwhhM);

    for (int step = 0; step < 18; step++) {
        const bf16* hH = (step & 1) ? h1H : h0H;
        const bf16* hM = (step & 1) ? h1M : h0M;
        bf16* oH = (step & 1) ? h0H : h1H;
        bf16* oM = (step & 1) ? h0M : h1M;
        const float* gx = (step < SS) ? gatesx + (size_t)step * BB * 4 * HH
                                      : gatesxu;

        if (step == SS) load_weights(uwhhH, uwhhM);   // switch to unroll weights

        float acc[4][4];
#pragma unroll
        for (int j = 0; j < 4; j++)
#pragma unroll
            for (int q = 0; q < 4; q++) acc[j][q] = 0.f;

        if (step > 0) {
            // ---- GEMM: gates_h[128 x 32] = h[128 x 1024] @ Wres^T ----
            auto gloadA = [&](int buf, int k0) {
                const uint32_t bo = (uint32_t)(buf * 20480);
#pragma unroll
                for (int l = 0; l < 2; l++) {
                    int rr = r + l * 64;
                    uint32_t so = (uint32_t)(rr * 80 + ch * 16);
                    cp16(sbase + bo +         so, &hH[(size_t)rr * HH + k0 + ch * 8]);
                    cp16(sbase + bo + 10240 + so, &hM[(size_t)rr * HH + k0 + ch * 8]);
                }
                cp_commit();
            };

            gloadA(0, 0);
            cp_wait();
            __syncthreads();

            for (int kt = 0; kt < 32; kt++) {
                const int cur = kt & 1;
                if (kt + 1 < 32) gloadA(cur ^ 1, (kt + 1) * 32);

                const uint32_t aA0 = sbase + (uint32_t)(cur * 20480);
                const uint32_t aA1 = aA0 + 10240;

#pragma unroll
                for (int s = 0; s < 2; s++) {
                    uint32_t b0f[4][2], b1f[4][2];
                    const uint32_t bOff = (uint32_t)((lane & 7) * WSTR + kt * 64
                                                     + s * 32 + ((lane >> 3) & 1) * 16);
#pragma unroll
                    for (int nt = 0; nt < 4; nt++) {
                        uint32_t na = (uint32_t)((nt * 8) * WSTR);
                        ldsm2(b0f[nt][0], b0f[nt][1], sbase + SW_H + na + bOff);
                        ldsm2(b1f[nt][0], b1f[nt][1], sbase + SW_M + na + bOff);
                    }
                    const uint32_t aOff = (uint32_t)((warp * 16 + (lane & 15)) * 80
                                                     + s * 32 + (lane >> 4) * 16);
                    uint32_t a0[4], a1[4];
                    ldsm4(a0[0], a0[1], a0[2], a0[3], aA0 + aOff);
                    ldsm4(a1[0], a1[1], a1[2], a1[3], aA1 + aOff);
#pragma unroll
                    for (int nt = 0; nt < 4; nt++) {
                        MMA_BF16(acc[nt], a0, b0f[nt]);
                        MMA_BF16(acc[nt], a0, b1f[nt]);
                        MMA_BF16(acc[nt], a1, b0f[nt]);
                    }
                }

                if (kt + 1 < 32) { cp_wait(); __syncthreads(); }
            }
            __syncthreads();
        }

        // dump accumulators
#pragma unroll
        for (int nt = 0; nt < 4; nt++) {
            int m = warp * 16 + (lane >> 2);
            int n = nt * 8 + 2 * (lane & 3);
            gsum[m * 36 + n]           = acc[nt][0];
            gsum[m * 36 + n + 1]       = acc[nt][1];
            gsum[(m + 8) * 36 + n]     = acc[nt][2];
            gsum[(m + 8) * 36 + n + 1] = acc[nt][3];
        }
        __syncthreads();

        // cell
#pragma unroll
        for (int q = 0; q < 4; q++) {
            int idx = tid + q * 256;
            int b  = idx >> 3;
            int jj = idx & 7;
            float4 g  = *reinterpret_cast<float4*>(&gsum[b * 36 + jj * 4]);
            float4 gv = *reinterpret_cast<const float4*>(
                &gx[(size_t)b * (4 * HH) + col0 + jj * 4]);
            float gi = g.x + gv.x;
            float gf = g.y + gv.y;
            float gg = g.z + gv.z;
            float go = g.w + gv.w;
            float si = 1.f / (1.f + expf(-gi));
            float sf = 1.f / (1.f + expf(-gf));
            float so = 1.f / (1.f + expf(-go));
            float tg = tanhf(gg);
            float cn = sf * c_sm[b * 8 + jj] + si * tg;
            float hn = so * tanhf(cn);
            c_sm[b * 8 + jj] = cn;
            int j = (col0 >> 2) + jj;
            bf16 hh, hm;
            split_bf(hn, hh, hm);
            oH[(size_t)b * HH + j] = hh;
            oM[(size_t)b * HH + j] = hm;
        }

        if (step < 17) {
            // grid barrier (all threads fence their h stores first)
            __threadfence();
            __syncthreads();
            if (tid == 0) {
                unsigned int expect = s_phase + (unsigned int)(step + 1);
                unsigned int ticket = atomicAdd(&g_bar_count, 1);
                if (ticket == gridDim.x - 1) {
                    g_bar_count = 0;
                    __threadfence();
                    atomicAdd(&g_bar_phase, 1);
                } else {
                    while (atomicAdd(&g_bar_phase, 0) < expect) { }
                }
            }
            __syncthreads();
        }
    }
}

// ---------------------------------------------------------------------------
// Prep kernels (fp32 -> split bf16)
// ---------------------------------------------------------------------------
__global__ void split2bf(const float* __restrict__ s,
                         bf16* __restrict__ H, bf16* __restrict__ M, int n4)
{
    int i = blockIdx.x * blockDim.x + threadIdx.x;
    if (i >= n4) return;
    float4 v = reinterpret_cast<const float4*>(s)[i];
    __nv_bfloat162 h0, h1, m0, m1;
    split_bf(v.x, h0.x, m0.x); split_bf(v.y, h0.y, m0.y);
    split_bf(v.z, h1.x, m1.x); split_bf(v.w, h1.y, m1.y);
    reinterpret_cast<__nv_bfloat162*>(H)[2 * i]     = h0;
    reinterpret_cast<__nv_bfloat162*>(H)[2 * i + 1] = h1;
    reinterpret_cast<__nv_bfloat162*>(M)[2 * i]     = m0;
    reinterpret_cast<__nv_bfloat162*>(M)[2 * i + 1] = m1;
}

// dst row p <- src row (p&3)*HH + (p>>2);  rows = 4*HH
__global__ void split_perm_bf(const float* __restrict__ s,
                              bf16* __restrict__ H, bf16* __restrict__ M, int cols)
{
    int i = blockIdx.x * blockDim.x + threadIdx.x;
    int cols4 = cols >> 2;
    int tot = 4 * HH * cols4;
    if (i >= tot) return;
    int p  = i / cols4;
    int cq = i % cols4;
    int sr = (p & 3) * HH + (p >> 2);
    float4 v = *reinterpret_cast<const float4*>(&s[(size_t)sr * cols + cq * 4]);
    __nv_bfloat162 h0, h1, m0, m1;
    split_bf(v.x, h0.x, m0.x); split_bf(v.y, h0.y, m0.y);
    split_bf(v.z, h1.x, m1.x); split_bf(v.w, h1.y, m1.y);
    size_t o = (size_t)p * cols + cq * 4;
    *reinterpret_cast<__nv_bfloat162*>(&H[o])     = h0;
    *reinterpret_cast<__nv_bfloat162*>(&H[o + 2]) = h1;
    *reinterpret_cast<__nv_bfloat162*>(&M[o])     = m0;
    *reinterpret_cast<__nv_bfloat162*>(&M[o + 2]) = m1;
}

__global__ void hands_split_bf(const float* __restrict__ lh, const float* __restrict__ rh,
                               bf16* __restrict__ H, bf16* __restrict__ M)
{
    int i = blockIdx.x * blockDim.x + threadIdx.x;
    if (i >= SS * BB * HPAD) return;
    int col = i % HPAD, row = i / HPAD;
    float v = 0.f;
    if (col < HANDD)          v = lh[row * HANDD + col];
    else if (col < 2 * HANDD) v = rh[row * HANDD + (col - HANDD)];
    bf16 h, m; split_bf(v, h, m);
    H[i] = h; M[i] = m;
}

__global__ void fchw_split_bf(const float* __restrict__ w,
                              bf16* __restrict__ H, bf16* __restrict__ M)
{
    int i = blockIdx.x * blockDim.x + threadIdx.x;
    if (i >= HH * HPAD) return;
    int col = i % HPAD, row = i / HPAD;
    float v = (col < 2 * HANDD) ? w[row * 2 * HANDD + col] : 0.f;
    bf16 h, m; split_bf(v, h, m);
    H[i] = h; M[i] = m;
}

// cls_w (1000x1024) -> padded (1024x1024) split
__global__ void cls_split_bf(const float* __restrict__ w,
                             bf16* __restrict__ H, bf16* __restrict__ M)
{
    int i = blockIdx.x * blockDim.x + threadIdx.x;
    if (i >= 1024 * (HH / 4)) return;
    int rr = i / (HH / 4), cq = i % (HH / 4);
    float4 v = (rr < CC)
        ? *reinterpret_cast<const float4*>(&w[(size_t)rr * HH + cq * 4])
        : make_float4(0.f, 0.f, 0.f, 0.f);
    __nv_bfloat162 h0, h1, m0, m1;
    split_bf(v.x, h0.x, m0.x); split_bf(v.y, h0.y, m0.y);
    split_bf(v.z, h1.x, m1.x); split_bf(v.w, h1.y, m1.y);
    size_t o = (size_t)rr * HH + cq * 4;
    *reinterpret_cast<__nv_bfloat162*>(&H[o])     = h0;
    *reinterpret_cast<__nv_bfloat162*>(&H[o + 2]) = h1;
    *reinterpret_cast<__nv_bfloat162*>(&M[o])     = m0;
    *reinterpret_cast<__nv_bfloat162*>(&M[o + 2]) = m1;
}

__global__ void row_stats(const float* __restrict__ out,
                          const int* __restrict__ act,
                          float* __restrict__ pred_f,
                          float* __restrict__ lossrow)
{
    const int b = blockIdx.x;
    const float* row = out + (size_t)b * CC;
    __shared__ float smax[128];
    __shared__ int   sidx[128];
    __shared__ float ssum[128];
    const int t = threadIdx.x;

    float best = -INFINITY;
    int bidx = 0;
    for (int j = t; j < CC; j += 128) {
        float v = row[j];
        if (v > best) { best = v; bidx = j; }
    }
    smax[t] = best; sidx[t] = bidx;
    __syncthreads();
    for (int s = 64; s > 0; s >>= 1) {
        if (t < s) {
            float v2 = smax[t + s]; int i2 = sidx[t + s];
            if (v2 > smax[t] || (v2 == smax[t] && i2 < sidx[t])) {
                smax[t] = v2; sidx[t] = i2;
            }
        }
        __syncthreads();
    }
    const float rowmax = smax[0];
    const int   rowarg = sidx[0];

    float lsum = 0.f;
    for (int j = t; j < CC; j += 128) lsum += expf(row[j] - rowmax);
    ssum[t] = lsum;
    __syncthreads();
    for (int s = 64; s > 0; s >>= 1) {
        if (t < s) ssum[t] += ssum[t + s];
        __syncthreads();
    }
    if (t == 0) {
        float logz = rowmax + logf(ssum[0]);
        lossrow[b] = logz - row[act[b]];
        if (pred_f) pred_f[b] = (float)rowarg;
    }
}

__global__ void mean_loss(const float* __restrict__ lossrow, float* loss_out)
{
    __shared__ float s[128];
    int t = threadIdx.x;
    s[t] = lossrow[t];
    __syncthreads();
    for (int st = 64; st > 0; st >>= 1) {
        if (t < st) s[t] += s[t + st];
        __syncthreads();
    }
    if (t == 0) *loss_out = s[0] / (float)BB;
}

// ---------------------------------------------------------------------------
// Launch
// ---------------------------------------------------------------------------
#define GSM 81920

extern "C" void kernel_launch(void* const* d_in, const int* in_sizes, int n_in,
                              void* d_out, int out_size)
{
    const float* feats    = (const float*)d_in[0];
    const float* lh       = (const float*)d_in[1];
    const float* rh       = (const float*)d_in[2];
    const int*   act      = (const int*)  d_in[3];
    const float* fc1_w    = (const float*)d_in[4];
    const float* fc1_b    = (const float*)d_in[5];
    const float* fch_w    = (const float*)d_in[6];
    const float* fch_b    = (const float*)d_in[7];
    const float* roll_wih = (const float*)d_in[8];
    const float* roll_whh = (const float*)d_in[9];
    const float* roll_bih = (const float*)d_in[10];
    const float* roll_bhh = (const float*)d_in[11];
    const float* u_wih    = (const float*)d_in[12];
    const float* u_whh    = (const float*)d_in[13];
    const float* u_bih    = (const float*)d_in[14];
    const float* u_bhh    = (const float*)d_in[15];
    const float* cls_w    = (const float*)d_in[16];
    const float* cls_b    = (const float*)d_in[17];
    float* out = (float*)d_out;

    cudaFuncSetAttribute(gemm_bf<0, 1>, cudaFuncAttributeMaxDynamicSharedMemorySize, GSM);
    cudaFuncSetAttribute(gemm_bf<1, 0>, cudaFuncAttributeMaxDynamicSharedMemorySize, GSM);
    cudaFuncSetAttribute(gemm_bf<0, 0>, cudaFuncAttributeMaxDynamicSharedMemorySize, GSM);
    cudaFuncSetAttribute(lstm_persistent, cudaFuncAttributeMaxDynamicSharedMemorySize, PSM);

    float* sc = nullptr;
    cudaGetSymbolAddress((void**)&sc, g_scratch);

    bf16* featsH = (bf16*)(sc + OFF_FEATSH); bf16* featsM = (bf16*)(sc + OFF_FEATSM);
    bf16* xH     = (bf16*)(sc + OFF_XH);     bf16* xM     = (bf16*)(sc + OFF_XM);
    float* gatesx  = sc + OFF_GATESX;
    float* gatesxu = sc + OFF_GATESXU;
    bf16* h0H = (bf16*)(sc + OFF_H0H); bf16* h0M = (bf16*)(sc + OFF_H0M);
    bf16* h1H = (bf16*)(sc + OFF_H1H); bf16* h1M = (bf16*)(sc + OFF_H1M);
    bf16* handsH = (bf16*)(sc + OFF_HANDSH); bf16* handsM = (bf16*)(sc + OFF_HANDSM);
    bf16* fc1H   = (bf16*)(sc + OFF_FC1H);   bf16* fc1M   = (bf16*)(sc + OFF_FC1M);
    bf16* fchwH  = (bf16*)(sc + OFF_FCHWH);  bf16* fchwM  = (bf16*)(sc + OFF_FCHWM);
    bf16* rwihH  = (bf16*)(sc + OFF_RWIHH);  bf16* rwihM  = (bf16*)(sc + OFF_RWIHM);
    bf16* rwhhH  = (bf16*)(sc + OFF_RWHHH);  bf16* rwhhM  = (bf16*)(sc + OFF_RWHHM);
    bf16* uwihH  = (bf16*)(sc + OFF_UWIHH);  bf16* uwihM  = (bf16*)(sc + OFF_UWIHM);
    bf16* uwhhH  = (bf16*)(sc + OFF_UWHHH);  bf16* uwhhM  = (bf16*)(sc + OFF_UWHHM);
    bf16* clsH   = (bf16*)(sc + OFF_CLSH);   bf16* clsM   = (bf16*)(sc + OFF_CLSM);
    float* lossrow = sc + OFF_LOSSROW;

    // ---- prep: split all operands to (hi,mid) bf16 ----
    split2bf<<<(NB_FEATS/4 + 255)/256, 256>>>(feats, featsH, featsM, NB_FEATS/4);
    split2bf<<<(NB_FC1/4 + 255)/256, 256>>>(fc1_w, fc1H, fc1M, NB_FC1/4);
    split_perm_bf<<<(4*HH*(2*HH/4) + 255)/256, 256>>>(roll_wih, rwihH, rwihM, 2*HH);
    split_perm_bf<<<(4*HH*(HH/4)   + 255)/256, 256>>>(roll_whh, rwhhH, rwhhM, HH);
    split_perm_bf<<<(4*HH*(2*HH/4) + 255)/256, 256>>>(u_wih, uwihH, uwihM, 2*HH);
    split_perm_bf<<<(4*HH*(HH/4)   + 255)/256, 256>>>(u_whh, uwhhH, uwhhM, HH);
    hands_split_bf<<<(SS*BB*HPAD + 255)/256, 256>>>(lh, rh, handsH, handsM);
    fchw_split_bf<<<(HH*HPAD + 255)/256, 256>>>(fch_w, fchwH, fchwM);
    cls_split_bf<<<(1024*(HH/4) + 255)/256, 256>>>(cls_w, clsH, clsM);

    // ---- GEMMs ----
    gemm_bf<0,1><<<dim3(8,16), 256, GSM>>>(featsH, featsM, FEATD,
                                           fc1H, fc1M, FEATD,
                                           nullptr, xH, xM, 2*HH,
                                           fc1_b, nullptr, HH, FEATD);
    gemm_bf<0,1><<<dim3(8,16), 256, GSM>>>(handsH, handsM, HPAD,
                                           fchwH, fchwM, HPAD,
                                           nullptr, xH + HH, xM + HH, 2*HH,
                                           fch_b, nullptr, HH, HPAD);
    gemm_bf<1,0><<<dim3(32,16), 256, GSM>>>(xH, xM, 2*HH,
                                            rwihH, rwihM, 2*HH,
                                            gatesx, nullptr, nullptr, 4*HH,
                                            roll_bih, roll_bhh, 4*HH, 2*HH);
    gemm_bf<1,0><<<dim3(32,1), 256, GSM>>>(xH + (size_t)(SS-1)*BB*2*HH,
                                           xM + (size_t)(SS-1)*BB*2*HH, 2*HH,
                                           uwihH, uwihM, 2*HH,
                                           gatesxu, nullptr, nullptr, 4*HH,
                                           u_bih, u_bhh, 4*HH, 2*HH);

    // ---- recurrence: one persistent kernel, 18 steps ----
    lstm_persistent<<<128, 256, PSM>>>(rwhhH, rwhhM, uwhhH, uwhhM,
                                       gatesx, gatesxu,
                                       h0H, h0M, h1H, h1M);

    // ---- classifier (final h lands in h0 after 18 steps) ----
    gemm_bf<0,0><<<dim3(8,1), 256, GSM>>>(h0H, h0M, HH,
                                          clsH, clsM, HH,
                                          out, nullptr, nullptr, CC,
                                          cls_b, nullptr, CC, HH);

    // ---- stats ----
    float* pred_f = (out_size >= BB * CC + BB)     ? out + BB * CC : nullptr;
    float* loss_p = (out_size >= BB * CC + BB + 1) ? out + BB * CC + BB : nullptr;
    row_stats<<<BB, 128>>>(out, act, pred_f, lossrow);
    if (loss_p) mean_loss<<<1, 128>>>(lossrow, loss_p);
}

// round 10
// speedup vs baseline: 3.8980x; 1.0681x over previous
#include <cuda_runtime.h>
#include <cuda_bf16.h>
#include <math.h>
#include <stdint.h>

#define SS    16
#define BB    128
#define FEATD 2048
#define HANDD 63
#define HH    1024
#define CC    1000
#define HPAD  128

// ---------------------------------------------------------------------------
// Scratch layout. bf16 arrays are carved out of the float scratch (count/2).
// ---------------------------------------------------------------------------
#define NB_FEATS (SS*BB*FEATD)
#define NB_X     (SS*BB*2*HH)
#define NB_HANDS (SS*BB*HPAD)
#define NB_FC1   (HH*FEATD)
#define NB_FCHW  (HH*HPAD)
#define NB_RWIH  (4*HH*2*HH)
#define NB_RWHH  (4*HH*HH)
#define NB_CLS   (1024*HH)
#define NB_H     (BB*HH)

#define OFF_FEATSH  0
#define OFF_FEATSM  (OFF_FEATSH + NB_FEATS/2)
#define OFF_XH      (OFF_FEATSM + NB_FEATS/2)
#define OFF_XM      (OFF_XH     + NB_X/2)
#define OFF_GATESX  (OFF_XM     + NB_X/2)
#define OFF_GATESXU (OFF_GATESX + SS*BB*4*HH)
#define OFF_H0H     (OFF_GATESXU+ BB*4*HH)
#define OFF_H0M     (OFF_H0H    + NB_H/2)
#define OFF_H1H     (OFF_H0M    + NB_H/2)
#define OFF_H1M     (OFF_H1H    + NB_H/2)
#define OFF_HANDSH  (OFF_H1M    + NB_H/2)
#define OFF_HANDSM  (OFF_HANDSH + NB_HANDS/2)
#define OFF_FC1H    (OFF_HANDSM + NB_HANDS/2)
#define OFF_FC1M    (OFF_FC1H   + NB_FC1/2)
#define OFF_FCHWH   (OFF_FC1M   + NB_FC1/2)
#define OFF_FCHWM   (OFF_FCHWH  + NB_FCHW/2)
#define OFF_RWIHH   (OFF_FCHWM  + NB_FCHW/2)
#define OFF_RWIHM   (OFF_RWIHH  + NB_RWIH/2)
#define OFF_RWHHH   (OFF_RWIHM  + NB_RWIH/2)
#define OFF_RWHHM   (OFF_RWHHH  + NB_RWHH/2)
#define OFF_UWIHH   (OFF_RWHHM  + NB_RWHH/2)
#define OFF_UWIHM   (OFF_UWIHH  + NB_RWIH/2)
#define OFF_UWHHH   (OFF_UWIHM  + NB_RWIH/2)
#define OFF_UWHHM   (OFF_UWHHH  + NB_RWHH/2)
#define OFF_CLSH    (OFF_UWHHM  + NB_RWHH/2)
#define OFF_CLSM    (OFF_CLSH   + NB_CLS/2)
#define OFF_LOSSROW (OFF_CLSM   + NB_CLS/2)
#define SCRATCH_TOT (OFF_LOSSROW + BB)

__device__ __align__(16) float g_scratch[SCRATCH_TOT];

// grid-barrier state (phase-counting; snapshot at kernel entry -> replay-safe)
__device__ unsigned int g_bar_count = 0;
__device__ unsigned int g_bar_phase = 0;

typedef __nv_bfloat16 bf16;

// ---------------------------------------------------------------------------
// helpers
// ---------------------------------------------------------------------------
__device__ __forceinline__ void split_bf(float v, bf16& h, bf16& m)
{
    h = __float2bfloat16_rn(v);
    m = __float2bfloat16_rn(v - __bfloat162float(h));
}

#define MMA_BF16(d, a, b)                                                     \
    asm volatile(                                                             \
        "mma.sync.aligned.m16n8k16.row.col.f32.bf16.bf16.f32 "                \
        "{%0,%1,%2,%3},{%4,%5,%6,%7},{%8,%9},{%0,%1,%2,%3};"                  \
        : "+f"(d[0]), "+f"(d[1]), "+f"(d[2]), "+f"(d[3])                      \
        : "r"(a[0]), "r"(a[1]), "r"(a[2]), "r"(a[3]), "r"(b[0]), "r"(b[1]))

__device__ __forceinline__ void ldsm4(uint32_t& r0, uint32_t& r1,
                                      uint32_t& r2, uint32_t& r3, uint32_t addr)
{
    asm volatile("ldmatrix.sync.aligned.m8n8.x4.shared.b16 {%0,%1,%2,%3}, [%4];"
                 : "=r"(r0), "=r"(r1), "=r"(r2), "=r"(r3) : "r"(addr));
}
__device__ __forceinline__ void ldsm2(uint32_t& r0, uint32_t& r1, uint32_t addr)
{
    asm volatile("ldmatrix.sync.aligned.m8n8.x2.shared.b16 {%0,%1}, [%2];"
                 : "=r"(r0), "=r"(r1) : "r"(addr));
}

__device__ __forceinline__ void cp16(uint32_t dst, const void* src)
{
    asm volatile("cp.async.cg.shared.global [%0], [%1], 16;" :: "r"(dst), "l"(src));
}
__device__ __forceinline__ void cp_commit() { asm volatile("cp.async.commit_group;"); }
__device__ __forceinline__ void cp_wait()   { asm volatile("cp.async.wait_group 0;"); }

// ---------------------------------------------------------------------------
// bf16x2-split GEMM (3 products): C = A*W^T (+bias)  [proven]
// ---------------------------------------------------------------------------
template<int PERMBIAS, int SPLITOUT>
__global__ void __launch_bounds__(256, 2)
gemm_bf(const bf16* __restrict__ AH, const bf16* __restrict__ AM, int lda,
        const bf16* __restrict__ WH, const bf16* __restrict__ WM, int ldw,
        float* __restrict__ Cf, bf16* __restrict__ CbH, bf16* __restrict__ CbM,
        int ldc, const float* __restrict__ b1, const float* __restrict__ b2,
        int Nstore, int K)
{
    extern __shared__ __align__(16) char smraw[];
    const uint32_t sbase = (uint32_t)__cvta_generic_to_shared(smraw);

    const int tid  = threadIdx.x;
    const int lane = tid & 31;
    const int warp = tid >> 5;
    const int wm   = warp >> 2;
    const int wn   = warp & 3;
    const int row0 = blockIdx.y * 128;
    const int col0 = blockIdx.x * 128;

    float acc[4][4][4];
#pragma unroll
    for (int i = 0; i < 4; i++)
#pragma unroll
        for (int j = 0; j < 4; j++)
#pragma unroll
            for (int q = 0; q < 4; q++) acc[i][j][q] = 0.f;

    const int r  = tid >> 2;
    const int ch = tid & 3;

    auto gload = [&](int buf, int k0) {
        const uint32_t bo = (uint32_t)(buf * 40960);
#pragma unroll
        for (int l = 0; l < 2; l++) {
            int rr = r + l * 64;
            uint32_t so = (uint32_t)(rr * 80 + ch * 16);
            cp16(sbase + bo +         so, &AH[(size_t)(row0 + rr) * lda + k0 + ch * 8]);
            cp16(sbase + bo + 10240 + so, &AM[(size_t)(row0 + rr) * lda + k0 + ch * 8]);
            cp16(sbase + bo + 20480 + so, &WH[(size_t)(col0 + rr) * ldw + k0 + ch * 8]);
            cp16(sbase + bo + 30720 + so, &WM[(size_t)(col0 + rr) * ldw + k0 + ch * 8]);
        }
        cp_commit();
    };

    const int nk = K / 32;
    gload(0, 0);
    cp_wait();
    __syncthreads();

    for (int kt = 0; kt < nk; kt++) {
        const int cur = kt & 1;
        if (kt + 1 < nk) gload(cur ^ 1, (kt + 1) * 32);

        const uint32_t bo  = (uint32_t)(cur * 40960);
        const uint32_t aA0 = sbase + bo;
        const uint32_t aA1 = sbase + bo + 10240;
        const uint32_t aB0 = sbase + bo + 20480;
        const uint32_t aB1 = sbase + bo + 30720;

#pragma unroll
        for (int s = 0; s < 2; s++) {
            uint32_t b0f[4][2], b1f[4][2];
            const uint32_t bOff = (uint32_t)((lane & 7) * 80 + s * 32 + ((lane >> 3) & 1) * 16);
#pragma unroll
            for (int nt = 0; nt < 4; nt++) {
                uint32_t na = (uint32_t)((wn * 32 + nt * 8) * 80);
                ldsm2(b0f[nt][0], b0f[nt][1], aB0 + na + bOff);
                ldsm2(b1f[nt][0], b1f[nt][1], aB1 + na + bOff);
            }
            const uint32_t aOff = (uint32_t)((lane & 15) * 80 + s * 32 + (lane >> 4) * 16);
#pragma unroll
            for (int mt = 0; mt < 4; mt++) {
                uint32_t ma = (uint32_t)((wm * 64 + mt * 16) * 80);
                uint32_t a0[4], a1[4];
                ldsm4(a0[0], a0[1], a0[2], a0[3], aA0 + ma + aOff);
                ldsm4(a1[0], a1[1], a1[2], a1[3], aA1 + ma + aOff);
#pragma unroll
                for (int nt = 0; nt < 4; nt++) {
                    MMA_BF16(acc[mt][nt], a0, b0f[nt]);
                    MMA_BF16(acc[mt][nt], a0, b1f[nt]);
                    MMA_BF16(acc[mt][nt], a1, b0f[nt]);
                }
            }
        }

        if (kt + 1 < nk) { cp_wait(); __syncthreads(); }
    }

#pragma unroll
    for (int mt = 0; mt < 4; mt++)
#pragma unroll
        for (int nt = 0; nt < 4; nt++) {
            int m = row0 + wm * 64 + mt * 16 + (lane >> 2);
            int n = col0 + wn * 32 + nt * 8 + 2 * (lane & 3);
            if (n + 1 >= Nstore) continue;
            float bv0 = 0.f, bv1 = 0.f;
            int bi0 = PERMBIAS ? ((n & 3) * HH + (n >> 2)) : n;
            int bi1 = PERMBIAS ? (((n + 1) & 3) * HH + ((n + 1) >> 2)) : (n + 1);
            if (b1) { bv0 += b1[bi0]; bv1 += b1[bi1]; }
            if (b2) { bv0 += b2[bi0]; bv1 += b2[bi1]; }
            float v00 = acc[mt][nt][0] + bv0, v01 = acc[mt][nt][1] + bv1;
            float v10 = acc[mt][nt][2] + bv0, v11 = acc[mt][nt][3] + bv1;
            if (SPLITOUT) {
                __nv_bfloat162 h0, m0, h1, m1;
                split_bf(v00, h0.x, m0.x); split_bf(v01, h0.y, m0.y);
                split_bf(v10, h1.x, m1.x); split_bf(v11, h1.y, m1.y);
                *reinterpret_cast<__nv_bfloat162*>(&CbH[(size_t)m * ldc + n])       = h0;
                *reinterpret_cast<__nv_bfloat162*>(&CbM[(size_t)m * ldc + n])       = m0;
                *reinterpret_cast<__nv_bfloat162*>(&CbH[(size_t)(m + 8) * ldc + n]) = h1;
                *reinterpret_cast<__nv_bfloat162*>(&CbM[(size_t)(m + 8) * ldc + n]) = m1;
            } else {
                *reinterpret_cast<float2*>(&Cf[(size_t)m * ldc + n])       = make_float2(v00, v01);
                *reinterpret_cast<float2*>(&Cf[(size_t)(m + 8) * ldc + n]) = make_float2(v10, v11);
            }
        }
}

// ---------------------------------------------------------------------------
// Persistent LSTM recurrence: all 18 steps in one kernel.
// Same as R9 plus: (a) gx slice staged into smem via cp.async at step start
// (hides DRAM latency under the GEMM), (b) volatile-load barrier poll.
//
// smem layout (dyn, 211968 B):
//   0      : A tiles, 2 bufs x (H 10240 | M 10240)  = 40960
//   40960  : W_H  32 rows x 2064 B                  = 66048
//   107008 : W_M  32 rows x 2064 B                  = 66048
//   173056 : gsum 128 x 36 floats                   = 18432
//   191488 : c    128 x 8 floats                    = 4096
//   195584 : gx stage 128 rows x 128 B              = 16384
// ---------------------------------------------------------------------------
#define PSM  211968
#define SW_H 40960
#define SW_M 107008
#define SGS  173056
#define SCC  191488
#define SGX  195584
#define WSTR 2064

__global__ void __launch_bounds__(256)
lstm_persistent(const bf16* __restrict__ rwhhH, const bf16* __restrict__ rwhhM,
                const bf16* __restrict__ uwhhH, const bf16* __restrict__ uwhhM,
                const float* __restrict__ gatesx,   // [16][128][4096] permuted
                const float* __restrict__ gatesxu,  // [128][4096] permuted
                bf16* __restrict__ h0H, bf16* __restrict__ h0M,
                bf16* __restrict__ h1H, bf16* __restrict__ h1M)
{
    extern __shared__ __align__(16) char smraw[];
    const uint32_t sbase = (uint32_t)__cvta_generic_to_shared(smraw);
    float* gsum = reinterpret_cast<float*>(smraw + SGS);
    float* c_sm = reinterpret_cast<float*>(smraw + SCC);

    const int tid  = threadIdx.x;
    const int lane = tid & 31;
    const int warp = tid >> 5;
    const int col0 = blockIdx.x * 32;

    // snapshot barrier phase BEFORE first arrival (replay-safe)
    __shared__ unsigned int s_phase;
    if (tid == 0) s_phase = g_bar_phase;

    // init resident c = 0
#pragma unroll
    for (int q = 0; q < 4; q++) c_sm[tid + q * 256] = 0.f;

    const int r  = tid >> 2;
    const int ch = tid & 3;

    // ---- load resident weights: 32 rows x 2048 B (hi & mid), stride 2064 ----
    auto load_weights = [&](const bf16* wH, const bf16* wM) {
        for (int i = tid; i < 4096; i += 256) {
            int row = i >> 7;          // 0..31
            int chk = i & 127;         // 16-B chunk, 0..127 -> 2048 B/row
            uint32_t so = (uint32_t)(row * WSTR + chk * 16);
            cp16(sbase + SW_H + so, &wH[(size_t)(col0 + row) * HH + chk * 8]);
            cp16(sbase + SW_M + so, &wM[(size_t)(col0 + row) * HH + chk * 8]);
        }
        cp_commit();
        cp_wait();
        __syncthreads();
    };
    load_weights(rwhhH, rwhhM);

    for (int step = 0; step < 18; step++) {
        const bf16* hH = (step & 1) ? h1H : h0H;
        const bf16* hM = (step & 1) ? h1M : h0M;
        bf16* oH = (step & 1) ? h0H : h1H;
        bf16* oM = (step & 1) ? h0M : h1M;
        const float* gx = (step < SS) ? gatesx + (size_t)step * BB * 4 * HH
                                      : gatesxu;

        if (step == SS) load_weights(uwhhH, uwhhM);   // switch to unroll weights

        // stage this step's gx slice (128 rows x 128 B) into smem early
        {
#pragma unroll
            for (int l = 0; l < 4; l++) {
                int idx = tid + l * 256;      // 0..1023
                int b   = idx >> 3;
                int chk = idx & 7;
                cp16(sbase + SGX + (uint32_t)(b * 128 + chk * 16),
                     &gx[(size_t)b * (4 * HH) + col0 + chk * 4]);
            }
            cp_commit();
        }

        float acc[4][4];
#pragma unroll
        for (int j = 0; j < 4; j++)
#pragma unroll
            for (int q = 0; q < 4; q++) acc[j][q] = 0.f;

        if (step > 0) {
            // ---- GEMM: gates_h[128 x 32] = h[128 x 1024] @ Wres^T ----
            auto gloadA = [&](int buf, int k0) {
                const uint32_t bo = (uint32_t)(buf * 20480);
#pragma unroll
                for (int l = 0; l < 2; l++) {
                    int rr = r + l * 64;
                    uint32_t so = (uint32_t)(rr * 80 + ch * 16);
                    cp16(sbase + bo +         so, &hH[(size_t)rr * HH + k0 + ch * 8]);
                    cp16(sbase + bo + 10240 + so, &hM[(size_t)rr * HH + k0 + ch * 8]);
                }
                cp_commit();
            };

            gloadA(0, 0);
            cp_wait();
            __syncthreads();

            for (int kt = 0; kt < 32; kt++) {
                const int cur = kt & 1;
                if (kt + 1 < 32) gloadA(cur ^ 1, (kt + 1) * 32);

                const uint32_t aA0 = sbase + (uint32_t)(cur * 20480);
                const uint32_t aA1 = aA0 + 10240;

#pragma unroll
                for (int s = 0; s < 2; s++) {
                    uint32_t b0f[4][2], b1f[4][2];
                    const uint32_t bOff = (uint32_t)((lane & 7) * WSTR + kt * 64
                                                     + s * 32 + ((lane >> 3) & 1) * 16);
#pragma unroll
                    for (int nt = 0; nt < 4; nt++) {
                        uint32_t na = (uint32_t)((nt * 8) * WSTR);
                        ldsm2(b0f[nt][0], b0f[nt][1], sbase + SW_H + na + bOff);
                        ldsm2(b1f[nt][0], b1f[nt][1], sbase + SW_M + na + bOff);
                    }
                    const uint32_t aOff = (uint32_t)((warp * 16 + (lane & 15)) * 80
                                                     + s * 32 + (lane >> 4) * 16);
                    uint32_t a0[4], a1[4];
                    ldsm4(a0[0], a0[1], a0[2], a0[3], aA0 + aOff);
                    ldsm4(a1[0], a1[1], a1[2], a1[3], aA1 + aOff);
#pragma unroll
                    for (int nt = 0; nt < 4; nt++) {
                        MMA_BF16(acc[nt], a0, b0f[nt]);
                        MMA_BF16(acc[nt], a0, b1f[nt]);
                        MMA_BF16(acc[nt], a1, b0f[nt]);
                    }
                }

                if (kt + 1 < 32) { cp_wait(); __syncthreads(); }
            }
        }

        // dump accumulators
#pragma unroll
        for (int nt = 0; nt < 4; nt++) {
            int m = warp * 16 + (lane >> 2);
            int n = nt * 8 + 2 * (lane & 3);
            gsum[m * 36 + n]           = acc[nt][0];
            gsum[m * 36 + n + 1]       = acc[nt][1];
            gsum[(m + 8) * 36 + n]     = acc[nt][2];
            gsum[(m + 8) * 36 + n + 1] = acc[nt][3];
        }
        cp_wait();            // gx stage complete (no-op if already drained)
        __syncthreads();

        // cell (gx read from smem stage)
#pragma unroll
        for (int q = 0; q < 4; q++) {
            int idx = tid + q * 256;
            int b  = idx >> 3;
            int jj = idx & 7;
            float4 g  = *reinterpret_cast<float4*>(&gsum[b * 36 + jj * 4]);
            float4 gv = *reinterpret_cast<float4*>(smraw + SGX + b * 128 + jj * 16);
            float gi = g.x + gv.x;
            float gf = g.y + gv.y;
            float gg = g.z + gv.z;
            float go = g.w + gv.w;
            float si = 1.f / (1.f + expf(-gi));
            float sf = 1.f / (1.f + expf(-gf));
            float so = 1.f / (1.f + expf(-go));
            float tg = tanhf(gg);
            float cn = sf * c_sm[b * 8 + jj] + si * tg;
            float hn = so * tanhf(cn);
            c_sm[b * 8 + jj] = cn;
            int j = (col0 >> 2) + jj;
            bf16 hh, hm;
            split_bf(hn, hh, hm);
            oH[(size_t)b * HH + j] = hh;
            oM[(size_t)b * HH + j] = hm;
        }

        if (step < 17) {
            // grid barrier (all threads fence their h stores first)
            __threadfence();
            __syncthreads();
            if (tid == 0) {
                unsigned int expect = s_phase + (unsigned int)(step + 1);
                unsigned int ticket = atomicAdd(&g_bar_count, 1);
                if (ticket == gridDim.x - 1) {
                    g_bar_count = 0;
                    __threadfence();
                    atomicAdd(&g_bar_phase, 1);
                } else {
                    volatile unsigned int* ph = &g_bar_phase;
                    while (*ph < expect) { }
                }
            }
            __syncthreads();
        }
    }
}

// ---------------------------------------------------------------------------
// Prep kernels (fp32 -> split bf16)
// ---------------------------------------------------------------------------
__global__ void split2bf(const float* __restrict__ s,
                         bf16* __restrict__ H, bf16* __restrict__ M, int n4)
{
    int i = blockIdx.x * blockDim.x + threadIdx.x;
    if (i >= n4) return;
    float4 v = reinterpret_cast<const float4*>(s)[i];
    __nv_bfloat162 h0, h1, m0, m1;
    split_bf(v.x, h0.x, m0.x); split_bf(v.y, h0.y, m0.y);
    split_bf(v.z, h1.x, m1.x); split_bf(v.w, h1.y, m1.y);
    reinterpret_cast<__nv_bfloat162*>(H)[2 * i]     = h0;
    reinterpret_cast<__nv_bfloat162*>(H)[2 * i + 1] = h1;
    reinterpret_cast<__nv_bfloat162*>(M)[2 * i]     = m0;
    reinterpret_cast<__nv_bfloat162*>(M)[2 * i + 1] = m1;
}

// dst row p <- src row (p&3)*HH + (p>>2);  rows = 4*HH
__global__ void split_perm_bf(const float* __restrict__ s,
                              bf16* __restrict__ H, bf16* __restrict__ M, int cols)
{
    int i = blockIdx.x * blockDim.x + threadIdx.x;
    int cols4 = cols >> 2;
    int tot = 4 * HH * cols4;
    if (i >= tot) return;
    int p  = i / cols4;
    int cq = i % cols4;
    int sr = (p & 3) * HH + (p >> 2);
    float4 v = *reinterpret_cast<const float4*>(&s[(size_t)sr * cols + cq * 4]);
    __nv_bfloat162 h0, h1, m0, m1;
    split_bf(v.x, h0.x, m0.x); split_bf(v.y, h0.y, m0.y);
    split_bf(v.z, h1.x, m1.x); split_bf(v.w, h1.y, m1.y);
    size_t o = (size_t)p * cols + cq * 4;
    *reinterpret_cast<__nv_bfloat162*>(&H[o])     = h0;
    *reinterpret_cast<__nv_bfloat162*>(&H[o + 2]) = h1;
    *reinterpret_cast<__nv_bfloat162*>(&M[o])     = m0;
    *reinterpret_cast<__nv_bfloat162*>(&M[o + 2]) = m1;
}

__global__ void hands_split_bf(const float* __restrict__ lh, const float* __restrict__ rh,
                               bf16* __restrict__ H, bf16* __restrict__ M)
{
    int i = blockIdx.x * blockDim.x + threadIdx.x;
    if (i >= SS * BB * HPAD) return;
    int col = i % HPAD, row = i / HPAD;
    float v = 0.f;
    if (col < HANDD)          v = lh[row * HANDD + col];
    else if (col < 2 * HANDD) v = rh[row * HANDD + (col - HANDD)];
    bf16 h, m; split_bf(v, h, m);
    H[i] = h; M[i] = m;
}

__global__ void fchw_split_bf(const float* __restrict__ w,
                              bf16* __restrict__ H, bf16* __restrict__ M)
{
    int i = blockIdx.x * blockDim.x + threadIdx.x;
    if (i >= HH * HPAD) return;
    int col = i % HPAD, row = i / HPAD;
    float v = (col < 2 * HANDD) ? w[row * 2 * HANDD + col] : 0.f;
    bf16 h, m; split_bf(v, h, m);
    H[i] = h; M[i] = m;
}

// cls_w (1000x1024) -> padded (1024x1024) split
__global__ void cls_split_bf(const float* __restrict__ w,
                             bf16* __restrict__ H, bf16* __restrict__ M)
{
    int i = blockIdx.x * blockDim.x + threadIdx.x;
    if (i >= 1024 * (HH / 4)) return;
    int rr = i / (HH / 4), cq = i % (HH / 4);
    float4 v = (rr < CC)
        ? *reinterpret_cast<const float4*>(&w[(size_t)rr * HH + cq * 4])
        : make_float4(0.f, 0.f, 0.f, 0.f);
    __nv_bfloat162 h0, h1, m0, m1;
    split_bf(v.x, h0.x, m0.x); split_bf(v.y, h0.y, m0.y);
    split_bf(v.z, h1.x, m1.x); split_bf(v.w, h1.y, m1.y);
    size_t o = (size_t)rr * HH + cq * 4;
    *reinterpret_cast<__nv_bfloat162*>(&H[o])     = h0;
    *reinterpret_cast<__nv_bfloat162*>(&H[o + 2]) = h1;
    *reinterpret_cast<__nv_bfloat162*>(&M[o])     = m0;
    *reinterpret_cast<__nv_bfloat162*>(&M[o + 2]) = m1;
}

__global__ void row_stats(const float* __restrict__ out,
                          const int* __restrict__ act,
                          float* __restrict__ pred_f,
                          float* __restrict__ lossrow)
{
    const int b = blockIdx.x;
    const float* row = out + (size_t)b * CC;
    __shared__ float smax[128];
    __shared__ int   sidx[128];
    __shared__ float ssum[128];
    const int t = threadIdx.x;

    float best = -INFINITY;
    int bidx = 0;
    for (int j = t; j < CC; j += 128) {
        float v = row[j];
        if (v > best) { best = v; bidx = j; }
    }
    smax[t] = best; sidx[t] = bidx;
    __syncthreads();
    for (int s = 64; s > 0; s >>= 1) {
        if (t < s) {
            float v2 = smax[t + s]; int i2 = sidx[t + s];
            if (v2 > smax[t] || (v2 == smax[t] && i2 < sidx[t])) {
                smax[t] = v2; sidx[t] = i2;
            }
        }
        __syncthreads();
    }
    const float rowmax = smax[0];
    const int   rowarg = sidx[0];

    float lsum = 0.f;
    for (int j = t; j < CC; j += 128) lsum += expf(row[j] - rowmax);
    ssum[t] = lsum;
    __syncthreads();
    for (int s = 64; s > 0; s >>= 1) {
        if (t < s) ssum[t] += ssum[t + s];
        __syncthreads();
    }
    if (t == 0) {
        float logz = rowmax + logf(ssum[0]);
        lossrow[b] = logz - row[act[b]];
        if (pred_f) pred_f[b] = (float)rowarg;
    }
}

__global__ void mean_loss(const float* __restrict__ lossrow, float* loss_out)
{
    __shared__ float s[128];
    int t = threadIdx.x;
    s[t] = lossrow[t];
    __syncthreads();
    for (int st = 64; st > 0; st >>= 1) {
        if (t < st) s[t] += s[t + st];
        __syncthreads();
    }
    if (t == 0) *loss_out = s[0] / (float)BB;
}

// ---------------------------------------------------------------------------
// Launch — two-branch graph: side stream runs preps/hproj/gatesxu in parallel
// with the main-path GEMMs. Streams/events are created once (outside capture,
// on the first correctness call) and reused; the captured work is identical
// on every call.
// ---------------------------------------------------------------------------
#define GSM 81920

extern "C" void kernel_launch(void* const* d_in, const int* in_sizes, int n_in,
                              void* d_out, int out_size)
{
    const float* feats    = (const float*)d_in[0];
    const float* lh       = (const float*)d_in[1];
    const float* rh       = (const float*)d_in[2];
    const int*   act      = (const int*)  d_in[3];
    const float* fc1_w    = (const float*)d_in[4];
    const float* fc1_b    = (const float*)d_in[5];
    const float* fch_w    = (const float*)d_in[6];
    const float* fch_b    = (const float*)d_in[7];
    const float* roll_wih = (const float*)d_in[8];
    const float* roll_whh = (const float*)d_in[9];
    const float* roll_bih = (const float*)d_in[10];
    const float* roll_bhh = (const float*)d_in[11];
    const float* u_wih    = (const float*)d_in[12];
    const float* u_whh    = (const float*)d_in[13];
    const float* u_bih    = (const float*)d_in[14];
    const float* u_bhh    = (const float*)d_in[15];
    const float* cls_w    = (const float*)d_in[16];
    const float* cls_b    = (const float*)d_in[17];
    float* out = (float*)d_out;

    cudaFuncSetAttribute(gemm_bf<0, 1>, cudaFuncAttributeMaxDynamicSharedMemorySize, GSM);
    cudaFuncSetAttribute(gemm_bf<1, 0>, cudaFuncAttributeMaxDynamicSharedMemorySize, GSM);
    cudaFuncSetAttribute(gemm_bf<0, 0>, cudaFuncAttributeMaxDynamicSharedMemorySize, GSM);
    cudaFuncSetAttribute(lstm_persistent, cudaFuncAttributeMaxDynamicSharedMemorySize, PSM);

    static cudaStream_t s1 = nullptr;
    static cudaEvent_t evFork = nullptr, evS1 = nullptr, evB = nullptr, evC = nullptr;
    if (!s1) {
        cudaStreamCreateWithFlags(&s1, cudaStreamNonBlocking);
        cudaEventCreateWithFlags(&evFork, cudaEventDisableTiming);
        cudaEventCreateWithFlags(&evS1,   cudaEventDisableTiming);
        cudaEventCreateWithFlags(&evB,    cudaEventDisableTiming);
        cudaEventCreateWithFlags(&evC,    cudaEventDisableTiming);
    }

    float* sc = nullptr;
    cudaGetSymbolAddress((void**)&sc, g_scratch);

    bf16* featsH = (bf16*)(sc + OFF_FEATSH); bf16* featsM = (bf16*)(sc + OFF_FEATSM);
    bf16* xH     = (bf16*)(sc + OFF_XH);     bf16* xM     = (bf16*)(sc + OFF_XM);
    float* gatesx  = sc + OFF_GATESX;
    float* gatesxu = sc + OFF_GATESXU;
    bf16* h0H = (bf16*)(sc + OFF_H0H); bf16* h0M = (bf16*)(sc + OFF_H0M);
    bf16* h1H = (bf16*)(sc + OFF_H1H); bf16* h1M = (bf16*)(sc + OFF_H1M);
    bf16* handsH = (bf16*)(sc + OFF_HANDSH); bf16* handsM = (bf16*)(sc + OFF_HANDSM);
    bf16* fc1H   = (bf16*)(sc + OFF_FC1H);   bf16* fc1M   = (bf16*)(sc + OFF_FC1M);
    bf16* fchwH  = (bf16*)(sc + OFF_FCHWH);  bf16* fchwM  = (bf16*)(sc + OFF_FCHWM);
    bf16* rwihH  = (bf16*)(sc + OFF_RWIHH);  bf16* rwihM  = (bf16*)(sc + OFF_RWIHM);
    bf16* rwhhH  = (bf16*)(sc + OFF_RWHHH);  bf16* rwhhM  = (bf16*)(sc + OFF_RWHHM);
    bf16* uwihH  = (bf16*)(sc + OFF_UWIHH);  bf16* uwihM  = (bf16*)(sc + OFF_UWIHM);
    bf16* uwhhH  = (bf16*)(sc + OFF_UWHHH);  bf16* uwhhM  = (bf16*)(sc + OFF_UWHHM);
    bf16* clsH   = (bf16*)(sc + OFF_CLSH);   bf16* clsM   = (bf16*)(sc + OFF_CLSM);
    float* lossrow = sc + OFF_LOSSROW;

    // ---- fork side stream ----
    cudaEventRecord(evFork, 0);
    cudaStreamWaitEvent(s1, evFork, 0);

    // ---- side stream: preps not on the critical path, then hproj ----
    hands_split_bf<<<(SS*BB*HPAD + 255)/256, 256, 0, s1>>>(lh, rh, handsH, handsM);
    fchw_split_bf<<<(HH*HPAD + 255)/256, 256, 0, s1>>>(fch_w, fchwH, fchwM);
    split_perm_bf<<<(4*HH*(2*HH/4) + 255)/256, 256, 0, s1>>>(roll_wih, rwihH, rwihM, 2*HH);
    gemm_bf<0,1><<<dim3(8,16), 256, GSM, s1>>>(handsH, handsM, HPAD,
                                               fchwH, fchwM, HPAD,
                                               nullptr, xH + HH, xM + HH, 2*HH,
                                               fch_b, nullptr, HH, HPAD);
    cudaEventRecord(evS1, s1);   // hproj + rwih ready (needed by gates)
    split_perm_bf<<<(4*HH*(2*HH/4) + 255)/256, 256, 0, s1>>>(u_wih, uwihH, uwihM, 2*HH);
    split_perm_bf<<<(4*HH*(HH/4)   + 255)/256, 256, 0, s1>>>(roll_whh, rwhhH, rwhhM, HH);
    split_perm_bf<<<(4*HH*(HH/4)   + 255)/256, 256, 0, s1>>>(u_whh, uwhhH, uwhhM, HH);
    cls_split_bf<<<(1024*(HH/4) + 255)/256, 256, 0, s1>>>(cls_w, clsH, clsM);

    // ---- main stream: critical path ----
    split2bf<<<(NB_FEATS/4 + 255)/256, 256>>>(feats, featsH, featsM, NB_FEATS/4);
    split2bf<<<(NB_FC1/4 + 255)/256, 256>>>(fc1_w, fc1H, fc1M, NB_FC1/4);
    gemm_bf<0,1><<<dim3(8,16), 256, GSM>>>(featsH, featsM, FEATD,
                                           fc1H, fc1M, FEATD,
                                           nullptr, xH, xM, 2*HH,
                                           fc1_b, nullptr, HH, FEATD);
    cudaEventRecord(evB, 0);             // xproj done
    cudaStreamWaitEvent(s1, evB, 0);     // side stream: gatesxu needs full x row S-1

    // side stream: gatesxu (concurrent with gates GEMM below)
    gemm_bf<1,0><<<dim3(32,1), 256, GSM, s1>>>(xH + (size_t)(SS-1)*BB*2*HH,
                                               xM + (size_t)(SS-1)*BB*2*HH, 2*HH,
                                               uwihH, uwihM, 2*HH,
                                               gatesxu, nullptr, nullptr, 4*HH,
                                               u_bih, u_bhh, 4*HH, 2*HH);
    cudaEventRecord(evC, s1);

    // main: gates GEMM (needs hproj + rwih from side stream)
    cudaStreamWaitEvent(0, evS1, 0);
    gemm_bf<1,0><<<dim3(32,16), 256, GSM>>>(xH, xM, 2*HH,
                                            rwihH, rwihM, 2*HH,
                                            gatesx, nullptr, nullptr, 4*HH,
                                            roll_bih, roll_bhh, 4*HH, 2*HH);

    // join side stream (gatesxu, rwhh/uwhh, cls splits) before recurrence
    cudaStreamWaitEvent(0, evC, 0);

    // ---- recurrence: one persistent kernel, 18 steps ----
    lstm_persistent<<<128, 256, PSM>>>(rwhhH, rwhhM, uwhhH, uwhhM,
                                       gatesx, gatesxu,
                                       h0H, h0M, h1H, h1M);

    // ---- classifier (final h lands in h0 after 18 steps) ----
    gemm_bf<0,0><<<dim3(8,1), 256, GSM>>>(h0H, h0M, HH,
                                          clsH, clsM, HH,
                                          out, nullptr, nullptr, CC,
                                          cls_b, nullptr, CC, HH);

    // ---- stats ----
    float* pred_f = (out_size >= BB * CC + BB)     ? out + BB * CC : nullptr;
    float* loss_p = (out_size >= BB * CC + BB + 1) ? out + BB * CC + BB : nullptr;
    row_stats<<<BB, 128>>>(out, act, pred_f, lossrow);
    if (loss_p) mean_loss<<<1, 128>>>(lossrow, loss_p);
}

// round 11
// speedup vs baseline: 4.1070x; 1.0536x over previous
#include <cuda_runtime.h>
#include <cuda_bf16.h>
#include <math.h>
#include <stdint.h>

#define SS    16
#define BB    128
#define FEATD 2048
#define HANDD 63
#define HH    1024
#define CC    1000
#define HPAD  128

// ---------------------------------------------------------------------------
// Scratch layout. bf16 arrays are carved out of the float scratch (count/2).
// ---------------------------------------------------------------------------
#define NB_FEATS (SS*BB*FEATD)
#define NB_X     (SS*BB*2*HH)
#define NB_HANDS (SS*BB*HPAD)
#define NB_FC1   (HH*FEATD)
#define NB_FCHW  (HH*HPAD)
#define NB_RWIH  (4*HH*2*HH)
#define NB_RWHH  (4*HH*HH)
#define NB_CLS   (1024*HH)
#define NB_H     (BB*HH)

#define OFF_FEATSH  0
#define OFF_FEATSM  (OFF_FEATSH + NB_FEATS/2)
#define OFF_XH      (OFF_FEATSM + NB_FEATS/2)
#define OFF_XM      (OFF_XH     + NB_X/2)
#define OFF_GATESX  (OFF_XM     + NB_X/2)
#define OFF_GATESXU (OFF_GATESX + SS*BB*4*HH)
#define OFF_H0H     (OFF_GATESXU+ BB*4*HH)
#define OFF_H0M     (OFF_H0H    + NB_H/2)
#define OFF_H1H     (OFF_H0M    + NB_H/2)
#define OFF_H1M     (OFF_H1H    + NB_H/2)
#define OFF_HANDSH  (OFF_H1M    + NB_H/2)
#define OFF_HANDSM  (OFF_HANDSH + NB_HANDS/2)
#define OFF_FC1H    (OFF_HANDSM + NB_HANDS/2)
#define OFF_FC1M    (OFF_FC1H   + NB_FC1/2)
#define OFF_FCHWH   (OFF_FC1M   + NB_FC1/2)
#define OFF_FCHWM   (OFF_FCHWH  + NB_FCHW/2)
#define OFF_RWIHH   (OFF_FCHWM  + NB_FCHW/2)
#define OFF_RWIHM   (OFF_RWIHH  + NB_RWIH/2)
#define OFF_RWHHH   (OFF_RWIHM  + NB_RWIH/2)
#define OFF_RWHHM   (OFF_RWHHH  + NB_RWHH/2)
#define OFF_UWIHH   (OFF_RWHHM  + NB_RWHH/2)
#define OFF_UWIHM   (OFF_UWIHH  + NB_RWIH/2)
#define OFF_UWHHH   (OFF_UWIHM  + NB_RWIH/2)
#define OFF_UWHHM   (OFF_UWHHH  + NB_RWHH/2)
#define OFF_CLSH    (OFF_UWHHM  + NB_RWHH/2)
#define OFF_CLSM    (OFF_CLSH   + NB_CLS/2)
#define OFF_LOSSROW (OFF_CLSM   + NB_CLS/2)
#define SCRATCH_TOT (OFF_LOSSROW + BB)

__device__ __align__(16) float g_scratch[SCRATCH_TOT];

// grid-barrier state (phase-counting; snapshot at kernel entry -> replay-safe)
__device__ unsigned int g_bar_count = 0;
__device__ unsigned int g_bar_phase = 0;

typedef __nv_bfloat16 bf16;

// ---------------------------------------------------------------------------
// helpers
// ---------------------------------------------------------------------------
__device__ __forceinline__ void split_bf(float v, bf16& h, bf16& m)
{
    h = __float2bfloat16_rn(v);
    m = __float2bfloat16_rn(v - __bfloat162float(h));
}

#define MMA_BF16(d, a, b)                                                     \
    asm volatile(                                                             \
        "mma.sync.aligned.m16n8k16.row.col.f32.bf16.bf16.f32 "                \
        "{%0,%1,%2,%3},{%4,%5,%6,%7},{%8,%9},{%0,%1,%2,%3};"                  \
        : "+f"(d[0]), "+f"(d[1]), "+f"(d[2]), "+f"(d[3])                      \
        : "r"(a[0]), "r"(a[1]), "r"(a[2]), "r"(a[3]), "r"(b[0]), "r"(b[1]))

__device__ __forceinline__ void ldsm4(uint32_t& r0, uint32_t& r1,
                                      uint32_t& r2, uint32_t& r3, uint32_t addr)
{
    asm volatile("ldmatrix.sync.aligned.m8n8.x4.shared.b16 {%0,%1,%2,%3}, [%4];"
                 : "=r"(r0), "=r"(r1), "=r"(r2), "=r"(r3) : "r"(addr));
}
__device__ __forceinline__ void ldsm2(uint32_t& r0, uint32_t& r1, uint32_t addr)
{
    asm volatile("ldmatrix.sync.aligned.m8n8.x2.shared.b16 {%0,%1}, [%2];"
                 : "=r"(r0), "=r"(r1) : "r"(addr));
}

__device__ __forceinline__ void cp16(uint32_t dst, const void* src)
{
    asm volatile("cp.async.cg.shared.global [%0], [%1], 16;" :: "r"(dst), "l"(src));
}
__device__ __forceinline__ void cp_commit() { asm volatile("cp.async.commit_group;"); }
__device__ __forceinline__ void cp_wait()   { asm volatile("cp.async.wait_group 0;"); }
__device__ __forceinline__ void cp_wait1()  { asm volatile("cp.async.wait_group 1;"); }

// ---------------------------------------------------------------------------
// bf16x2-split GEMM (3 products): C = A*W^T (+bias)  [proven]
// ---------------------------------------------------------------------------
template<int PERMBIAS, int SPLITOUT>
__global__ void __launch_bounds__(256, 2)
gemm_bf(const bf16* __restrict__ AH, const bf16* __restrict__ AM, int lda,
        const bf16* __restrict__ WH, const bf16* __restrict__ WM, int ldw,
        float* __restrict__ Cf, bf16* __restrict__ CbH, bf16* __restrict__ CbM,
        int ldc, const float* __restrict__ b1, const float* __restrict__ b2,
        int Nstore, int K)
{
    extern __shared__ __align__(16) char smraw[];
    const uint32_t sbase = (uint32_t)__cvta_generic_to_shared(smraw);

    const int tid  = threadIdx.x;
    const int lane = tid & 31;
    const int warp = tid >> 5;
    const int wm   = warp >> 2;
    const int wn   = warp & 3;
    const int row0 = blockIdx.y * 128;
    const int col0 = blockIdx.x * 128;

    float acc[4][4][4];
#pragma unroll
    for (int i = 0; i < 4; i++)
#pragma unroll
        for (int j = 0; j < 4; j++)
#pragma unroll
            for (int q = 0; q < 4; q++) acc[i][j][q] = 0.f;

    const int r  = tid >> 2;
    const int ch = tid & 3;

    auto gload = [&](int buf, int k0) {
        const uint32_t bo = (uint32_t)(buf * 40960);
#pragma unroll
        for (int l = 0; l < 2; l++) {
            int rr = r + l * 64;
            uint32_t so = (uint32_t)(rr * 80 + ch * 16);
            cp16(sbase + bo +         so, &AH[(size_t)(row0 + rr) * lda + k0 + ch * 8]);
            cp16(sbase + bo + 10240 + so, &AM[(size_t)(row0 + rr) * lda + k0 + ch * 8]);
            cp16(sbase + bo + 20480 + so, &WH[(size_t)(col0 + rr) * ldw + k0 + ch * 8]);
            cp16(sbase + bo + 30720 + so, &WM[(size_t)(col0 + rr) * ldw + k0 + ch * 8]);
        }
        cp_commit();
    };

    const int nk = K / 32;
    gload(0, 0);
    cp_wait();
    __syncthreads();

    for (int kt = 0; kt < nk; kt++) {
        const int cur = kt & 1;
        if (kt + 1 < nk) gload(cur ^ 1, (kt + 1) * 32);

        const uint32_t bo  = (uint32_t)(cur * 40960);
        const uint32_t aA0 = sbase + bo;
        const uint32_t aA1 = sbase + bo + 10240;
        const uint32_t aB0 = sbase + bo + 20480;
        const uint32_t aB1 = sbase + bo + 30720;

#pragma unroll
        for (int s = 0; s < 2; s++) {
            uint32_t b0f[4][2], b1f[4][2];
            const uint32_t bOff = (uint32_t)((lane & 7) * 80 + s * 32 + ((lane >> 3) & 1) * 16);
#pragma unroll
            for (int nt = 0; nt < 4; nt++) {
                uint32_t na = (uint32_t)((wn * 32 + nt * 8) * 80);
                ldsm2(b0f[nt][0], b0f[nt][1], aB0 + na + bOff);
                ldsm2(b1f[nt][0], b1f[nt][1], aB1 + na + bOff);
            }
            const uint32_t aOff = (uint32_t)((lane & 15) * 80 + s * 32 + (lane >> 4) * 16);
#pragma unroll
            for (int mt = 0; mt < 4; mt++) {
                uint32_t ma = (uint32_t)((wm * 64 + mt * 16) * 80);
                uint32_t a0[4], a1[4];
                ldsm4(a0[0], a0[1], a0[2], a0[3], aA0 + ma + aOff);
                ldsm4(a1[0], a1[1], a1[2], a1[3], aA1 + ma + aOff);
#pragma unroll
                for (int nt = 0; nt < 4; nt++) {
                    MMA_BF16(acc[mt][nt], a0, b0f[nt]);
                    MMA_BF16(acc[mt][nt], a0, b1f[nt]);
                    MMA_BF16(acc[mt][nt], a1, b0f[nt]);
                }
            }
        }

        if (kt + 1 < nk) { cp_wait(); __syncthreads(); }
    }

#pragma unroll
    for (int mt = 0; mt < 4; mt++)
#pragma unroll
        for (int nt = 0; nt < 4; nt++) {
            int m = row0 + wm * 64 + mt * 16 + (lane >> 2);
            int n = col0 + wn * 32 + nt * 8 + 2 * (lane & 3);
            if (n + 1 >= Nstore) continue;
            float bv0 = 0.f, bv1 = 0.f;
            int bi0 = PERMBIAS ? ((n & 3) * HH + (n >> 2)) : n;
            int bi1 = PERMBIAS ? (((n + 1) & 3) * HH + ((n + 1) >> 2)) : (n + 1);
            if (b1) { bv0 += b1[bi0]; bv1 += b1[bi1]; }
            if (b2) { bv0 += b2[bi0]; bv1 += b2[bi1]; }
            float v00 = acc[mt][nt][0] + bv0, v01 = acc[mt][nt][1] + bv1;
            float v10 = acc[mt][nt][2] + bv0, v11 = acc[mt][nt][3] + bv1;
            if (SPLITOUT) {
                __nv_bfloat162 h0, m0, h1, m1;
                split_bf(v00, h0.x, m0.x); split_bf(v01, h0.y, m0.y);
                split_bf(v10, h1.x, m1.x); split_bf(v11, h1.y, m1.y);
                *reinterpret_cast<__nv_bfloat162*>(&CbH[(size_t)m * ldc + n])       = h0;
                *reinterpret_cast<__nv_bfloat162*>(&CbM[(size_t)m * ldc + n])       = m0;
                *reinterpret_cast<__nv_bfloat162*>(&CbH[(size_t)(m + 8) * ldc + n]) = h1;
                *reinterpret_cast<__nv_bfloat162*>(&CbM[(size_t)(m + 8) * ldc + n]) = m1;
            } else {
                *reinterpret_cast<float2*>(&Cf[(size_t)m * ldc + n])       = make_float2(v00, v01);
                *reinterpret_cast<float2*>(&Cf[(size_t)(m + 8) * ldc + n]) = make_float2(v10, v11);
            }
        }
}

// ---------------------------------------------------------------------------
// Persistent LSTM recurrence: all 18 steps in one kernel.
// R10 version + (a) 3-stage cp.async ring (2 compute-periods of latency
// hiding) with gsum aliased into A-stage buffer 0, (b) fence-free grid
// barrier: __syncthreads + single release-atomic / acquire-poll per CTA
// (the grid.sync pattern) instead of 256 GPU-scope membars.
//
// smem layout (dyn, 214016 B):
//   0      : A stages, 3 bufs x (H 10240 | M 10240) = 61440   (gsum aliases buf0)
//   61440  : W_H  32 rows x 2064 B                  = 66048
//   127488 : W_M  32 rows x 2064 B                  = 66048
//   193536 : gx stage 128 rows x 128 B              = 16384
//   209920 : c    128 x 8 floats                    = 4096
// ---------------------------------------------------------------------------
#define PSM  214016
#define SW_H 61440
#define SW_M 127488
#define SGX  193536
#define SCC  209920
#define WSTR 2064

__global__ void __launch_bounds__(256)
lstm_persistent(const bf16* __restrict__ rwhhH, const bf16* __restrict__ rwhhM,
                const bf16* __restrict__ uwhhH, const bf16* __restrict__ uwhhM,
                const float* __restrict__ gatesx,   // [16][128][4096] permuted
                const float* __restrict__ gatesxu,  // [128][4096] permuted
                bf16* __restrict__ h0H, bf16* __restrict__ h0M,
                bf16* __restrict__ h1H, bf16* __restrict__ h1M)
{
    extern __shared__ __align__(16) char smraw[];
    const uint32_t sbase = (uint32_t)__cvta_generic_to_shared(smraw);
    float* gsum = reinterpret_cast<float*>(smraw);          // aliases A buf 0
    float* c_sm = reinterpret_cast<float*>(smraw + SCC);

    const int tid  = threadIdx.x;
    const int lane = tid & 31;
    const int warp = tid >> 5;
    const int col0 = blockIdx.x * 32;

    // snapshot barrier phase BEFORE first arrival (replay-safe)
    __shared__ unsigned int s_phase;
    if (tid == 0) s_phase = g_bar_phase;

    // init resident c = 0
#pragma unroll
    for (int q = 0; q < 4; q++) c_sm[tid + q * 256] = 0.f;

    const int r  = tid >> 2;
    const int ch = tid & 3;

    // ---- load resident weights: 32 rows x 2048 B (hi & mid), stride 2064 ----
    auto load_weights = [&](const bf16* wH, const bf16* wM) {
        for (int i = tid; i < 4096; i += 256) {
            int row = i >> 7;
            int chk = i & 127;
            uint32_t so = (uint32_t)(row * WSTR + chk * 16);
            cp16(sbase + SW_H + so, &wH[(size_t)(col0 + row) * HH + chk * 8]);
            cp16(sbase + SW_M + so, &wM[(size_t)(col0 + row) * HH + chk * 8]);
        }
        cp_commit();
        cp_wait();
        __syncthreads();
    };
    load_weights(rwhhH, rwhhM);

    for (int step = 0; step < 18; step++) {
        const bf16* hH = (step & 1) ? h1H : h0H;
        const bf16* hM = (step & 1) ? h1M : h0M;
        bf16* oH = (step & 1) ? h0H : h1H;
        bf16* oM = (step & 1) ? h0M : h1M;
        const float* gx = (step < SS) ? gatesx + (size_t)step * BB * 4 * HH
                                      : gatesxu;

        if (step == SS) load_weights(uwhhH, uwhhM);   // switch to unroll weights

        // stage this step's gx slice (128 rows x 128 B) into smem early
        {
#pragma unroll
            for (int l = 0; l < 4; l++) {
                int idx = tid + l * 256;
                int b   = idx >> 3;
                int chk = idx & 7;
                cp16(sbase + SGX + (uint32_t)(b * 128 + chk * 16),
                     &gx[(size_t)b * (4 * HH) + col0 + chk * 4]);
            }
            cp_commit();
        }

        float acc[4][4];
#pragma unroll
        for (int j = 0; j < 4; j++)
#pragma unroll
            for (int q = 0; q < 4; q++) acc[j][q] = 0.f;

        if (step > 0) {
            // ---- GEMM: gates_h[128 x 32] = h[128 x 1024] @ Wres^T ----
            // 3-stage ring over A tiles; single __syncthreads per iteration.
            auto gloadA = [&](int buf, int k0) {
                const uint32_t bo = (uint32_t)(buf * 20480);
#pragma unroll
                for (int l = 0; l < 2; l++) {
                    int rr = r + l * 64;
                    uint32_t so = (uint32_t)(rr * 80 + ch * 16);
                    cp16(sbase + bo +         so, &hH[(size_t)rr * HH + k0 + ch * 8]);
                    cp16(sbase + bo + 10240 + so, &hM[(size_t)rr * HH + k0 + ch * 8]);
                }
                cp_commit();
            };

            gloadA(0, 0);
            gloadA(1, 32);

            for (int kt = 0; kt < 32; kt++) {
                if (kt == 31) cp_wait(); else cp_wait1();   // buffer kt ready
                __syncthreads();

                const int buf = kt % 3;
                const uint32_t aA0 = sbase + (uint32_t)(buf * 20480);
                const uint32_t aA1 = aA0 + 10240;

#pragma unroll
                for (int s = 0; s < 2; s++) {
                    uint32_t b0f[4][2], b1f[4][2];
                    const uint32_t bOff = (uint32_t)((lane & 7) * WSTR + kt * 64
                                                     + s * 32 + ((lane >> 3) & 1) * 16);
#pragma unroll
                    for (int nt = 0; nt < 4; nt++) {
                        uint32_t na = (uint32_t)((nt * 8) * WSTR);
                        ldsm2(b0f[nt][0], b0f[nt][1], sbase + SW_H + na + bOff);
                        ldsm2(b1f[nt][0], b1f[nt][1], sbase + SW_M + na + bOff);
                    }
                    const uint32_t aOff = (uint32_t)((warp * 16 + (lane & 15)) * 80
                                                     + s * 32 + (lane >> 4) * 16);
                    uint32_t a0[4], a1[4];
                    ldsm4(a0[0], a0[1], a0[2], a0[3], aA0 + aOff);
                    ldsm4(a1[0], a1[1], a1[2], a1[3], aA1 + aOff);
#pragma unroll
                    for (int nt = 0; nt < 4; nt++) {
                        MMA_BF16(acc[nt], a0, b0f[nt]);
                        MMA_BF16(acc[nt], a0, b1f[nt]);
                        MMA_BF16(acc[nt], a1, b0f[nt]);
                    }
                }

                if (kt + 2 < 32) gloadA((kt + 2) % 3, (kt + 2) * 32);
            }
            __syncthreads();   // all warps done with buf0 before gsum alias write
        } else {
            cp_wait();         // gx stage
            __syncthreads();
        }

        // dump accumulators (gsum aliases A buf 0 — GEMM is fully drained)
#pragma unroll
        for (int nt = 0; nt < 4; nt++) {
            int m = warp * 16 + (lane >> 2);
            int n = nt * 8 + 2 * (lane & 3);
            gsum[m * 36 + n]           = acc[nt][0];
            gsum[m * 36 + n + 1]       = acc[nt][1];
            gsum[(m + 8) * 36 + n]     = acc[nt][2];
            gsum[(m + 8) * 36 + n + 1] = acc[nt][3];
        }
        __syncthreads();

        // cell (gx read from smem stage)
#pragma unroll
        for (int q = 0; q < 4; q++) {
            int idx = tid + q * 256;
            int b  = idx >> 3;
            int jj = idx & 7;
            float4 g  = *reinterpret_cast<float4*>(&gsum[b * 36 + jj * 4]);
            float4 gv = *reinterpret_cast<float4*>(smraw + SGX + b * 128 + jj * 16);
            float gi = g.x + gv.x;
            float gf = g.y + gv.y;
            float gg = g.z + gv.z;
            float go = g.w + gv.w;
            float si = 1.f / (1.f + expf(-gi));
            float sf = 1.f / (1.f + expf(-gf));
            float so = 1.f / (1.f + expf(-go));
            float tg = tanhf(gg);
            float cn = sf * c_sm[b * 8 + jj] + si * tg;
            float hn = so * tanhf(cn);
            c_sm[b * 8 + jj] = cn;
            int j = (col0 >> 2) + jj;
            bf16 hh, hm;
            split_bf(hn, hh, hm);
            oH[(size_t)b * HH + j] = hh;
            oM[(size_t)b * HH + j] = hm;
        }

        if (step < 17) {
            // fence-free grid barrier: bar.sync gives CTA-scope ordering of the
            // h stores above; thread 0's release-atomic publishes them at GPU
            // scope; waiters acquire-poll (grid.sync pattern).
            __syncthreads();
            if (tid == 0) {
                unsigned int expect = s_phase + (unsigned int)(step + 1);
                unsigned int ticket;
                asm volatile("atom.release.gpu.global.add.u32 %0, [%1], 1;"
                             : "=r"(ticket) : "l"(&g_bar_count) : "memory");
                if (ticket == gridDim.x - 1) {
                    asm volatile("st.relaxed.gpu.global.u32 [%0], %1;"
                                 :: "l"(&g_bar_count), "r"(0u) : "memory");
                    unsigned int dummy;
                    asm volatile("atom.release.gpu.global.add.u32 %0, [%1], 1;"
                                 : "=r"(dummy) : "l"(&g_bar_phase) : "memory");
                } else {
                    unsigned int ph;
                    do {
                        asm volatile("ld.acquire.gpu.global.u32 %0, [%1];"
                                     : "=r"(ph) : "l"(&g_bar_phase) : "memory");
                    } while (ph < expect);
                }
            }
            __syncthreads();
        }
    }
}

// ---------------------------------------------------------------------------
// Prep kernels (fp32 -> split bf16)
// ---------------------------------------------------------------------------
__global__ void split2bf(const float* __restrict__ s,
                         bf16* __restrict__ H, bf16* __restrict__ M, int n4)
{
    int i = blockIdx.x * blockDim.x + threadIdx.x;
    if (i >= n4) return;
    float4 v = reinterpret_cast<const float4*>(s)[i];
    __nv_bfloat162 h0, h1, m0, m1;
    split_bf(v.x, h0.x, m0.x); split_bf(v.y, h0.y, m0.y);
    split_bf(v.z, h1.x, m1.x); split_bf(v.w, h1.y, m1.y);
    reinterpret_cast<__nv_bfloat162*>(H)[2 * i]     = h0;
    reinterpret_cast<__nv_bfloat162*>(H)[2 * i + 1] = h1;
    reinterpret_cast<__nv_bfloat162*>(M)[2 * i]     = m0;
    reinterpret_cast<__nv_bfloat162*>(M)[2 * i + 1] = m1;
}

// dst row p <- src row (p&3)*HH + (p>>2);  rows = 4*HH
__global__ void split_perm_bf(const float* __restrict__ s,
                              bf16* __restrict__ H, bf16* __restrict__ M, int cols)
{
    int i = blockIdx.x * blockDim.x + threadIdx.x;
    int cols4 = cols >> 2;
    int tot = 4 * HH * cols4;
    if (i >= tot) return;
    int p  = i / cols4;
    int cq = i % cols4;
    int sr = (p & 3) * HH + (p >> 2);
    float4 v = *reinterpret_cast<const float4*>(&s[(size_t)sr * cols + cq * 4]);
    __nv_bfloat162 h0, h1, m0, m1;
    split_bf(v.x, h0.x, m0.x); split_bf(v.y, h0.y, m0.y);
    split_bf(v.z, h1.x, m1.x); split_bf(v.w, h1.y, m1.y);
    size_t o = (size_t)p * cols + cq * 4;
    *reinterpret_cast<__nv_bfloat162*>(&H[o])     = h0;
    *reinterpret_cast<__nv_bfloat162*>(&H[o + 2]) = h1;
    *reinterpret_cast<__nv_bfloat162*>(&M[o])     = m0;
    *reinterpret_cast<__nv_bfloat162*>(&M[o + 2]) = m1;
}

__global__ void hands_split_bf(const float* __restrict__ lh, const float* __restrict__ rh,
                               bf16* __restrict__ H, bf16* __restrict__ M)
{
    int i = blockIdx.x * blockDim.x + threadIdx.x;
    if (i >= SS * BB * HPAD) return;
    int col = i % HPAD, row = i / HPAD;
    float v = 0.f;
    if (col < HANDD)          v = lh[row * HANDD + col];
    else if (col < 2 * HANDD) v = rh[row * HANDD + (col - HANDD)];
    bf16 h, m; split_bf(v, h, m);
    H[i] = h; M[i] = m;
}

__global__ void fchw_split_bf(const float* __restrict__ w,
                              bf16* __restrict__ H, bf16* __restrict__ M)
{
    int i = blockIdx.x * blockDim.x + threadIdx.x;
    if (i >= HH * HPAD) return;
    int col = i % HPAD, row = i / HPAD;
    float v = (col < 2 * HANDD) ? w[row * 2 * HANDD + col] : 0.f;
    bf16 h, m; split_bf(v, h, m);
    H[i] = h; M[i] = m;
}

// cls_w (1000x1024) -> padded (1024x1024) split
__global__ void cls_split_bf(const float* __restrict__ w,
                             bf16* __restrict__ H, bf16* __restrict__ M)
{
    int i = blockIdx.x * blockDim.x + threadIdx.x;
    if (i >= 1024 * (HH / 4)) return;
    int rr = i / (HH / 4), cq = i % (HH / 4);
    float4 v = (rr < CC)
        ? *reinterpret_cast<const float4*>(&w[(size_t)rr * HH + cq * 4])
        : make_float4(0.f, 0.f, 0.f, 0.f);
    __nv_bfloat162 h0, h1, m0, m1;
    split_bf(v.x, h0.x, m0.x); split_bf(v.y, h0.y, m0.y);
    split_bf(v.z, h1.x, m1.x); split_bf(v.w, h1.y, m1.y);
    size_t o = (size_t)rr * HH + cq * 4;
    *reinterpret_cast<__nv_bfloat162*>(&H[o])     = h0;
    *reinterpret_cast<__nv_bfloat162*>(&H[o + 2]) = h1;
    *reinterpret_cast<__nv_bfloat162*>(&M[o])     = m0;
    *reinterpret_cast<__nv_bfloat162*>(&M[o + 2]) = m1;
}

__global__ void row_stats(const float* __restrict__ out,
                          const int* __restrict__ act,
                          float* __restrict__ pred_f,
                          float* __restrict__ lossrow)
{
    const int b = blockIdx.x;
    const float* row = out + (size_t)b * CC;
    __shared__ float smax[128];
    __shared__ int   sidx[128];
    __shared__ float ssum[128];
    const int t = threadIdx.x;

    float best = -INFINITY;
    int bidx = 0;
    for (int j = t; j < CC; j += 128) {
        float v = row[j];
        if (v > best) { best = v; bidx = j; }
    }
    smax[t] = best; sidx[t] = bidx;
    __syncthreads();
    for (int s = 64; s > 0; s >>= 1) {
        if (t < s) {
            float v2 = smax[t + s]; int i2 = sidx[t + s];
            if (v2 > smax[t] || (v2 == smax[t] && i2 < sidx[t])) {
                smax[t] = v2; sidx[t] = i2;
            }
        }
        __syncthreads();
    }
    const float rowmax = smax[0];
    const int   rowarg = sidx[0];

    float lsum = 0.f;
    for (int j = t; j < CC; j += 128) lsum += expf(row[j] - rowmax);
    ssum[t] = lsum;
    __syncthreads();
    for (int s = 64; s > 0; s >>= 1) {
        if (t < s) ssum[t] += ssum[t + s];
        __syncthreads();
    }
    if (t == 0) {
        float logz = rowmax + logf(ssum[0]);
        lossrow[b] = logz - row[act[b]];
        if (pred_f) pred_f[b] = (float)rowarg;
    }
}

__global__ void mean_loss(const float* __restrict__ lossrow, float* loss_out)
{
    __shared__ float s[128];
    int t = threadIdx.x;
    s[t] = lossrow[t];
    __syncthreads();
    for (int st = 64; st > 0; st >>= 1) {
        if (t < st) s[t] += s[t + st];
        __syncthreads();
    }
    if (t == 0) *loss_out = s[0] / (float)BB;
}

// ---------------------------------------------------------------------------
// Launch — two-branch graph (proven in R10)
// ---------------------------------------------------------------------------
#define GSM 81920

extern "C" void kernel_launch(void* const* d_in, const int* in_sizes, int n_in,
                              void* d_out, int out_size)
{
    const float* feats    = (const float*)d_in[0];
    const float* lh       = (const float*)d_in[1];
    const float* rh       = (const float*)d_in[2];
    const int*   act      = (const int*)  d_in[3];
    const float* fc1_w    = (const float*)d_in[4];
    const float* fc1_b    = (const float*)d_in[5];
    const float* fch_w    = (const float*)d_in[6];
    const float* fch_b    = (const float*)d_in[7];
    const float* roll_wih = (const float*)d_in[8];
    const float* roll_whh = (const float*)d_in[9];
    const float* roll_bih = (const float*)d_in[10];
    const float* roll_bhh = (const float*)d_in[11];
    const float* u_wih    = (const float*)d_in[12];
    const float* u_whh    = (const float*)d_in[13];
    const float* u_bih    = (const float*)d_in[14];
    const float* u_bhh    = (const float*)d_in[15];
    const float* cls_w    = (const float*)d_in[16];
    const float* cls_b    = (const float*)d_in[17];
    float* out = (float*)d_out;

    cudaFuncSetAttribute(gemm_bf<0, 1>, cudaFuncAttributeMaxDynamicSharedMemorySize, GSM);
    cudaFuncSetAttribute(gemm_bf<1, 0>, cudaFuncAttributeMaxDynamicSharedMemorySize, GSM);
    cudaFuncSetAttribute(gemm_bf<0, 0>, cudaFuncAttributeMaxDynamicSharedMemorySize, GSM);
    cudaFuncSetAttribute(lstm_persistent, cudaFuncAttributeMaxDynamicSharedMemorySize, PSM);

    static cudaStream_t s1 = nullptr;
    static cudaEvent_t evFork = nullptr, evS1 = nullptr, evB = nullptr, evC = nullptr;
    if (!s1) {
        cudaStreamCreateWithFlags(&s1, cudaStreamNonBlocking);
        cudaEventCreateWithFlags(&evFork, cudaEventDisableTiming);
        cudaEventCreateWithFlags(&evS1,   cudaEventDisableTiming);
        cudaEventCreateWithFlags(&evB,    cudaEventDisableTiming);
        cudaEventCreateWithFlags(&evC,    cudaEventDisableTiming);
    }

    float* sc = nullptr;
    cudaGetSymbolAddress((void**)&sc, g_scratch);

    bf16* featsH = (bf16*)(sc + OFF_FEATSH); bf16* featsM = (bf16*)(sc + OFF_FEATSM);
    bf16* xH     = (bf16*)(sc + OFF_XH);     bf16* xM     = (bf16*)(sc + OFF_XM);
    float* gatesx  = sc + OFF_GATESX;
    float* gatesxu = sc + OFF_GATESXU;
    bf16* h0H = (bf16*)(sc + OFF_H0H); bf16* h0M = (bf16*)(sc + OFF_H0M);
    bf16* h1H = (bf16*)(sc + OFF_H1H); bf16* h1M = (bf16*)(sc + OFF_H1M);
    bf16* handsH = (bf16*)(sc + OFF_HANDSH); bf16* handsM = (bf16*)(sc + OFF_HANDSM);
    bf16* fc1H   = (bf16*)(sc + OFF_FC1H);   bf16* fc1M   = (bf16*)(sc + OFF_FC1M);
    bf16* fchwH  = (bf16*)(sc + OFF_FCHWH);  bf16* fchwM  = (bf16*)(sc + OFF_FCHWM);
    bf16* rwihH  = (bf16*)(sc + OFF_RWIHH);  bf16* rwihM  = (bf16*)(sc + OFF_RWIHM);
    bf16* rwhhH  = (bf16*)(sc + OFF_RWHHH);  bf16* rwhhM  = (bf16*)(sc + OFF_RWHHM);
    bf16* uwihH  = (bf16*)(sc + OFF_UWIHH);  bf16* uwihM  = (bf16*)(sc + OFF_UWIHM);
    bf16* uwhhH  = (bf16*)(sc + OFF_UWHHH);  bf16* uwhhM  = (bf16*)(sc + OFF_UWHHM);
    bf16* clsH   = (bf16*)(sc + OFF_CLSH);   bf16* clsM   = (bf16*)(sc + OFF_CLSM);
    float* lossrow = sc + OFF_LOSSROW;

    // ---- fork side stream ----
    cudaEventRecord(evFork, 0);
    cudaStreamWaitEvent(s1, evFork, 0);

    // ---- side stream: preps not on the critical path, then hproj ----
    hands_split_bf<<<(SS*BB*HPAD + 255)/256, 256, 0, s1>>>(lh, rh, handsH, handsM);
    fchw_split_bf<<<(HH*HPAD + 255)/256, 256, 0, s1>>>(fch_w, fchwH, fchwM);
    split_perm_bf<<<(4*HH*(2*HH/4) + 255)/256, 256, 0, s1>>>(roll_wih, rwihH, rwihM, 2*HH);
    gemm_bf<0,1><<<dim3(8,16), 256, GSM, s1>>>(handsH, handsM, HPAD,
                                               fchwH, fchwM, HPAD,
                                               nullptr, xH + HH, xM + HH, 2*HH,
                                               fch_b, nullptr, HH, HPAD);
    cudaEventRecord(evS1, s1);   // hproj + rwih ready (needed by gates)
    split_perm_bf<<<(4*HH*(2*HH/4) + 255)/256, 256, 0, s1>>>(u_wih, uwihH, uwihM, 2*HH);
    split_perm_bf<<<(4*HH*(HH/4)   + 255)/256, 256, 0, s1>>>(roll_whh, rwhhH, rwhhM, HH);
    split_perm_bf<<<(4*HH*(HH/4)   + 255)/256, 256, 0, s1>>>(u_whh, uwhhH, uwhhM, HH);
    cls_split_bf<<<(1024*(HH/4) + 255)/256, 256, 0, s1>>>(cls_w, clsH, clsM);

    // ---- main stream: critical path ----
    split2bf<<<(NB_FEATS/4 + 255)/256, 256>>>(feats, featsH, featsM, NB_FEATS/4);
    split2bf<<<(NB_FC1/4 + 255)/256, 256>>>(fc1_w, fc1H, fc1M, NB_FC1/4);
    gemm_bf<0,1><<<dim3(8,16), 256, GSM>>>(featsH, featsM, FEATD,
                                           fc1H, fc1M, FEATD,
                                           nullptr, xH, xM, 2*HH,
                                           fc1_b, nullptr, HH, FEATD);
    cudaEventRecord(evB, 0);             // xproj done
    cudaStreamWaitEvent(s1, evB, 0);     // side stream: gatesxu needs full x row S-1

    // side stream: gatesxu (concurrent with gates GEMM below)
    gemm_bf<1,0><<<dim3(32,1), 256, GSM, s1>>>(xH + (size_t)(SS-1)*BB*2*HH,
                                               xM + (size_t)(SS-1)*BB*2*HH, 2*HH,
                                               uwihH, uwihM, 2*HH,
                                               gatesxu, nullptr, nullptr, 4*HH,
                                               u_bih, u_bhh, 4*HH, 2*HH);
    cudaEventRecord(evC, s1);

    // main: gates GEMM (needs hproj + rwih from side stream)
    cudaStreamWaitEvent(0, evS1, 0);
    gemm_bf<1,0><<<dim3(32,16), 256, GSM>>>(xH, xM, 2*HH,
                                            rwihH, rwihM, 2*HH,
                                            gatesx, nullptr, nullptr, 4*HH,
                                            roll_bih, roll_bhh, 4*HH, 2*HH);

    // join side stream (gatesxu, rwhh/uwhh, cls splits) before recurrence
    cudaStreamWaitEvent(0, evC, 0);

    // ---- recurrence: one persistent kernel, 18 steps ----
    lstm_persistent<<<128, 256, PSM>>>(rwhhH, rwhhM, uwhhH, uwhhM,
                                       gatesx, gatesxu,
                                       h0H, h0M, h1H, h1M);

    // ---- classifier (final h lands in h0 after 18 steps) ----
    gemm_bf<0,0><<<dim3(8,1), 256, GSM>>>(h0H, h0M, HH,
                                          clsH, clsM, HH,
                                          out, nullptr, nullptr, CC,
                                          cls_b, nullptr, CC, HH);

    // ---- stats ----
    float* pred_f = (out_size >= BB * CC + BB)     ? out + BB * CC : nullptr;
    float* loss_p = (out_size >= BB * CC + BB + 1) ? out + BB * CC + BB : nullptr;
    row_stats<<<BB, 128>>>(out, act, pred_f, lossrow);
    if (loss_p) mean_loss<<<1, 128>>>(lossrow, loss_p);
}

// round 12
// speedup vs baseline: 4.2907x; 1.0447x over previous
#include <cuda_runtime.h>
#include <cuda_bf16.h>
#include <math.h>
#include <stdint.h>

#define SS    16
#define BB    128
#define FEATD 2048
#define HANDD 63
#define HH    1024
#define CC    1000
#define HPAD  128

// ---------------------------------------------------------------------------
// Scratch layout. bf16 arrays are carved out of the float scratch (count/2).
// ---------------------------------------------------------------------------
#define NB_FEATS (SS*BB*FEATD)
#define NB_X     (SS*BB*2*HH)
#define NB_HANDS (SS*BB*HPAD)
#define NB_FC1   (HH*FEATD)
#define NB_FCHW  (HH*HPAD)
#define NB_RWIH  (4*HH*2*HH)
#define NB_RWHH  (4*HH*HH)
#define NB_CLS   (1024*HH)
#define NB_H     (BB*HH)

#define OFF_FEATSH  0
#define OFF_FEATSM  (OFF_FEATSH + NB_FEATS/2)
#define OFF_XH      (OFF_FEATSM + NB_FEATS/2)
#define OFF_XM      (OFF_XH     + NB_X/2)
#define OFF_GATESX  (OFF_XM     + NB_X/2)
#define OFF_GATESXU (OFF_GATESX + SS*BB*4*HH)
#define OFF_H0H     (OFF_GATESXU+ BB*4*HH)
#define OFF_H0M     (OFF_H0H    + NB_H/2)
#define OFF_H1H     (OFF_H0M    + NB_H/2)
#define OFF_H1M     (OFF_H1H    + NB_H/2)
#define OFF_HANDSH  (OFF_H1M    + NB_H/2)
#define OFF_HANDSM  (OFF_HANDSH + NB_HANDS/2)
#define OFF_FC1H    (OFF_HANDSM + NB_HANDS/2)
#define OFF_FC1M    (OFF_FC1H   + NB_FC1/2)
#define OFF_FCHWH   (OFF_FC1M   + NB_FC1/2)
#define OFF_FCHWM   (OFF_FCHWH  + NB_FCHW/2)
#define OFF_RWIHH   (OFF_FCHWM  + NB_FCHW/2)
#define OFF_RWIHM   (OFF_RWIHH  + NB_RWIH/2)
#define OFF_RWHHH   (OFF_RWIHM  + NB_RWIH/2)
#define OFF_RWHHM   (OFF_RWHHH  + NB_RWHH/2)
#define OFF_UWIHH   (OFF_RWHHM  + NB_RWHH/2)
#define OFF_UWIHM   (OFF_UWIHH  + NB_RWIH/2)
#define OFF_UWHHH   (OFF_UWIHM  + NB_RWIH/2)
#define OFF_UWHHM   (OFF_UWHHH  + NB_RWHH/2)
#define OFF_CLSH    (OFF_UWHHM  + NB_RWHH/2)
#define OFF_CLSM    (OFF_CLSH   + NB_CLS/2)
#define OFF_LOSSROW (OFF_CLSM   + NB_CLS/2)
#define SCRATCH_TOT (OFF_LOSSROW + BB)

__device__ __align__(16) float g_scratch[SCRATCH_TOT];

// grid-barrier state (phase-counting; snapshot at kernel entry -> replay-safe)
__device__ unsigned int g_bar_count = 0;
__device__ unsigned int g_bar_phase = 0;

typedef __nv_bfloat16 bf16;

// ---------------------------------------------------------------------------
// helpers
// ---------------------------------------------------------------------------
__device__ __forceinline__ void split_bf(float v, bf16& h, bf16& m)
{
    h = __float2bfloat16_rn(v);
    m = __float2bfloat16_rn(v - __bfloat162float(h));
}

#define MMA_BF16(d, a, b)                                                     \
    asm volatile(                                                             \
        "mma.sync.aligned.m16n8k16.row.col.f32.bf16.bf16.f32 "                \
        "{%0,%1,%2,%3},{%4,%5,%6,%7},{%8,%9},{%0,%1,%2,%3};"                  \
        : "+f"(d[0]), "+f"(d[1]), "+f"(d[2]), "+f"(d[3])                      \
        : "r"(a[0]), "r"(a[1]), "r"(a[2]), "r"(a[3]), "r"(b[0]), "r"(b[1]))

__device__ __forceinline__ void ldsm4(uint32_t& r0, uint32_t& r1,
                                      uint32_t& r2, uint32_t& r3, uint32_t addr)
{
    asm volatile("ldmatrix.sync.aligned.m8n8.x4.shared.b16 {%0,%1,%2,%3}, [%4];"
                 : "=r"(r0), "=r"(r1), "=r"(r2), "=r"(r3) : "r"(addr));
}
__device__ __forceinline__ void ldsm2(uint32_t& r0, uint32_t& r1, uint32_t addr)
{
    asm volatile("ldmatrix.sync.aligned.m8n8.x2.shared.b16 {%0,%1}, [%2];"
                 : "=r"(r0), "=r"(r1) : "r"(addr));
}

__device__ __forceinline__ void cp16(uint32_t dst, const void* src)
{
    asm volatile("cp.async.cg.shared.global [%0], [%1], 16;" :: "r"(dst), "l"(src));
}
__device__ __forceinline__ void cp_commit() { asm volatile("cp.async.commit_group;"); }
__device__ __forceinline__ void cp_wait()   { asm volatile("cp.async.wait_group 0;"); }
__device__ __forceinline__ void cp_wait1()  { asm volatile("cp.async.wait_group 1;"); }

// ---------------------------------------------------------------------------
// bf16x2-split GEMM (3 products): C = A*W^T (+bias)  [proven, unchanged]
// ---------------------------------------------------------------------------
template<int PERMBIAS, int SPLITOUT>
__global__ void __launch_bounds__(256, 2)
gemm_bf(const bf16* __restrict__ AH, const bf16* __restrict__ AM, int lda,
        const bf16* __restrict__ WH, const bf16* __restrict__ WM, int ldw,
        float* __restrict__ Cf, bf16* __restrict__ CbH, bf16* __restrict__ CbM,
        int ldc, const float* __restrict__ b1, const float* __restrict__ b2,
        int Nstore, int K)
{
    extern __shared__ __align__(16) char smraw[];
    const uint32_t sbase = (uint32_t)__cvta_generic_to_shared(smraw);

    const int tid  = threadIdx.x;
    const int lane = tid & 31;
    const int warp = tid >> 5;
    const int wm   = warp >> 2;
    const int wn   = warp & 3;
    const int row0 = blockIdx.y * 128;
    const int col0 = blockIdx.x * 128;

    float acc[4][4][4];
#pragma unroll
    for (int i = 0; i < 4; i++)
#pragma unroll
        for (int j = 0; j < 4; j++)
#pragma unroll
            for (int q = 0; q < 4; q++) acc[i][j][q] = 0.f;

    const int r  = tid >> 2;
    const int ch = tid & 3;

    auto gload = [&](int buf, int k0) {
        const uint32_t bo = (uint32_t)(buf * 40960);
#pragma unroll
        for (int l = 0; l < 2; l++) {
            int rr = r + l * 64;
            uint32_t so = (uint32_t)(rr * 80 + ch * 16);
            cp16(sbase + bo +         so, &AH[(size_t)(row0 + rr) * lda + k0 + ch * 8]);
            cp16(sbase + bo + 10240 + so, &AM[(size_t)(row0 + rr) * lda + k0 + ch * 8]);
            cp16(sbase + bo + 20480 + so, &WH[(size_t)(col0 + rr) * ldw + k0 + ch * 8]);
            cp16(sbase + bo + 30720 + so, &WM[(size_t)(col0 + rr) * ldw + k0 + ch * 8]);
        }
        cp_commit();
    };

    const int nk = K / 32;
    gload(0, 0);
    cp_wait();
    __syncthreads();

    for (int kt = 0; kt < nk; kt++) {
        const int cur = kt & 1;
        if (kt + 1 < nk) gload(cur ^ 1, (kt + 1) * 32);

        const uint32_t bo  = (uint32_t)(cur * 40960);
        const uint32_t aA0 = sbase + bo;
        const uint32_t aA1 = sbase + bo + 10240;
        const uint32_t aB0 = sbase + bo + 20480;
        const uint32_t aB1 = sbase + bo + 30720;

#pragma unroll
        for (int s = 0; s < 2; s++) {
            uint32_t b0f[4][2], b1f[4][2];
            const uint32_t bOff = (uint32_t)((lane & 7) * 80 + s * 32 + ((lane >> 3) & 1) * 16);
#pragma unroll
            for (int nt = 0; nt < 4; nt++) {
                uint32_t na = (uint32_t)((wn * 32 + nt * 8) * 80);
                ldsm2(b0f[nt][0], b0f[nt][1], aB0 + na + bOff);
                ldsm2(b1f[nt][0], b1f[nt][1], aB1 + na + bOff);
            }
            const uint32_t aOff = (uint32_t)((lane & 15) * 80 + s * 32 + (lane >> 4) * 16);
#pragma unroll
            for (int mt = 0; mt < 4; mt++) {
                uint32_t ma = (uint32_t)((wm * 64 + mt * 16) * 80);
                uint32_t a0[4], a1[4];
                ldsm4(a0[0], a0[1], a0[2], a0[3], aA0 + ma + aOff);
                ldsm4(a1[0], a1[1], a1[2], a1[3], aA1 + ma + aOff);
#pragma unroll
                for (int nt = 0; nt < 4; nt++) {
                    MMA_BF16(acc[mt][nt], a0, b0f[nt]);
                    MMA_BF16(acc[mt][nt], a0, b1f[nt]);
                    MMA_BF16(acc[mt][nt], a1, b0f[nt]);
                }
            }
        }

        if (kt + 1 < nk) { cp_wait(); __syncthreads(); }
    }

#pragma unroll
    for (int mt = 0; mt < 4; mt++)
#pragma unroll
        for (int nt = 0; nt < 4; nt++) {
            int m = row0 + wm * 64 + mt * 16 + (lane >> 2);
            int n = col0 + wn * 32 + nt * 8 + 2 * (lane & 3);
            if (n + 1 >= Nstore) continue;
            float bv0 = 0.f, bv1 = 0.f;
            int bi0 = PERMBIAS ? ((n & 3) * HH + (n >> 2)) : n;
            int bi1 = PERMBIAS ? (((n + 1) & 3) * HH + ((n + 1) >> 2)) : (n + 1);
            if (b1) { bv0 += b1[bi0]; bv1 += b1[bi1]; }
            if (b2) { bv0 += b2[bi0]; bv1 += b2[bi1]; }
            float v00 = acc[mt][nt][0] + bv0, v01 = acc[mt][nt][1] + bv1;
            float v10 = acc[mt][nt][2] + bv0, v11 = acc[mt][nt][3] + bv1;
            if (SPLITOUT) {
                __nv_bfloat162 h0, m0, h1, m1;
                split_bf(v00, h0.x, m0.x); split_bf(v01, h0.y, m0.y);
                split_bf(v10, h1.x, m1.x); split_bf(v11, h1.y, m1.y);
                *reinterpret_cast<__nv_bfloat162*>(&CbH[(size_t)m * ldc + n])       = h0;
                *reinterpret_cast<__nv_bfloat162*>(&CbM[(size_t)m * ldc + n])       = m0;
                *reinterpret_cast<__nv_bfloat162*>(&CbH[(size_t)(m + 8) * ldc + n]) = h1;
                *reinterpret_cast<__nv_bfloat162*>(&CbM[(size_t)(m + 8) * ldc + n]) = m1;
            } else {
                *reinterpret_cast<float2*>(&Cf[(size_t)m * ldc + n])       = make_float2(v00, v01);
                *reinterpret_cast<float2*>(&Cf[(size_t)(m + 8) * ldc + n]) = make_float2(v10, v11);
            }
        }
}

// ---------------------------------------------------------------------------
// Persistent LSTM recurrence, 512 threads (16 warps: 8 over M x 2 over N).
// Warp tile 16M x 16N. Conflict-free resident-weight stride 2096 B
// (524 words = 12 mod 32 -> the 8 ldmatrix row addresses cover all banks).
// 3-stage cp.async ring; gsum aliases A buffer 0; fence-free grid barrier.
//
// smem layout (dyn, 216064 B):
//   0      : A stages, 3 bufs x (H 10240 | M 10240) = 61440  (gsum aliases buf0)
//   61440  : W_H  32 rows x 2096 B                  = 67072
//   128512 : W_M  32 rows x 2096 B                  = 67072
//   195584 : gx stage 128 rows x 128 B              = 16384
//   211968 : c    128 x 8 floats                    = 4096
// ---------------------------------------------------------------------------
#define PSM  216064
#define SW_H 61440
#define SW_M 128512
#define SGX  195584
#define SCC  211968
#define WSTR 2096
#define PTHREADS 512

__global__ void __launch_bounds__(PTHREADS)
lstm_persistent(const bf16* __restrict__ rwhhH, const bf16* __restrict__ rwhhM,
                const bf16* __restrict__ uwhhH, const bf16* __restrict__ uwhhM,
                const float* __restrict__ gatesx,   // [16][128][4096] permuted
                const float* __restrict__ gatesxu,  // [128][4096] permuted
                bf16* __restrict__ h0H, bf16* __restrict__ h0M,
                bf16* __restrict__ h1H, bf16* __restrict__ h1M)
{
    extern __shared__ __align__(16) char smraw[];
    const uint32_t sbase = (uint32_t)__cvta_generic_to_shared(smraw);
    float* gsum = reinterpret_cast<float*>(smraw);          // aliases A buf 0
    float* c_sm = reinterpret_cast<float*>(smraw + SCC);

    const int tid  = threadIdx.x;
    const int lane = tid & 31;
    const int warp = tid >> 5;          // 0..15
    const int wm   = warp >> 1;         // 0..7 over M (16 rows each)
    const int wn   = warp & 1;          // 0..1 over N (16 cols each)
    const int col0 = blockIdx.x * 32;

    // snapshot barrier phase BEFORE first arrival (replay-safe)
    __shared__ unsigned int s_phase;
    if (tid == 0) s_phase = g_bar_phase;

    // init resident c = 0
#pragma unroll
    for (int q = 0; q < 2; q++) c_sm[tid + q * PTHREADS] = 0.f;

    const int r  = tid >> 2;            // 0..127
    const int ch = tid & 3;

    // ---- load resident weights: 32 rows x 2048 B (hi & mid), stride 2096 ----
    auto load_weights = [&](const bf16* wH, const bf16* wM) {
        for (int i = tid; i < 4096; i += PTHREADS) {
            int row = i >> 7;
            int chk = i & 127;
            uint32_t so = (uint32_t)(row * WSTR + chk * 16);
            cp16(sbase + SW_H + so, &wH[(size_t)(col0 + row) * HH + chk * 8]);
            cp16(sbase + SW_M + so, &wM[(size_t)(col0 + row) * HH + chk * 8]);
        }
        cp_commit();
        cp_wait();
        __syncthreads();
    };
    load_weights(rwhhH, rwhhM);

    for (int step = 0; step < 18; step++) {
        const bf16* hH = (step & 1) ? h1H : h0H;
        const bf16* hM = (step & 1) ? h1M : h0M;
        bf16* oH = (step & 1) ? h0H : h1H;
        bf16* oM = (step & 1) ? h0M : h1M;
        const float* gx = (step < SS) ? gatesx + (size_t)step * BB * 4 * HH
                                      : gatesxu;

        if (step == SS) load_weights(uwhhH, uwhhM);   // switch to unroll weights

        // stage this step's gx slice (128 rows x 128 B) into smem early
        {
#pragma unroll
            for (int l = 0; l < 2; l++) {
                int idx = tid + l * PTHREADS;   // 0..1023
                int b   = idx >> 3;
                int chk = idx & 7;
                cp16(sbase + SGX + (uint32_t)(b * 128 + chk * 16),
                     &gx[(size_t)b * (4 * HH) + col0 + chk * 4]);
            }
            cp_commit();
        }

        float acc[2][4];
#pragma unroll
        for (int j = 0; j < 2; j++)
#pragma unroll
            for (int q = 0; q < 4; q++) acc[j][q] = 0.f;

        if (step > 0) {
            // ---- GEMM: gates_h[128 x 32] = h[128 x 1024] @ Wres^T ----
            auto gloadA = [&](int buf, int k0) {
                const uint32_t bo = (uint32_t)(buf * 20480);
                uint32_t so = (uint32_t)(r * 80 + ch * 16);
                cp16(sbase + bo +         so, &hH[(size_t)r * HH + k0 + ch * 8]);
                cp16(sbase + bo + 10240 + so, &hM[(size_t)r * HH + k0 + ch * 8]);
                cp_commit();
            };

            gloadA(0, 0);
            gloadA(1, 32);

            for (int kt = 0; kt < 32; kt++) {
                if (kt == 31) cp_wait(); else cp_wait1();
                __syncthreads();

                const int buf = kt % 3;
                const uint32_t aA0 = sbase + (uint32_t)(buf * 20480);
                const uint32_t aA1 = aA0 + 10240;

#pragma unroll
                for (int s = 0; s < 2; s++) {
                    uint32_t b0f[2][2], b1f[2][2];
                    const uint32_t bOff = (uint32_t)((lane & 7) * WSTR + kt * 64
                                                     + s * 32 + ((lane >> 3) & 1) * 16);
#pragma unroll
                    for (int nt = 0; nt < 2; nt++) {
                        uint32_t na = (uint32_t)((wn * 16 + nt * 8) * WSTR);
                        ldsm2(b0f[nt][0], b0f[nt][1], sbase + SW_H + na + bOff);
                        ldsm2(b1f[nt][0], b1f[nt][1], sbase + SW_M + na + bOff);
                    }
                    const uint32_t aOff = (uint32_t)((wm * 16 + (lane & 15)) * 80
                                                     + s * 32 + (lane >> 4) * 16);
                    uint32_t a0[4], a1[4];
                    ldsm4(a0[0], a0[1], a0[2], a0[3], aA0 + aOff);
                    ldsm4(a1[0], a1[1], a1[2], a1[3], aA1 + aOff);
#pragma unroll
                    for (int nt = 0; nt < 2; nt++) {
                        MMA_BF16(acc[nt], a0, b0f[nt]);
                        MMA_BF16(acc[nt], a0, b1f[nt]);
                        MMA_BF16(acc[nt], a1, b0f[nt]);
                    }
                }

                if (kt + 2 < 32) gloadA((kt + 2) % 3, (kt + 2) * 32);
            }
            __syncthreads();   // all warps done with buf0 before gsum alias write
        } else {
            cp_wait();         // gx stage
            __syncthreads();
        }

        // dump accumulators (gsum aliases A buf 0 — GEMM fully drained)
#pragma unroll
        for (int nt = 0; nt < 2; nt++) {
            int m = wm * 16 + (lane >> 2);
            int n = wn * 16 + nt * 8 + 2 * (lane & 3);
            gsum[m * 36 + n]           = acc[nt][0];
            gsum[m * 36 + n + 1]       = acc[nt][1];
            gsum[(m + 8) * 36 + n]     = acc[nt][2];
            gsum[(m + 8) * 36 + n + 1] = acc[nt][3];
        }
        __syncthreads();

        // cell (gx read from smem stage)
#pragma unroll
        for (int q = 0; q < 2; q++) {
            int idx = tid + q * PTHREADS;
            int b  = idx >> 3;
            int jj = idx & 7;
            float4 g  = *reinterpret_cast<float4*>(&gsum[b * 36 + jj * 4]);
            float4 gv = *reinterpret_cast<float4*>(smraw + SGX + b * 128 + jj * 16);
            float gi = g.x + gv.x;
            float gf = g.y + gv.y;
            float gg = g.z + gv.z;
            float go = g.w + gv.w;
            float si = 1.f / (1.f + expf(-gi));
            float sf = 1.f / (1.f + expf(-gf));
            float so = 1.f / (1.f + expf(-go));
            float tg = tanhf(gg);
            float cn = sf * c_sm[b * 8 + jj] + si * tg;
            float hn = so * tanhf(cn);
            c_sm[b * 8 + jj] = cn;
            int j = (col0 >> 2) + jj;
            bf16 hh, hm;
            split_bf(hn, hh, hm);
            oH[(size_t)b * HH + j] = hh;
            oM[(size_t)b * HH + j] = hm;
        }

        if (step < 17) {
            // fence-free grid barrier (grid.sync pattern)
            __syncthreads();
            if (tid == 0) {
                unsigned int expect = s_phase + (unsigned int)(step + 1);
                unsigned int ticket;
                asm volatile("atom.release.gpu.global.add.u32 %0, [%1], 1;"
                             : "=r"(ticket) : "l"(&g_bar_count) : "memory");
                if (ticket == gridDim.x - 1) {
                    asm volatile("st.relaxed.gpu.global.u32 [%0], %1;"
                                 :: "l"(&g_bar_count), "r"(0u) : "memory");
                    unsigned int dummy;
                    asm volatile("atom.release.gpu.global.add.u32 %0, [%1], 1;"
                                 : "=r"(dummy) : "l"(&g_bar_phase) : "memory");
                } else {
                    unsigned int ph;
                    do {
                        asm volatile("ld.acquire.gpu.global.u32 %0, [%1];"
                                     : "=r"(ph) : "l"(&g_bar_phase) : "memory");
                    } while (ph < expect);
                }
            }
            __syncthreads();
        }
    }
}

// ---------------------------------------------------------------------------
// Merged prep kernels (grid-stride over independent jobs)
// ---------------------------------------------------------------------------
// main path: feats + fc1 splits
__global__ void prep_main(const float* __restrict__ feats,
                          const float* __restrict__ fc1_w,
                          bf16* __restrict__ featsH, bf16* __restrict__ featsM,
                          bf16* __restrict__ fc1H,   bf16* __restrict__ fc1M)
{
    const int stride = gridDim.x * blockDim.x;
    int g = blockIdx.x * blockDim.x + threadIdx.x;
    for (int i = g; i < NB_FEATS / 4; i += stride) {
        float4 v = reinterpret_cast<const float4*>(feats)[i];
        __nv_bfloat162 h0, h1, m0, m1;
        split_bf(v.x, h0.x, m0.x); split_bf(v.y, h0.y, m0.y);
        split_bf(v.z, h1.x, m1.x); split_bf(v.w, h1.y, m1.y);
        reinterpret_cast<__nv_bfloat162*>(featsH)[2 * i]     = h0;
        reinterpret_cast<__nv_bfloat162*>(featsH)[2 * i + 1] = h1;
        reinterpret_cast<__nv_bfloat162*>(featsM)[2 * i]     = m0;
        reinterpret_cast<__nv_bfloat162*>(featsM)[2 * i + 1] = m1;
    }
    for (int i = g; i < NB_FC1 / 4; i += stride) {
        float4 v = reinterpret_cast<const float4*>(fc1_w)[i];
        __nv_bfloat162 h0, h1, m0, m1;
        split_bf(v.x, h0.x, m0.x); split_bf(v.y, h0.y, m0.y);
        split_bf(v.z, h1.x, m1.x); split_bf(v.w, h1.y, m1.y);
        reinterpret_cast<__nv_bfloat162*>(fc1H)[2 * i]     = h0;
        reinterpret_cast<__nv_bfloat162*>(fc1H)[2 * i + 1] = h1;
        reinterpret_cast<__nv_bfloat162*>(fc1M)[2 * i]     = m0;
        reinterpret_cast<__nv_bfloat162*>(fc1M)[2 * i + 1] = m1;
    }
}

__device__ __forceinline__ void perm_split_body(const float* s, bf16* H, bf16* M,
                                                int cols, int i)
{
    int cols4 = cols >> 2;
    int p  = i / cols4;
    int cq = i % cols4;
    int sr = (p & 3) * HH + (p >> 2);
    float4 v = *reinterpret_cast<const float4*>(&s[(size_t)sr * cols + cq * 4]);
    __nv_bfloat162 h0, h1, m0, m1;
    split_bf(v.x, h0.x, m0.x); split_bf(v.y, h0.y, m0.y);
    split_bf(v.z, h1.x, m1.x); split_bf(v.w, h1.y, m1.y);
    size_t o = (size_t)p * cols + cq * 4;
    *reinterpret_cast<__nv_bfloat162*>(&H[o])     = h0;
    *reinterpret_cast<__nv_bfloat162*>(&H[o + 2]) = h1;
    *reinterpret_cast<__nv_bfloat162*>(&M[o])     = m0;
    *reinterpret_cast<__nv_bfloat162*>(&M[o + 2]) = m1;
}

// side path: rwih, uwih, rwhh, uwhh (perm splits), hands, fchw, cls
__global__ void prep_side(const float* __restrict__ roll_wih,
                          const float* __restrict__ u_wih,
                          const float* __restrict__ roll_whh,
                          const float* __restrict__ u_whh,
                          const float* __restrict__ lh,
                          const float* __restrict__ rh,
                          const float* __restrict__ fch_w,
                          const float* __restrict__ cls_w,
                          bf16* rwihH, bf16* rwihM, bf16* uwihH, bf16* uwihM,
                          bf16* rwhhH, bf16* rwhhM, bf16* uwhhH, bf16* uwhhM,
                          bf16* handsH, bf16* handsM,
                          bf16* fchwH, bf16* fchwM,
                          bf16* clsH, bf16* clsM)
{
    const int stride = gridDim.x * blockDim.x;
    int g = blockIdx.x * blockDim.x + threadIdx.x;

    const int N_IH = 4 * HH * (2 * HH / 4);
    const int N_HH = 4 * HH * (HH / 4);
    for (int i = g; i < N_IH; i += stride) perm_split_body(roll_wih, rwihH, rwihM, 2*HH, i);
    for (int i = g; i < N_IH; i += stride) perm_split_body(u_wih,    uwihH, uwihM, 2*HH, i);
    for (int i = g; i < N_HH; i += stride) perm_split_body(roll_whh, rwhhH, rwhhM, HH, i);
    for (int i = g; i < N_HH; i += stride) perm_split_body(u_whh,    uwhhH, uwhhM, HH, i);

    for (int i = g; i < SS * BB * HPAD; i += stride) {
        int col = i % HPAD, row = i / HPAD;
        float v = 0.f;
        if (col < HANDD)          v = lh[row * HANDD + col];
        else if (col < 2 * HANDD) v = rh[row * HANDD + (col - HANDD)];
        bf16 h, m; split_bf(v, h, m);
        handsH[i] = h; handsM[i] = m;
    }
    for (int i = g; i < HH * HPAD; i += stride) {
        int col = i % HPAD, row = i / HPAD;
        float v = (col < 2 * HANDD) ? fch_w[row * 2 * HANDD + col] : 0.f;
        bf16 h, m; split_bf(v, h, m);
        fchwH[i] = h; fchwM[i] = m;
    }
    for (int i = g; i < 1024 * (HH / 4); i += stride) {
        int rr = i / (HH / 4), cq = i % (HH / 4);
        float4 v = (rr < CC)
            ? *reinterpret_cast<const float4*>(&cls_w[(size_t)rr * HH + cq * 4])
            : make_float4(0.f, 0.f, 0.f, 0.f);
        __nv_bfloat162 h0, h1, m0, m1;
        split_bf(v.x, h0.x, m0.x); split_bf(v.y, h0.y, m0.y);
        split_bf(v.z, h1.x, m1.x); split_bf(v.w, h1.y, m1.y);
        size_t o = (size_t)rr * HH + cq * 4;
        *reinterpret_cast<__nv_bfloat162*>(&clsH[o])     = h0;
        *reinterpret_cast<__nv_bfloat162*>(&clsH[o + 2]) = h1;
        *reinterpret_cast<__nv_bfloat162*>(&clsM[o])     = m0;
        *reinterpret_cast<__nv_bfloat162*>(&clsM[o + 2]) = m1;
    }
}

__global__ void row_stats(const float* __restrict__ out,
                          const int* __restrict__ act,
                          float* __restrict__ pred_f,
                          float* __restrict__ lossrow)
{
    const int b = blockIdx.x;
    const float* row = out + (size_t)b * CC;
    __shared__ float smax[128];
    __shared__ int   sidx[128];
    __shared__ float ssum[128];
    const int t = threadIdx.x;

    float best = -INFINITY;
    int bidx = 0;
    for (int j = t; j < CC; j += 128) {
        float v = row[j];
        if (v > best) { best = v; bidx = j; }
    }
    smax[t] = best; sidx[t] = bidx;
    __syncthreads();
    for (int s = 64; s > 0; s >>= 1) {
        if (t < s) {
            float v2 = smax[t + s]; int i2 = sidx[t + s];
            if (v2 > smax[t] || (v2 == smax[t] && i2 < sidx[t])) {
                smax[t] = v2; sidx[t] = i2;
            }
        }
        __syncthreads();
    }
    const float rowmax = smax[0];
    const int   rowarg = sidx[0];

    float lsum = 0.f;
    for (int j = t; j < CC; j += 128) lsum += expf(row[j] - rowmax);
    ssum[t] = lsum;
    __syncthreads();
    for (int s = 64; s > 0; s >>= 1) {
        if (t < s) ssum[t] += ssum[t + s];
        __syncthreads();
    }
    if (t == 0) {
        float logz = rowmax + logf(ssum[0]);
        lossrow[b] = logz - row[act[b]];
        if (pred_f) pred_f[b] = (float)rowarg;
    }
}

__global__ void mean_loss(const float* __restrict__ lossrow, float* loss_out)
{
    __shared__ float s[128];
    int t = threadIdx.x;
    s[t] = lossrow[t];
    __syncthreads();
    for (int st = 64; st > 0; st >>= 1) {
        if (t < st) s[t] += s[t + st];
        __syncthreads();
    }
    if (t == 0) *loss_out = s[0] / (float)BB;
}

// ---------------------------------------------------------------------------
// Launch — two-branch graph
// ---------------------------------------------------------------------------
#define GSM 81920

extern "C" void kernel_launch(void* const* d_in, const int* in_sizes, int n_in,
                              void* d_out, int out_size)
{
    const float* feats    = (const float*)d_in[0];
    const float* lh       = (const float*)d_in[1];
    const float* rh       = (const float*)d_in[2];
    const int*   act      = (const int*)  d_in[3];
    const float* fc1_w    = (const float*)d_in[4];
    const float* fc1_b    = (const float*)d_in[5];
    const float* fch_w    = (const float*)d_in[6];
    const float* fch_b    = (const float*)d_in[7];
    const float* roll_wih = (const float*)d_in[8];
    const float* roll_whh = (const float*)d_in[9];
    const float* roll_bih = (const float*)d_in[10];
    const float* roll_bhh = (const float*)d_in[11];
    const float* u_wih    = (const float*)d_in[12];
    const float* u_whh    = (const float*)d_in[13];
    const float* u_bih    = (const float*)d_in[14];
    const float* u_bhh    = (const float*)d_in[15];
    const float* cls_w    = (const float*)d_in[16];
    const float* cls_b    = (const float*)d_in[17];
    float* out = (float*)d_out;

    cudaFuncSetAttribute(gemm_bf<0, 1>, cudaFuncAttributeMaxDynamicSharedMemorySize, GSM);
    cudaFuncSetAttribute(gemm_bf<1, 0>, cudaFuncAttributeMaxDynamicSharedMemorySize, GSM);
    cudaFuncSetAttribute(gemm_bf<0, 0>, cudaFuncAttributeMaxDynamicSharedMemorySize, GSM);
    cudaFuncSetAttribute(lstm_persistent, cudaFuncAttributeMaxDynamicSharedMemorySize, PSM);

    static cudaStream_t s1 = nullptr;
    static cudaEvent_t evFork = nullptr, evS1 = nullptr, evB = nullptr, evC = nullptr;
    if (!s1) {
        cudaStreamCreateWithFlags(&s1, cudaStreamNonBlocking);
        cudaEventCreateWithFlags(&evFork, cudaEventDisableTiming);
        cudaEventCreateWithFlags(&evS1,   cudaEventDisableTiming);
        cudaEventCreateWithFlags(&evB,    cudaEventDisableTiming);
        cudaEventCreateWithFlags(&evC,    cudaEventDisableTiming);
    }

    float* sc = nullptr;
    cudaGetSymbolAddress((void**)&sc, g_scratch);

    bf16* featsH = (bf16*)(sc + OFF_FEATSH); bf16* featsM = (bf16*)(sc + OFF_FEATSM);
    bf16* xH     = (bf16*)(sc + OFF_XH);     bf16* xM     = (bf16*)(sc + OFF_XM);
    float* gatesx  = sc + OFF_GATESX;
    float* gatesxu = sc + OFF_GATESXU;
    bf16* h0H = (bf16*)(sc + OFF_H0H); bf16* h0M = (bf16*)(sc + OFF_H0M);
    bf16* h1H = (bf16*)(sc + OFF_H1H); bf16* h1M = (bf16*)(sc + OFF_H1M);
    bf16* handsH = (bf16*)(sc + OFF_HANDSH); bf16* handsM = (bf16*)(sc + OFF_HANDSM);
    bf16* fc1H   = (bf16*)(sc + OFF_FC1H);   bf16* fc1M   = (bf16*)(sc + OFF_FC1M);
    bf16* fchwH  = (bf16*)(sc + OFF_FCHWH);  bf16* fchwM  = (bf16*)(sc + OFF_FCHWM);
    bf16* rwihH  = (bf16*)(sc + OFF_RWIHH);  bf16* rwihM  = (bf16*)(sc + OFF_RWIHM);
    bf16* rwhhH  = (bf16*)(sc + OFF_RWHHH);  bf16* rwhhM  = (bf16*)(sc + OFF_RWHHM);
    bf16* uwihH  = (bf16*)(sc + OFF_UWIHH);  bf16* uwihM  = (bf16*)(sc + OFF_UWIHM);
    bf16* uwhhH  = (bf16*)(sc + OFF_UWHHH);  bf16* uwhhM  = (bf16*)(sc + OFF_UWHHM);
    bf16* clsH   = (bf16*)(sc + OFF_CLSH);   bf16* clsM   = (bf16*)(sc + OFF_CLSM);
    float* lossrow = sc + OFF_LOSSROW;

    // ---- fork side stream ----
    cudaEventRecord(evFork, 0);
    cudaStreamWaitEvent(s1, evFork, 0);

    // ---- side stream: merged prep, then hproj ----
    prep_side<<<592, 256, 0, s1>>>(roll_wih, u_wih, roll_whh, u_whh,
                                   lh, rh, fch_w, cls_w,
                                   rwihH, rwihM, uwihH, uwihM,
                                   rwhhH, rwhhM, uwhhH, uwhhM,
                                   handsH, handsM, fchwH, fchwM, clsH, clsM);
    gemm_bf<0,1><<<dim3(8,16), 256, GSM, s1>>>(handsH, handsM, HPAD,
                                               fchwH, fchwM, HPAD,
                                               nullptr, xH + HH, xM + HH, 2*HH,
                                               fch_b, nullptr, HH, HPAD);
    cudaEventRecord(evS1, s1);   // hproj + all side preps ready

    // ---- main stream: critical path ----
    prep_main<<<592, 256>>>(feats, fc1_w, featsH, featsM, fc1H, fc1M);
    gemm_bf<0,1><<<dim3(8,16), 256, GSM>>>(featsH, featsM, FEATD,
                                           fc1H, fc1M, FEATD,
                                           nullptr, xH, xM, 2*HH,
                                           fc1_b, nullptr, HH, FEATD);
    cudaEventRecord(evB, 0);             // xproj done
    cudaStreamWaitEvent(s1, evB, 0);     // side: gatesxu needs full x row S-1

    // side stream: gatesxu (concurrent with gates GEMM below)
    gemm_bf<1,0><<<dim3(32,1), 256, GSM, s1>>>(xH + (size_t)(SS-1)*BB*2*HH,
                                               xM + (size_t)(SS-1)*BB*2*HH, 2*HH,
                                               uwihH, uwihM, 2*HH,
                                               gatesxu, nullptr, nullptr, 4*HH,
                                               u_bih, u_bhh, 4*HH, 2*HH);
    cudaEventRecord(evC, s1);

    // main: gates GEMM (needs hproj + rwih from side stream)
    cudaStreamWaitEvent(0, evS1, 0);
    gemm_bf<1,0><<<dim3(32,16), 256, GSM>>>(xH, xM, 2*HH,
                                            rwihH, rwihM, 2*HH,
                                            gatesx, nullptr, nullptr, 4*HH,
                                            roll_bih, roll_bhh, 4*HH, 2*HH);

    // join side stream before recurrence
    cudaStreamWaitEvent(0, evC, 0);

    // ---- recurrence: one persistent kernel, 18 steps ----
    lstm_persistent<<<128, PTHREADS, PSM>>>(rwhhH, rwhhM, uwhhH, uwhhM,
                                            gatesx, gatesxu,
                                            h0H, h0M, h1H, h1M);

    // ---- classifier (final h lands in h0 after 18 steps) ----
    gemm_bf<0,0><<<dim3(8,1), 256, GSM>>>(h0H, h0M, HH,
                                          clsH, clsM, HH,
                                          out, nullptr, nullptr, CC,
                                          cls_b, nullptr, CC, HH);

    // ---- stats ----
    float* pred_f = (out_size >= BB * CC + BB)     ? out + BB * CC : nullptr;
    float* loss_p = (out_size >= BB * CC + BB + 1) ? out + BB * CC + BB : nullptr;
    row_stats<<<BB, 128>>>(out, act, pred_f, lossrow);
    if (loss_p) mean_loss<<<1, 128>>>(lossrow, loss_p);
}

// round 13
// speedup vs baseline: 4.3878x; 1.0226x over previous
#include <cuda_runtime.h>
#include <cuda_bf16.h>
#include <math.h>
#include <stdint.h>

#define SS    16
#define BB    128
#define FEATD 2048
#define HANDD 63
#define HH    1024
#define CC    1000
#define HPAD  128

// ---------------------------------------------------------------------------
// Scratch layout. bf16 arrays are carved out of the float scratch (count/2).
// ---------------------------------------------------------------------------
#define NB_FEATS (SS*BB*FEATD)
#define NB_X     (SS*BB*2*HH)
#define NB_HANDS (SS*BB*HPAD)
#define NB_FC1   (HH*FEATD)
#define NB_FCHW  (HH*HPAD)
#define NB_RWIH  (4*HH*2*HH)
#define NB_RWHH  (4*HH*HH)
#define NB_CLS   (1024*HH)
#define NB_H     (BB*HH)

#define OFF_FEATSH  0
#define OFF_FEATSM  (OFF_FEATSH + NB_FEATS/2)
#define OFF_XH      (OFF_FEATSM + NB_FEATS/2)
#define OFF_XM      (OFF_XH     + NB_X/2)
#define OFF_GATESX  (OFF_XM     + NB_X/2)
#define OFF_GATESXU (OFF_GATESX + SS*BB*4*HH)
#define OFF_H0H     (OFF_GATESXU+ BB*4*HH)
#define OFF_H0M     (OFF_H0H    + NB_H/2)
#define OFF_H1H     (OFF_H0M    + NB_H/2)
#define OFF_H1M     (OFF_H1H    + NB_H/2)
#define OFF_HANDSH  (OFF_H1M    + NB_H/2)
#define OFF_HANDSM  (OFF_HANDSH + NB_HANDS/2)
#define OFF_FC1H    (OFF_HANDSM + NB_HANDS/2)
#define OFF_FC1M    (OFF_FC1H   + NB_FC1/2)
#define OFF_FCHWH   (OFF_FC1M   + NB_FC1/2)
#define OFF_FCHWM   (OFF_FCHWH  + NB_FCHW/2)
#define OFF_RWIHH   (OFF_FCHWM  + NB_FCHW/2)
#define OFF_RWIHM   (OFF_RWIHH  + NB_RWIH/2)
#define OFF_RWHHH   (OFF_RWIHM  + NB_RWIH/2)
#define OFF_RWHHM   (OFF_RWHHH  + NB_RWHH/2)
#define OFF_UWIHH   (OFF_RWHHM  + NB_RWHH/2)
#define OFF_UWIHM   (OFF_UWIHH  + NB_RWIH/2)
#define OFF_UWHHH   (OFF_UWIHM  + NB_RWIH/2)
#define OFF_UWHHM   (OFF_UWHHH  + NB_RWHH/2)
#define OFF_CLSH    (OFF_UWHHM  + NB_RWHH/2)
#define OFF_CLSM    (OFF_CLSH   + NB_CLS/2)
#define OFF_LOSSROW (OFF_CLSM   + NB_CLS/2)
#define SCRATCH_TOT (OFF_LOSSROW + BB)

__device__ __align__(16) float g_scratch[SCRATCH_TOT];

// tree grid-barrier state (monotone counters; snapshot at entry -> replay-safe)
__device__ unsigned int g_grp[8];
__device__ unsigned int g_root  = 0;
__device__ unsigned int g_phase = 0;

typedef __nv_bfloat16 bf16;

// ---------------------------------------------------------------------------
// helpers
// ---------------------------------------------------------------------------
__device__ __forceinline__ void split_bf(float v, bf16& h, bf16& m)
{
    h = __float2bfloat16_rn(v);
    m = __float2bfloat16_rn(v - __bfloat162float(h));
}

#define MMA_BF16(d, a, b)                                                     \
    asm volatile(                                                             \
        "mma.sync.aligned.m16n8k16.row.col.f32.bf16.bf16.f32 "                \
        "{%0,%1,%2,%3},{%4,%5,%6,%7},{%8,%9},{%0,%1,%2,%3};"                  \
        : "+f"(d[0]), "+f"(d[1]), "+f"(d[2]), "+f"(d[3])                      \
        : "r"(a[0]), "r"(a[1]), "r"(a[2]), "r"(a[3]), "r"(b[0]), "r"(b[1]))

__device__ __forceinline__ void ldsm4(uint32_t& r0, uint32_t& r1,
                                      uint32_t& r2, uint32_t& r3, uint32_t addr)
{
    asm volatile("ldmatrix.sync.aligned.m8n8.x4.shared.b16 {%0,%1,%2,%3}, [%4];"
                 : "=r"(r0), "=r"(r1), "=r"(r2), "=r"(r3) : "r"(addr));
}
__device__ __forceinline__ void ldsm2(uint32_t& r0, uint32_t& r1, uint32_t addr)
{
    asm volatile("ldmatrix.sync.aligned.m8n8.x2.shared.b16 {%0,%1}, [%2];"
                 : "=r"(r0), "=r"(r1) : "r"(addr));
}

__device__ __forceinline__ void cp16(uint32_t dst, const void* src)
{
    asm volatile("cp.async.cg.shared.global [%0], [%1], 16;" :: "r"(dst), "l"(src));
}
__device__ __forceinline__ void cp_commit() { asm volatile("cp.async.commit_group;"); }
__device__ __forceinline__ void cp_wait()   { asm volatile("cp.async.wait_group 0;"); }
__device__ __forceinline__ void cp_wait1()  { asm volatile("cp.async.wait_group 1;"); }

__device__ __forceinline__ unsigned int atom_add_acqrel(unsigned int* p, unsigned int v)
{
    unsigned int old;
    asm volatile("atom.acq_rel.gpu.global.add.u32 %0, [%1], %2;"
                 : "=r"(old) : "l"(p), "r"(v) : "memory");
    return old;
}
__device__ __forceinline__ unsigned int ld_acquire(unsigned int* p)
{
    unsigned int v;
    asm volatile("ld.acquire.gpu.global.u32 %0, [%1];" : "=r"(v) : "l"(p) : "memory");
    return v;
}

// ---------------------------------------------------------------------------
// bf16x2-split GEMM (3 products): C = A*W^T (+bias)  [proven, unchanged]
// ---------------------------------------------------------------------------
template<int PERMBIAS, int SPLITOUT>
__global__ void __launch_bounds__(256, 2)
gemm_bf(const bf16* __restrict__ AH, const bf16* __restrict__ AM, int lda,
        const bf16* __restrict__ WH, const bf16* __restrict__ WM, int ldw,
        float* __restrict__ Cf, bf16* __restrict__ CbH, bf16* __restrict__ CbM,
        int ldc, const float* __restrict__ b1, const float* __restrict__ b2,
        int Nstore, int K)
{
    extern __shared__ __align__(16) char smraw[];
    const uint32_t sbase = (uint32_t)__cvta_generic_to_shared(smraw);

    const int tid  = threadIdx.x;
    const int lane = tid & 31;
    const int warp = tid >> 5;
    const int wm   = warp >> 2;
    const int wn   = warp & 3;
    const int row0 = blockIdx.y * 128;
    const int col0 = blockIdx.x * 128;

    float acc[4][4][4];
#pragma unroll
    for (int i = 0; i < 4; i++)
#pragma unroll
        for (int j = 0; j < 4; j++)
#pragma unroll
            for (int q = 0; q < 4; q++) acc[i][j][q] = 0.f;

    const int r  = tid >> 2;
    const int ch = tid & 3;

    auto gload = [&](int buf, int k0) {
        const uint32_t bo = (uint32_t)(buf * 40960);
#pragma unroll
        for (int l = 0; l < 2; l++) {
            int rr = r + l * 64;
            uint32_t so = (uint32_t)(rr * 80 + ch * 16);
            cp16(sbase + bo +         so, &AH[(size_t)(row0 + rr) * lda + k0 + ch * 8]);
            cp16(sbase + bo + 10240 + so, &AM[(size_t)(row0 + rr) * lda + k0 + ch * 8]);
            cp16(sbase + bo + 20480 + so, &WH[(size_t)(col0 + rr) * ldw + k0 + ch * 8]);
            cp16(sbase + bo + 30720 + so, &WM[(size_t)(col0 + rr) * ldw + k0 + ch * 8]);
        }
        cp_commit();
    };

    const int nk = K / 32;
    gload(0, 0);
    cp_wait();
    __syncthreads();

    for (int kt = 0; kt < nk; kt++) {
        const int cur = kt & 1;
        if (kt + 1 < nk) gload(cur ^ 1, (kt + 1) * 32);

        const uint32_t bo  = (uint32_t)(cur * 40960);
        const uint32_t aA0 = sbase + bo;
        const uint32_t aA1 = sbase + bo + 10240;
        const uint32_t aB0 = sbase + bo + 20480;
        const uint32_t aB1 = sbase + bo + 30720;

#pragma unroll
        for (int s = 0; s < 2; s++) {
            uint32_t b0f[4][2], b1f[4][2];
            const uint32_t bOff = (uint32_t)((lane & 7) * 80 + s * 32 + ((lane >> 3) & 1) * 16);
#pragma unroll
            for (int nt = 0; nt < 4; nt++) {
                uint32_t na = (uint32_t)((wn * 32 + nt * 8) * 80);
                ldsm2(b0f[nt][0], b0f[nt][1], aB0 + na + bOff);
                ldsm2(b1f[nt][0], b1f[nt][1], aB1 + na + bOff);
            }
            const uint32_t aOff = (uint32_t)((lane & 15) * 80 + s * 32 + (lane >> 4) * 16);
#pragma unroll
            for (int mt = 0; mt < 4; mt++) {
                uint32_t ma = (uint32_t)((wm * 64 + mt * 16) * 80);
                uint32_t a0[4], a1[4];
                ldsm4(a0[0], a0[1], a0[2], a0[3], aA0 + ma + aOff);
                ldsm4(a1[0], a1[1], a1[2], a1[3], aA1 + ma + aOff);
#pragma unroll
                for (int nt = 0; nt < 4; nt++) {
                    MMA_BF16(acc[mt][nt], a0, b0f[nt]);
                    MMA_BF16(acc[mt][nt], a0, b1f[nt]);
                    MMA_BF16(acc[mt][nt], a1, b0f[nt]);
                }
            }
        }

        if (kt + 1 < nk) { cp_wait(); __syncthreads(); }
    }

#pragma unroll
    for (int mt = 0; mt < 4; mt++)
#pragma unroll
        for (int nt = 0; nt < 4; nt++) {
            int m = row0 + wm * 64 + mt * 16 + (lane >> 2);
            int n = col0 + wn * 32 + nt * 8 + 2 * (lane & 3);
            if (n + 1 >= Nstore) continue;
            float bv0 = 0.f, bv1 = 0.f;
            int bi0 = PERMBIAS ? ((n & 3) * HH + (n >> 2)) : n;
            int bi1 = PERMBIAS ? (((n + 1) & 3) * HH + ((n + 1) >> 2)) : (n + 1);
            if (b1) { bv0 += b1[bi0]; bv1 += b1[bi1]; }
            if (b2) { bv0 += b2[bi0]; bv1 += b2[bi1]; }
            float v00 = acc[mt][nt][0] + bv0, v01 = acc[mt][nt][1] + bv1;
            float v10 = acc[mt][nt][2] + bv0, v11 = acc[mt][nt][3] + bv1;
            if (SPLITOUT) {
                __nv_bfloat162 h0, m0, h1, m1;
                split_bf(v00, h0.x, m0.x); split_bf(v01, h0.y, m0.y);
                split_bf(v10, h1.x, m1.x); split_bf(v11, h1.y, m1.y);
                *reinterpret_cast<__nv_bfloat162*>(&CbH[(size_t)m * ldc + n])       = h0;
                *reinterpret_cast<__nv_bfloat162*>(&CbM[(size_t)m * ldc + n])       = m0;
                *reinterpret_cast<__nv_bfloat162*>(&CbH[(size_t)(m + 8) * ldc + n]) = h1;
                *reinterpret_cast<__nv_bfloat162*>(&CbM[(size_t)(m + 8) * ldc + n]) = m1;
            } else {
                *reinterpret_cast<float2*>(&Cf[(size_t)m * ldc + n])       = make_float2(v00, v01);
                *reinterpret_cast<float2*>(&Cf[(size_t)(m + 8) * ldc + n]) = make_float2(v10, v11);
            }
        }
}

// ---------------------------------------------------------------------------
// Persistent LSTM recurrence, 512 threads (16 warps: 8 over M x 2 over N).
// BK=64 (16 K-iterations/step, half the syncthreads), A-row stride 144 B
// (36 words = 4 mod 32 -> conflict-free ldsm). Resident weights stride 2096.
// Tree grid barrier (8 groups x 16 CTAs, monotone counters).
//
// smem layout (dyn, 228352 B):
//   0      : A stages, 2 bufs x (H 18432 | M 18432) = 73728  (gsum aliases buf0)
//   73728  : W_H  32 rows x 2096 B                  = 67072
//   140800 : W_M  32 rows x 2096 B                  = 67072
//   207872 : gx stage 128 rows x 128 B              = 16384
//   224256 : c    128 x 8 floats                    = 4096
// ---------------------------------------------------------------------------
#define PSM  228352
#define ABUF 36864
#define ASTR 144
#define SW_H 73728
#define SW_M 140800
#define SGX  207872
#define SCC  224256
#define WSTR 2096
#define PTHREADS 512

__global__ void __launch_bounds__(PTHREADS)
lstm_persistent(const bf16* __restrict__ rwhhH, const bf16* __restrict__ rwhhM,
                const bf16* __restrict__ uwhhH, const bf16* __restrict__ uwhhM,
                const float* __restrict__ gatesx,   // [16][128][4096] permuted
                const float* __restrict__ gatesxu,  // [128][4096] permuted
                bf16* __restrict__ h0H, bf16* __restrict__ h0M,
                bf16* __restrict__ h1H, bf16* __restrict__ h1M)
{
    extern __shared__ __align__(16) char smraw[];
    const uint32_t sbase = (uint32_t)__cvta_generic_to_shared(smraw);
    float* gsum = reinterpret_cast<float*>(smraw);          // aliases A buf 0
    float* c_sm = reinterpret_cast<float*>(smraw + SCC);

    const int tid  = threadIdx.x;
    const int lane = tid & 31;
    const int warp = tid >> 5;          // 0..15
    const int wm   = warp >> 1;         // 0..7 over M
    const int wn   = warp & 1;          // 0..1 over N
    const int col0 = blockIdx.x * 32;
    const int grp  = blockIdx.x >> 4;   // 0..7

    // snapshot phase BEFORE first arrival (replay-safe; counters are monotone)
    __shared__ unsigned int s_phase;
    if (tid == 0) s_phase = g_phase;

    // init resident c = 0
#pragma unroll
    for (int q = 0; q < 2; q++) c_sm[tid + q * PTHREADS] = 0.f;

    // ---- load resident weights: 32 rows x 2048 B (hi & mid), stride 2096 ----
    auto load_weights = [&](const bf16* wH, const bf16* wM) {
        for (int i = tid; i < 4096; i += PTHREADS) {
            int row = i >> 7;
            int chk = i & 127;
            uint32_t so = (uint32_t)(row * WSTR + chk * 16);
            cp16(sbase + SW_H + so, &wH[(size_t)(col0 + row) * HH + chk * 8]);
            cp16(sbase + SW_M + so, &wM[(size_t)(col0 + row) * HH + chk * 8]);
        }
        cp_commit();
        cp_wait();
        __syncthreads();
    };
    load_weights(rwhhH, rwhhM);

    for (int step = 0; step < 18; step++) {
        const bf16* hH = (step & 1) ? h1H : h0H;
        const bf16* hM = (step & 1) ? h1M : h0M;
        bf16* oH = (step & 1) ? h0H : h1H;
        bf16* oM = (step & 1) ? h0M : h1M;
        const float* gx = (step < SS) ? gatesx + (size_t)step * BB * 4 * HH
                                      : gatesxu;

        if (step == SS) load_weights(uwhhH, uwhhM);   // switch to unroll weights

        // stage this step's gx slice (128 rows x 128 B) into smem early
        {
#pragma unroll
            for (int l = 0; l < 2; l++) {
                int idx = tid + l * PTHREADS;
                int b   = idx >> 3;
                int chk = idx & 7;
                cp16(sbase + SGX + (uint32_t)(b * 128 + chk * 16),
                     &gx[(size_t)b * (4 * HH) + col0 + chk * 4]);
            }
            cp_commit();
        }

        float acc[2][4];
#pragma unroll
        for (int j = 0; j < 2; j++)
#pragma unroll
            for (int q = 0; q < 4; q++) acc[j][q] = 0.f;

        if (step > 0) {
            // ---- GEMM: gates_h[128 x 32] = h[128 x 1024] @ Wres^T, BK=64 ----
            auto gloadA = [&](int buf, int k0) {
                const uint32_t bo = (uint32_t)(buf * ABUF);
#pragma unroll
                for (int l = 0; l < 2; l++) {
                    int idx = tid + l * PTHREADS;     // 0..1023
                    int row = idx >> 3;
                    int chk = idx & 7;
                    uint32_t so = (uint32_t)(row * ASTR + chk * 16);
                    cp16(sbase + bo +         so, &hH[(size_t)row * HH + k0 + chk * 8]);
                    cp16(sbase + bo + 18432 + so, &hM[(size_t)row * HH + k0 + chk * 8]);
                }
                cp_commit();
            };

            gloadA(0, 0);

            for (int kt = 0; kt < 16; kt++) {
                if (kt + 1 < 16) { gloadA((kt + 1) & 1, (kt + 1) * 64); cp_wait1(); }
                else             { cp_wait(); }
                __syncthreads();

                const uint32_t aA0 = sbase + (uint32_t)((kt & 1) * ABUF);
                const uint32_t aA1 = aA0 + 18432;

#pragma unroll
                for (int s = 0; s < 4; s++) {
                    uint32_t b0f[2][2], b1f[2][2];
                    const uint32_t bOff = (uint32_t)((lane & 7) * WSTR + kt * 128
                                                     + s * 32 + ((lane >> 3) & 1) * 16);
#pragma unroll
                    for (int nt = 0; nt < 2; nt++) {
                        uint32_t na = (uint32_t)((wn * 16 + nt * 8) * WSTR);
                        ldsm2(b0f[nt][0], b0f[nt][1], sbase + SW_H + na + bOff);
                        ldsm2(b1f[nt][0], b1f[nt][1], sbase + SW_M + na + bOff);
                    }
                    const uint32_t aOff = (uint32_t)((wm * 16 + (lane & 15)) * ASTR
                                                     + s * 32 + (lane >> 4) * 16);
                    uint32_t a0[4], a1[4];
                    ldsm4(a0[0], a0[1], a0[2], a0[3], aA0 + aOff);
                    ldsm4(a1[0], a1[1], a1[2], a1[3], aA1 + aOff);
#pragma unroll
                    for (int nt = 0; nt < 2; nt++) {
                        MMA_BF16(acc[nt], a0, b0f[nt]);
                        MMA_BF16(acc[nt], a0, b1f[nt]);
                        MMA_BF16(acc[nt], a1, b0f[nt]);
                    }
                }
            }
            __syncthreads();   // all warps done with buf0 before gsum alias write
        } else {
            cp_wait();         // gx stage
            __syncthreads();
        }

        // dump accumulators (gsum aliases A buf 0 — GEMM fully drained)
#pragma unroll
        for (int nt = 0; nt < 2; nt++) {
            int m = wm * 16 + (lane >> 2);
            int n = wn * 16 + nt * 8 + 2 * (lane & 3);
            gsum[m * 36 + n]           = acc[nt][0];
            gsum[m * 36 + n + 1]       = acc[nt][1];
            gsum[(m + 8) * 36 + n]     = acc[nt][2];
            gsum[(m + 8) * 36 + n + 1] = acc[nt][3];
        }
        __syncthreads();

        // cell (gx read from smem stage)
#pragma unroll
        for (int q = 0; q < 2; q++) {
            int idx = tid + q * PTHREADS;
            int b  = idx >> 3;
            int jj = idx & 7;
            float4 g  = *reinterpret_cast<float4*>(&gsum[b * 36 + jj * 4]);
            float4 gv = *reinterpret_cast<float4*>(smraw + SGX + b * 128 + jj * 16);
            float gi = g.x + gv.x;
            float gf = g.y + gv.y;
            float gg = g.z + gv.z;
            float go = g.w + gv.w;
            float si = 1.f / (1.f + expf(-gi));
            float sf = 1.f / (1.f + expf(-gf));
            float so = 1.f / (1.f + expf(-go));
            float tg = tanhf(gg);
            float cn = sf * c_sm[b * 8 + jj] + si * tg;
            float hn = so * tanhf(cn);
            c_sm[b * 8 + jj] = cn;
            int j = (col0 >> 2) + jj;
            bf16 hh, hm;
            split_bf(hn, hh, hm);
            oH[(size_t)b * HH + j] = hh;
            oM[(size_t)b * HH + j] = hm;
        }

        if (step < 17) {
            // tree grid barrier (monotone counters; acq_rel chain carries the
            // release of this CTA's h stores to the poll's acquire).
            __syncthreads();
            if (tid == 0) {
                const unsigned int R = s_phase + (unsigned int)step;  // round idx
                unsigned int t1 = atom_add_acqrel(&g_grp[grp], 1);
                if (t1 == R * 16 + 15) {
                    unsigned int t2 = atom_add_acqrel(&g_root, 1);
                    if (t2 == R * 8 + 7) {
                        atom_add_acqrel(&g_phase, 1);   // phase -> R+1
                    }
                }
                while (ld_acquire(&g_phase) <= R) { }
            }
            __syncthreads();
        }
    }
}

// ---------------------------------------------------------------------------
// Prep kernels (fp32 -> split bf16), grid-stride
// ---------------------------------------------------------------------------
__global__ void prep_main(const float* __restrict__ feats,
                          const float* __restrict__ fc1_w,
                          bf16* __restrict__ featsH, bf16* __restrict__ featsM,
                          bf16* __restrict__ fc1H,   bf16* __restrict__ fc1M)
{
    const int stride = gridDim.x * blockDim.x;
    int g = blockIdx.x * blockDim.x + threadIdx.x;
    for (int i = g; i < NB_FEATS / 4; i += stride) {
        float4 v = reinterpret_cast<const float4*>(feats)[i];
        __nv_bfloat162 h0, h1, m0, m1;
        split_bf(v.x, h0.x, m0.x); split_bf(v.y, h0.y, m0.y);
        split_bf(v.z, h1.x, m1.x); split_bf(v.w, h1.y, m1.y);
        reinterpret_cast<__nv_bfloat162*>(featsH)[2 * i]     = h0;
        reinterpret_cast<__nv_bfloat162*>(featsH)[2 * i + 1] = h1;
        reinterpret_cast<__nv_bfloat162*>(featsM)[2 * i]     = m0;
        reinterpret_cast<__nv_bfloat162*>(featsM)[2 * i + 1] = m1;
    }
    for (int i = g; i < NB_FC1 / 4; i += stride) {
        float4 v = reinterpret_cast<const float4*>(fc1_w)[i];
        __nv_bfloat162 h0, h1, m0, m1;
        split_bf(v.x, h0.x, m0.x); split_bf(v.y, h0.y, m0.y);
        split_bf(v.z, h1.x, m1.x); split_bf(v.w, h1.y, m1.y);
        reinterpret_cast<__nv_bfloat162*>(fc1H)[2 * i]     = h0;
        reinterpret_cast<__nv_bfloat162*>(fc1H)[2 * i + 1] = h1;
        reinterpret_cast<__nv_bfloat162*>(fc1M)[2 * i]     = m0;
        reinterpret_cast<__nv_bfloat162*>(fc1M)[2 * i + 1] = m1;
    }
}

__device__ __forceinline__ void perm_split_body(const float* s, bf16* H, bf16* M,
                                                int cols, int i)
{
    int cols4 = cols >> 2;
    int p  = i / cols4;
    int cq = i % cols4;
    int sr = (p & 3) * HH + (p >> 2);
    float4 v = *reinterpret_cast<const float4*>(&s[(size_t)sr * cols + cq * 4]);
    __nv_bfloat162 h0, h1, m0, m1;
    split_bf(v.x, h0.x, m0.x); split_bf(v.y, h0.y, m0.y);
    split_bf(v.z, h1.x, m1.x); split_bf(v.w, h1.y, m1.y);
    size_t o = (size_t)p * cols + cq * 4;
    *reinterpret_cast<__nv_bfloat162*>(&H[o])     = h0;
    *reinterpret_cast<__nv_bfloat162*>(&H[o + 2]) = h1;
    *reinterpret_cast<__nv_bfloat162*>(&M[o])     = m0;
    *reinterpret_cast<__nv_bfloat162*>(&M[o + 2]) = m1;
}

// early side preps: rwih (needed by gates), hands + fchw (needed by hproj)
__global__ void prep_early(const float* __restrict__ roll_wih,
                           const float* __restrict__ lh,
                           const float* __restrict__ rh,
                           const float* __restrict__ fch_w,
                           bf16* rwihH, bf16* rwihM,
                           bf16* handsH, bf16* handsM,
                           bf16* fchwH, bf16* fchwM)
{
    const int stride = gridDim.x * blockDim.x;
    int g = blockIdx.x * blockDim.x + threadIdx.x;
    const int N_IH = 4 * HH * (2 * HH / 4);
    for (int i = g; i < N_IH; i += stride) perm_split_body(roll_wih, rwihH, rwihM, 2*HH, i);
    for (int i = g; i < SS * BB * HPAD; i += stride) {
        int col = i % HPAD, row = i / HPAD;
        float v = 0.f;
        if (col < HANDD)          v = lh[row * HANDD + col];
        else if (col < 2 * HANDD) v = rh[row * HANDD + (col - HANDD)];
        bf16 h, m; split_bf(v, h, m);
        handsH[i] = h; handsM[i] = m;
    }
    for (int i = g; i < HH * HPAD; i += stride) {
        int col = i % HPAD, row = i / HPAD;
        float v = (col < 2 * HANDD) ? fch_w[row * 2 * HANDD + col] : 0.f;
        bf16 h, m; split_bf(v, h, m);
        fchwH[i] = h; fchwM[i] = m;
    }
}

// late side preps: uwih, rwhh, uwhh, cls (overlap the gates GEMM)
__global__ void prep_late(const float* __restrict__ u_wih,
                          const float* __restrict__ roll_whh,
                          const float* __restrict__ u_whh,
                          const float* __restrict__ cls_w,
                          bf16* uwihH, bf16* uwihM,
                          bf16* rwhhH, bf16* rwhhM, bf16* uwhhH, bf16* uwhhM,
                          bf16* clsH, bf16* clsM)
{
    const int stride = gridDim.x * blockDim.x;
    int g = blockIdx.x * blockDim.x + threadIdx.x;
    const int N_IH = 4 * HH * (2 * HH / 4);
    const int N_HH = 4 * HH * (HH / 4);
    for (int i = g; i < N_IH; i += stride) perm_split_body(u_wih,    uwihH, uwihM, 2*HH, i);
    for (int i = g; i < N_HH; i += stride) perm_split_body(roll_whh, rwhhH, rwhhM, HH, i);
    for (int i = g; i < N_HH; i += stride) perm_split_body(u_whh,    uwhhH, uwhhM, HH, i);
    for (int i = g; i < 1024 * (HH / 4); i += stride) {
        int rr = i / (HH / 4), cq = i % (HH / 4);
        float4 v = (rr < CC)
            ? *reinterpret_cast<const float4*>(&cls_w[(size_t)rr * HH + cq * 4])
            : make_float4(0.f, 0.f, 0.f, 0.f);
        __nv_bfloat162 h0, h1, m0, m1;
        split_bf(v.x, h0.x, m0.x); split_bf(v.y, h0.y, m0.y);
        split_bf(v.z, h1.x, m1.x); split_bf(v.w, h1.y, m1.y);
        size_t o = (size_t)rr * HH + cq * 4;
        *reinterpret_cast<__nv_bfloat162*>(&clsH[o])     = h0;
        *reinterpret_cast<__nv_bfloat162*>(&clsH[o + 2]) = h1;
        *reinterpret_cast<__nv_bfloat162*>(&clsM[o])     = m0;
        *reinterpret_cast<__nv_bfloat162*>(&clsM[o + 2]) = m1;
    }
}

__global__ void row_stats(const float* __restrict__ out,
                          const int* __restrict__ act,
                          float* __restrict__ pred_f,
                          float* __restrict__ lossrow)
{
    const int b = blockIdx.x;
    const float* row = out + (size_t)b * CC;
    __shared__ float smax[128];
    __shared__ int   sidx[128];
    __shared__ float ssum[128];
    const int t = threadIdx.x;

    float best = -INFINITY;
    int bidx = 0;
    for (int j = t; j < CC; j += 128) {
        float v = row[j];
        if (v > best) { best = v; bidx = j; }
    }
    smax[t] = best; sidx[t] = bidx;
    __syncthreads();
    for (int s = 64; s > 0; s >>= 1) {
        if (t < s) {
            float v2 = smax[t + s]; int i2 = sidx[t + s];
            if (v2 > smax[t] || (v2 == smax[t] && i2 < sidx[t])) {
                smax[t] = v2; sidx[t] = i2;
            }
        }
        __syncthreads();
    }
    const float rowmax = smax[0];
    const int   rowarg = sidx[0];

    float lsum = 0.f;
    for (int j = t; j < CC; j += 128) lsum += expf(row[j] - rowmax);
    ssum[t] = lsum;
    __syncthreads();
    for (int s = 64; s > 0; s >>= 1) {
        if (t < s) ssum[t] += ssum[t + s];
        __syncthreads();
    }
    if (t == 0) {
        float logz = rowmax + logf(ssum[0]);
        lossrow[b] = logz - row[act[b]];
        if (pred_f) pred_f[b] = (float)rowarg;
    }
}

__global__ void mean_loss(const float* __restrict__ lossrow, float* loss_out)
{
    __shared__ float s[128];
    int t = threadIdx.x;
    s[t] = lossrow[t];
    __syncthreads();
    for (int st = 64; st > 0; st >>= 1) {
        if (t < st) s[t] += s[t + st];
        __syncthreads();
    }
    if (t == 0) *loss_out = s[0] / (float)BB;
}

// ---------------------------------------------------------------------------
// Launch — two-branch graph; late preps deferred past xproj's window
// ---------------------------------------------------------------------------
#define GSM 81920

extern "C" void kernel_launch(void* const* d_in, const int* in_sizes, int n_in,
                              void* d_out, int out_size)
{
    const float* feats    = (const float*)d_in[0];
    const float* lh       = (const float*)d_in[1];
    const float* rh       = (const float*)d_in[2];
    const int*   act      = (const int*)  d_in[3];
    const float* fc1_w    = (const float*)d_in[4];
    const float* fc1_b    = (const float*)d_in[5];
    const float* fch_w    = (const float*)d_in[6];
    const float* fch_b    = (const float*)d_in[7];
    const float* roll_wih = (const float*)d_in[8];
    const float* roll_whh = (const float*)d_in[9];
    const float* roll_bih = (const float*)d_in[10];
    const float* roll_bhh = (const float*)d_in[11];
    const float* u_wih    = (const float*)d_in[12];
    const float* u_whh    = (const float*)d_in[13];
    const float* u_bih    = (const float*)d_in[14];
    const float* u_bhh    = (const float*)d_in[15];
    const float* cls_w    = (const float*)d_in[16];
    const float* cls_b    = (const float*)d_in[17];
    float* out = (float*)d_out;

    cudaFuncSetAttribute(gemm_bf<0, 1>, cudaFuncAttributeMaxDynamicSharedMemorySize, GSM);
    cudaFuncSetAttribute(gemm_bf<1, 0>, cudaFuncAttributeMaxDynamicSharedMemorySize, GSM);
    cudaFuncSetAttribute(gemm_bf<0, 0>, cudaFuncAttributeMaxDynamicSharedMemorySize, GSM);
    cudaFuncSetAttribute(lstm_persistent, cudaFuncAttributeMaxDynamicSharedMemorySize, PSM);

    static cudaStream_t s1 = nullptr;
    static cudaEvent_t evFork = nullptr, evS1 = nullptr, evB = nullptr, evC = nullptr;
    if (!s1) {
        cudaStreamCreateWithFlags(&s1, cudaStreamNonBlocking);
        cudaEventCreateWithFlags(&evFork, cudaEventDisableTiming);
        cudaEventCreateWithFlags(&evS1,   cudaEventDisableTiming);
        cudaEventCreateWithFlags(&evB,    cudaEventDisableTiming);
        cudaEventCreateWithFlags(&evC,    cudaEventDisableTiming);
    }

    float* sc = nullptr;
    cudaGetSymbolAddress((void**)&sc, g_scratch);

    bf16* featsH = (bf16*)(sc + OFF_FEATSH); bf16* featsM = (bf16*)(sc + OFF_FEATSM);
    bf16* xH     = (bf16*)(sc + OFF_XH);     bf16* xM     = (bf16*)(sc + OFF_XM);
    float* gatesx  = sc + OFF_GATESX;
    float* gatesxu = sc + OFF_GATESXU;
    bf16* h0H = (bf16*)(sc + OFF_H0H); bf16* h0M = (bf16*)(sc + OFF_H0M);
    bf16* h1H = (bf16*)(sc + OFF_H1H); bf16* h1M = (bf16*)(sc + OFF_H1M);
    bf16* handsH = (bf16*)(sc + OFF_HANDSH); bf16* handsM = (bf16*)(sc + OFF_HANDSM);
    bf16* fc1H   = (bf16*)(sc + OFF_FC1H);   bf16* fc1M   = (bf16*)(sc + OFF_FC1M);
    bf16* fchwH  = (bf16*)(sc + OFF_FCHWH);  bf16* fchwM  = (bf16*)(sc + OFF_FCHWM);
    bf16* rwihH  = (bf16*)(sc + OFF_RWIHH);  bf16* rwihM  = (bf16*)(sc + OFF_RWIHM);
    bf16* rwhhH  = (bf16*)(sc + OFF_RWHHH);  bf16* rwhhM  = (bf16*)(sc + OFF_RWHHM);
    bf16* uwihH  = (bf16*)(sc + OFF_UWIHH);  bf16* uwihM  = (bf16*)(sc + OFF_UWIHM);
    bf16* uwhhH  = (bf16*)(sc + OFF_UWHHH);  bf16* uwhhM  = (bf16*)(sc + OFF_UWHHM);
    bf16* clsH   = (bf16*)(sc + OFF_CLSH);   bf16* clsM   = (bf16*)(sc + OFF_CLSM);
    float* lossrow = sc + OFF_LOSSROW;

    // ---- fork side stream ----
    cudaEventRecord(evFork, 0);
    cudaStreamWaitEvent(s1, evFork, 0);

    // ---- side stream: EARLY preps only, then hproj ----
    prep_early<<<296, 256, 0, s1>>>(roll_wih, lh, rh, fch_w,
                                    rwihH, rwihM, handsH, handsM, fchwH, fchwM);
    gemm_bf<0,1><<<dim3(8,16), 256, GSM, s1>>>(handsH, handsM, HPAD,
                                               fchwH, fchwM, HPAD,
                                               nullptr, xH + HH, xM + HH, 2*HH,
                                               fch_b, nullptr, HH, HPAD);
    cudaEventRecord(evS1, s1);   // hproj + rwih ready (needed by gates)
    // late preps overlap the gates GEMM, not xproj
    prep_late<<<296, 256, 0, s1>>>(u_wih, roll_whh, u_whh, cls_w,
                                   uwihH, uwihM, rwhhH, rwhhM, uwhhH, uwhhM,
                                   clsH, clsM);

    // ---- main stream: critical path ----
    prep_main<<<296, 256>>>(feats, fc1_w, featsH, featsM, fc1H, fc1M);
    gemm_bf<0,1><<<dim3(8,16), 256, GSM>>>(featsH, featsM, FEATD,
                                           fc1H, fc1M, FEATD,
                                           nullptr, xH, xM, 2*HH,
                                           fc1_b, nullptr, HH, FEATD);
    cudaEventRecord(evB, 0);             // xproj done
    cudaStreamWaitEvent(s1, evB, 0);     // side: gatesxu needs full x row S-1

    // side stream: gatesxu (concurrent with gates GEMM below)
    gemm_bf<1,0><<<dim3(32,1), 256, GSM, s1>>>(xH + (size_t)(SS-1)*BB*2*HH,
                                               xM + (size_t)(SS-1)*BB*2*HH, 2*HH,
                                               uwihH, uwihM, 2*HH,
                                               gatesxu, nullptr, nullptr, 4*HH,
                                               u_bih, u_bhh, 4*HH, 2*HH);
    cudaEventRecord(evC, s1);

    // main: gates GEMM (needs hproj + rwih from side stream)
    cudaStreamWaitEvent(0, evS1, 0);
    gemm_bf<1,0><<<dim3(32,16), 256, GSM>>>(xH, xM, 2*HH,
                                            rwihH, rwihM, 2*HH,
                                            gatesx, nullptr, nullptr, 4*HH,
                                            roll_bih, roll_bhh, 4*HH, 2*HH);

    // join side stream before recurrence
    cudaStreamWaitEvent(0, evC, 0);

    // ---- recurrence: one persistent kernel, 18 steps ----
    lstm_persistent<<<128, PTHREADS, PSM>>>(rwhhH, rwhhM, uwhhH, uwhhM,
                                            gatesx, gatesxu,
                                            h0H, h0M, h1H, h1M);

    // ---- classifier (final h lands in h0 after 18 steps) ----
    gemm_bf<0,0><<<dim3(8,1), 256, GSM>>>(h0H, h0M, HH,
                                          clsH, clsM, HH,
                                          out, nullptr, nullptr, CC,
                                          cls_b, nullptr, CC, HH);

    // ---- stats ----
    float* pred_f = (out_size >= BB * CC + BB)     ? out + BB * CC : nullptr;
    float* loss_p = (out_size >= BB * CC + BB + 1) ? out + BB * CC + BB : nullptr;
    row_stats<<<BB, 128>>>(out, act, pred_f, lossrow);
    if (loss_p) mean_loss<<<1, 128>>>(lossrow, loss_p);
}